// round 12
// baseline (speedup 1.0000x reference)
#include <cuda_runtime.h>
#include <cuda_bf16.h>
#include <math.h>
#include <stdint.h>

#define Bb 2
#define Tt 1024
#define Cc 512
#define Hh 8
#define KVh 2
#define HD 64
#define Ll 2
#define Ee 8
#define TOPK 2
#define Vv 32000
#define Nn (Bb*Tt)        // 2048 tokens
#define KVD (KVh*HD)      // 128
#define QKVN (Cc + 2*KVD) // 768
#define ECAP 2048         // per-expert slot capacity
#define QB 8              // queries per attention block
#define EPSf 1e-6f

// ---------------- scratch (device globals; no allocation allowed) ----------------
__device__ float g_h[Nn*Cc];
__device__ float g_xn[Nn*Cc];
__device__ float g_qkv[Nn*QKVN];
__device__ int   g_sel[Nn*TOPK];
__device__ float g_gw[Nn*TOPK];
__device__ int   g_cnt[Ee];
__device__ int   g_glist[Ee*ECAP];
__device__ int   g_tokslot[Nn*TOPK];
__device__ __nv_bfloat16 g_ah[Nn*Cc];
__device__ __nv_bfloat16 g_al[Nn*Cc];
__device__ __nv_bfloat16 g_gah[Ee*ECAP*Cc];
__device__ __nv_bfloat16 g_gal[Ee*ECAP*Cc];
__device__ float g_gmo[Ee*ECAP*Cc];
// pre-split weights (all layers)
__device__ __nv_bfloat16 g_wqkvh[Ll*QKVN*Cc];
__device__ __nv_bfloat16 g_wqkvl[Ll*QKVN*Cc];
__device__ __nv_bfloat16 g_woh[Ll*Cc*Cc];
__device__ __nv_bfloat16 g_wol[Ll*Cc*Cc];
__device__ __nv_bfloat16 g_wexh[Ll*Ee*Cc*Cc];
__device__ __nv_bfloat16 g_wexl[Ll*Ee*Cc*Cc];
__device__ __nv_bfloat16 g_wouth[Vv*Cc];
__device__ __nv_bfloat16 g_woutl[Vv*Cc];

// ---------------- embedding ----------------
__global__ void embed_kernel(const int* __restrict__ ids,
                             const float* __restrict__ tok,
                             const float* __restrict__ pos) {
    int idx = blockIdx.x * blockDim.x + threadIdx.x;
    if (idx >= Nn*Cc) return;
    int n = idx / Cc, c = idx - n*Cc;
    int t = n % Tt;
    g_h[idx] = tok[(size_t)ids[n]*Cc + c] + pos[(size_t)t*Cc + c];
}

// ---- fused (optional moe-combine) + rmsnorm + bf16 split; zeroes counters ----
__global__ void rmsnorm_split_kernel(float* __restrict__ hbuf,
                                     const float* __restrict__ w,
                                     float* __restrict__ xn,
                                     __nv_bfloat16* __restrict__ hi,
                                     __nv_bfloat16* __restrict__ lo,
                                     int do_moe) {
    int n = blockIdx.x;
    int tid = threadIdx.x;
    if (n == 0 && tid < Ee) g_cnt[tid] = 0;
    float* hr = hbuf + (size_t)n*Cc;
    float v0, v1;
    if (do_moe) {
        int e0 = g_sel[n*2],     e1 = g_sel[n*2+1];
        int s0 = g_tokslot[n*2], s1 = g_tokslot[n*2+1];
        float w0 = g_gw[n*2],    w1 = g_gw[n*2+1];
        const float* m0 = g_gmo + ((size_t)e0*ECAP + s0)*Cc;
        const float* m1 = g_gmo + ((size_t)e1*ECAP + s1)*Cc;
        v0 = hr[tid]     + w0*m0[tid]     + w1*m1[tid];
        v1 = hr[tid+256] + w0*m0[tid+256] + w1*m1[tid+256];
        hr[tid] = v0; hr[tid+256] = v1;
    } else {
        v0 = hr[tid]; v1 = hr[tid+256];
    }
    __shared__ float red[256];
    red[tid] = v0*v0 + v1*v1;
    __syncthreads();
    for (int o = 128; o > 0; o >>= 1) {
        if (tid < o) red[tid] += red[tid + o];
        __syncthreads();
    }
    float inv = rsqrtf(red[0] / (float)Cc + EPSf);
    float y0 = v0 * inv * w[tid];
    float y1 = v1 * inv * w[tid+256];
    xn[(size_t)n*Cc + tid]       = y0;
    xn[(size_t)n*Cc + tid + 256] = y1;
    __nv_bfloat16 h0 = __float2bfloat16(y0);
    __nv_bfloat16 h1 = __float2bfloat16(y1);
    hi[(size_t)n*Cc + tid]       = h0;
    hi[(size_t)n*Cc + tid + 256] = h1;
    lo[(size_t)n*Cc + tid]       = __float2bfloat16(y0 - __bfloat162float(h0));
    lo[(size_t)n*Cc + tid + 256] = __float2bfloat16(y1 - __bfloat162float(h1));
}

// ---------------- bf16 split helpers ----------------
__device__ __forceinline__ void split4(float4 v, __nv_bfloat162* H, __nv_bfloat162* L, size_t i4) {
    __nv_bfloat16 h0 = __float2bfloat16(v.x);
    __nv_bfloat16 h1 = __float2bfloat16(v.y);
    __nv_bfloat16 h2 = __float2bfloat16(v.z);
    __nv_bfloat16 h3 = __float2bfloat16(v.w);
    H[i4*2]   = __nv_bfloat162{h0, h1};
    H[i4*2+1] = __nv_bfloat162{h2, h3};
    L[i4*2]   = __nv_bfloat162{__float2bfloat16(v.x - __bfloat162float(h0)),
                               __float2bfloat16(v.y - __bfloat162float(h1))};
    L[i4*2+1] = __nv_bfloat162{__float2bfloat16(v.z - __bfloat162float(h2)),
                               __float2bfloat16(v.w - __bfloat162float(h3))};
}

__global__ void split_qkvw_kernel(const float* __restrict__ qw,
                                  const float* __restrict__ kw,
                                  const float* __restrict__ vw) {
    int idx4 = blockIdx.x*blockDim.x + threadIdx.x;
    const int per_l = QKVN*Cc/4;
    if (idx4 >= Ll*per_l) return;
    int l = idx4 / per_l, rem = idx4 - l*per_l;
    int row = rem >> 7, col4 = rem & 127;
    float4 v;
    if (row < 512)       v = ((const float4*)qw)[(size_t)l*(Cc*Cc/4)  + row*128 + col4];
    else if (row < 640)  v = ((const float4*)kw)[(size_t)l*(KVD*Cc/4) + (row-512)*128 + col4];
    else                 v = ((const float4*)vw)[(size_t)l*(KVD*Cc/4) + (row-640)*128 + col4];
    split4(v, (__nv_bfloat162*)g_wqkvh, (__nv_bfloat162*)g_wqkvl, idx4);
}

__global__ void split_ow_exw_kernel(const float* __restrict__ ow,
                                    const float* __restrict__ exw) {
    int idx4 = blockIdx.x*blockDim.x + threadIdx.x;
    const int n_o = Ll*Cc*Cc/4;
    const int n_e = Ll*Ee*Cc*Cc/4;
    if (idx4 < n_o) {
        split4(((const float4*)ow)[idx4], (__nv_bfloat162*)g_woh, (__nv_bfloat162*)g_wol, idx4);
    } else if (idx4 < n_o + n_e) {
        int j = idx4 - n_o;
        split4(((const float4*)exw)[j], (__nv_bfloat162*)g_wexh, (__nv_bfloat162*)g_wexl, j);
    }
}

__global__ void split_outw_kernel(const float* __restrict__ x) {
    int i = blockIdx.x*blockDim.x + threadIdx.x;
    if (i >= Vv*Cc/4) return;
    split4(((const float4*)x)[i], (__nv_bfloat162*)g_wouth, (__nv_bfloat162*)g_woutl, i);
}

// ---------------- mma helpers ----------------
__device__ __forceinline__ void ldsm_x4(uint32_t& r0, uint32_t& r1, uint32_t& r2, uint32_t& r3, uint32_t addr) {
    asm volatile("ldmatrix.sync.aligned.m8n8.x4.shared.b16 {%0,%1,%2,%3}, [%4];"
                 : "=r"(r0), "=r"(r1), "=r"(r2), "=r"(r3) : "r"(addr));
}
__device__ __forceinline__ void mma16816(float* c, uint32_t a0, uint32_t a1, uint32_t a2, uint32_t a3,
                                         uint32_t b0, uint32_t b1) {
    asm volatile("mma.sync.aligned.m16n8k16.row.col.f32.bf16.bf16.f32 "
                 "{%0,%1,%2,%3}, {%4,%5,%6,%7}, {%8,%9}, {%0,%1,%2,%3};"
                 : "+f"(c[0]), "+f"(c[1]), "+f"(c[2]), "+f"(c[3])
                 : "r"(a0), "r"(a1), "r"(a2), "r"(a3), "r"(b0), "r"(b1));
}
__device__ __forceinline__ void cp16(uint32_t smem, const void* gmem) {
    asm volatile("cp.async.cg.shared.global [%0], [%1], 16;" :: "r"(smem), "l"(gmem));
}
__device__ __forceinline__ void cp_commit() {
    asm volatile("cp.async.commit_group;" ::: "memory");
}
template<int N>
__device__ __forceinline__ void cp_wait() {
    asm volatile("cp.async.wait_group %0;" :: "n"(N) : "memory");
}

// ================= 128x64 bf16-split GEMM (all GEMMs, 3 CTAs/SM) =====
#define ARR64_A (128*40*2)        // 10240
#define ARR64_B (64*40*2)         // 5120
#define STG64_B (2*ARR64_A + 2*ARR64_B)   // 30720
#define GEMM64_SMEM (2*STG64_B)   // 61440

__global__ __launch_bounds__(256, 3)
void gemm64_bf16_nt(const __nv_bfloat16* __restrict__ Ah, const __nv_bfloat16* __restrict__ Al,
                    const __nv_bfloat16* __restrict__ Bh, const __nv_bfloat16* __restrict__ Bl,
                    float* __restrict__ Cm, int M, int N, int K,
                    size_t strideA, size_t strideB, size_t strideC,
                    const int* __restrict__ cntPtr, int addC) {
    int row0 = blockIdx.x * 128, col0 = blockIdx.y * 64;
    if (cntPtr && row0 >= cntPtr[blockIdx.z]) return;
    Ah += (size_t)blockIdx.z * strideA;
    Al += (size_t)blockIdx.z * strideA;
    Bh += (size_t)blockIdx.z * strideB;
    Bl += (size_t)blockIdx.z * strideB;
    Cm += (size_t)blockIdx.z * strideC;

    extern __shared__ __align__(16) char smem[];
    uint32_t smem_u32 = (uint32_t)__cvta_generic_to_shared(smem);

    int tid = threadIdx.x;
    int lane = tid & 31, wid = tid >> 5;
    int warpM = wid >> 1, warpN = wid & 1;   // 4 x 2 warp grid; warp tile 32x32

    float acc[2][4][4];
    #pragma unroll
    for (int mi = 0; mi < 2; mi++)
        #pragma unroll
        for (int ni = 0; ni < 4; ni++)
            #pragma unroll
            for (int r = 0; r < 4; r++) acc[mi][ni][r] = 0.f;

    int rA0 = tid >> 2,         fA = tid & 3;
    int rA1 = (tid + 256) >> 2;
    int rB  = tid >> 2;

    int aRow = (lane & 15);
    int aColOff = (lane >> 4) * 8;
    int bRowX4 = (lane & 7) + ((lane >> 4) << 3);
    int bColOff = ((lane >> 3) & 1) * 8;

    const int nk = K >> 5;

    auto load_stage = [&](int stg, int kt) {
        int k0 = kt << 5;
        uint32_t sb = smem_u32 + stg * STG64_B;
        uint32_t dAh = sb, dAl = sb + ARR64_A;
        uint32_t dBh = sb + 2*ARR64_A, dBl = sb + 2*ARR64_A + ARR64_B;
        cp16(dAh + rA0*80 + fA*16, Ah + (size_t)(row0 + rA0)*K + k0 + fA*8);
        cp16(dAh + rA1*80 + fA*16, Ah + (size_t)(row0 + rA1)*K + k0 + fA*8);
        cp16(dAl + rA0*80 + fA*16, Al + (size_t)(row0 + rA0)*K + k0 + fA*8);
        cp16(dAl + rA1*80 + fA*16, Al + (size_t)(row0 + rA1)*K + k0 + fA*8);
        cp16(dBh + rB*80 + fA*16,  Bh + (size_t)(col0 + rB)*K + k0 + fA*8);
        cp16(dBl + rB*80 + fA*16,  Bl + (size_t)(col0 + rB)*K + k0 + fA*8);
        cp_commit();
    };

    load_stage(0, 0);
    if (nk > 1) load_stage(1, 1);

    for (int kt = 0; kt < nk; kt++) {
        int stg = kt & 1;
        if (kt + 1 < nk) cp_wait<1>(); else cp_wait<0>();
        __syncthreads();

        uint32_t sb = smem_u32 + stg * STG64_B;
        uint32_t sAh = sb, sAl = sb + ARR64_A;
        uint32_t sBh = sb + 2*ARR64_A, sBl = sb + 2*ARR64_A + ARR64_B;

        #pragma unroll
        for (int ks = 0; ks < 32; ks += 16) {
            uint32_t bh[4][2], bl[4][2];
            #pragma unroll
            for (int nip = 0; nip < 2; nip++) {
                int brow = warpN*32 + nip*16 + bRowX4;
                uint32_t off = (uint32_t)(brow*80 + (ks + bColOff)*2);
                ldsm_x4(bh[2*nip][0], bh[2*nip][1], bh[2*nip+1][0], bh[2*nip+1][1], sBh + off);
                ldsm_x4(bl[2*nip][0], bl[2*nip][1], bl[2*nip+1][0], bl[2*nip+1][1], sBl + off);
            }
            #pragma unroll
            for (int mi = 0; mi < 2; mi++) {
                int arow = warpM*32 + mi*16 + aRow;
                uint32_t off = (uint32_t)(arow*80 + (ks + aColOff)*2);
                uint32_t ah0, ah1, ah2, ah3, al0, al1, al2, al3;
                ldsm_x4(ah0, ah1, ah2, ah3, sAh + off);
                ldsm_x4(al0, al1, al2, al3, sAl + off);
                #pragma unroll
                for (int ni = 0; ni < 4; ni++)
                    mma16816(acc[mi][ni], ah0, ah1, ah2, ah3, bh[ni][0], bh[ni][1]);
                #pragma unroll
                for (int ni = 0; ni < 4; ni++)
                    mma16816(acc[mi][ni], ah0, ah1, ah2, ah3, bl[ni][0], bl[ni][1]);
                #pragma unroll
                for (int ni = 0; ni < 4; ni++)
                    mma16816(acc[mi][ni], al0, al1, al2, al3, bh[ni][0], bh[ni][1]);
            }
        }
        __syncthreads();
        if (kt + 2 < nk) load_stage(stg, kt + 2);
    }

    #pragma unroll
    for (int mi = 0; mi < 2; mi++) {
        #pragma unroll
        for (int ni = 0; ni < 4; ni++) {
            int r = row0 + warpM*32 + mi*16 + (lane >> 2);
            int c = col0 + warpN*32 + ni*8 + (lane & 3)*2;
            float2 v0 = {acc[mi][ni][0], acc[mi][ni][1]};
            float2 v1 = {acc[mi][ni][2], acc[mi][ni][3]};
            float2* p0 = (float2*)&Cm[(size_t)r*N + c];
            float2* p1 = (float2*)&Cm[(size_t)(r + 8)*N + c];
            if (addC) {
                float2 o0 = *p0, o1 = *p1;
                v0.x += o0.x; v0.y += o0.y; v1.x += o1.x; v1.y += o1.y;
            }
            *p0 = v0;
            *p1 = v1;
        }
    }
}

// ---------------- tiled causal GQA attention: QB=8 queries per block --------
// PV phase: warp pairs share V rows (each float2 feeds 2 queries) => LDS/2.
// part layout: [slot(8)][par(2)][HD] -> stride slot*128 + par*64.
#define ATT_SC_F   (QB*Tt)
#define ATT_TILE_F (128*68)
#define ATT_QS_F   (QB*68)
#define ATT_PART_F (QB*2*HD)
#define ATT_SMEM   ((ATT_SC_F + ATT_TILE_F + ATT_QS_F + ATT_PART_F) * 4)

__global__ __launch_bounds__(256)
void attn_kernel() {
    int q0 = blockIdx.x * QB, hh = blockIdx.y, b = blockIdx.z;
    int kvh = hh >> 2;
    int tid = threadIdx.x;
    int lane = tid & 31, wid = tid >> 5;

    extern __shared__ __align__(16) float smem_f[];
    float* sc   = smem_f;                                     // [QB][Tt]
    float* tile = smem_f + ATT_SC_F;                          // [128][68]
    float* qs   = smem_f + ATT_SC_F + ATT_TILE_F;             // [QB][68]
    float* part = smem_f + ATT_SC_F + ATT_TILE_F + ATT_QS_F;  // [8][2][HD]

    if (tid < QB*16) {
        int qi = tid >> 4, c4 = tid & 15;
        const float4* src = (const float4*)(g_qkv + ((size_t)(b*Tt + q0 + qi))*QKVN + hh*HD);
        *(float4*)&qs[qi*68 + c4*4] = src[c4];
    }

    int nTiles = (q0 + QB + 127) >> 7;

    int qgrp = (wid >> 2) * 4;
    int krow = (wid & 3) * 32 + lane;

    // ---- pass 1: scores ----
    for (int kb = 0; kb < nTiles; kb++) {
        __syncthreads();
        #pragma unroll
        for (int i = 0; i < 8; i++) {
            int f4 = tid + i*256;
            int row = f4 >> 4, c4 = f4 & 15;
            const float4* src = (const float4*)(g_qkv + ((size_t)(b*Tt + kb*128 + row))*QKVN + Cc + kvh*HD);
            *(float4*)&tile[row*68 + c4*4] = src[c4];
        }
        __syncthreads();
        int kg = kb*128 + krow;
        if (kg <= q0 + qgrp + 3) {
            float a0 = 0.f, a1 = 0.f, a2 = 0.f, a3 = 0.f;
            const float4* k4 = (const float4*)&tile[krow*68];
            const float4* q40 = (const float4*)&qs[(qgrp+0)*68];
            const float4* q41 = (const float4*)&qs[(qgrp+1)*68];
            const float4* q42 = (const float4*)&qs[(qgrp+2)*68];
            const float4* q43 = (const float4*)&qs[(qgrp+3)*68];
            #pragma unroll
            for (int j = 0; j < 16; j++) {
                float4 kv = k4[j];
                float4 qv;
                qv = q40[j]; a0 += qv.x*kv.x + qv.y*kv.y + qv.z*kv.z + qv.w*kv.w;
                qv = q41[j]; a1 += qv.x*kv.x + qv.y*kv.y + qv.z*kv.z + qv.w*kv.w;
                qv = q42[j]; a2 += qv.x*kv.x + qv.y*kv.y + qv.z*kv.z + qv.w*kv.w;
                qv = q43[j]; a3 += qv.x*kv.x + qv.y*kv.y + qv.z*kv.z + qv.w*kv.w;
            }
            if (kg <= q0 + qgrp + 0) sc[(qgrp+0)*Tt + kg] = a0 * 0.125f;
            if (kg <= q0 + qgrp + 1) sc[(qgrp+1)*Tt + kg] = a1 * 0.125f;
            if (kg <= q0 + qgrp + 2) sc[(qgrp+2)*Tt + kg] = a2 * 0.125f;
            if (kg <= q0 + qgrp + 3) sc[(qgrp+3)*Tt + kg] = a3 * 0.125f;
        }
    }
    __syncthreads();

    // ---- softmax: warp w handles query q0+w; also zero-fill causal tail ----
    int qg = q0 + wid;
    int nk = qg + 1;
    int tileEnd = nTiles * 128;
    float m = -1e30f;
    for (int k = lane; k < nk; k += 32) m = fmaxf(m, sc[wid*Tt + k]);
    #pragma unroll
    for (int o = 16; o > 0; o >>= 1) m = fmaxf(m, __shfl_xor_sync(0xffffffffu, m, o));
    float s = 0.f;
    for (int k = lane; k < nk; k += 32) {
        float e = expf(sc[wid*Tt + k] - m);
        sc[wid*Tt + k] = e;
        s += e;
    }
    for (int k = nk + lane; k < tileEnd; k += 32) sc[wid*Tt + k] = 0.f;
    #pragma unroll
    for (int o = 16; o > 0; o >>= 1) s += __shfl_xor_sync(0xffffffffu, s, o);
    float inv = 1.f / s;

    // ---- pass 2: PV (warp w: queries (w&3, (w&3)+4), k rows kk%2 == w>>2) ----
    int qp  = wid & 3;
    int par = wid >> 2;
    float2 acc0 = {0.f, 0.f}, acc1 = {0.f, 0.f};
    for (int kb = 0; kb < nTiles; kb++) {
        __syncthreads();
        #pragma unroll
        for (int i = 0; i < 8; i++) {
            int f4 = tid + i*256;
            int row = f4 >> 4, c4 = f4 & 15;
            const float4* src = (const float4*)(g_qkv + ((size_t)(b*Tt + kb*128 + row))*QKVN + Cc + KVD + kvh*HD);
            *(float4*)&tile[row*68 + c4*4] = src[c4];
        }
        __syncthreads();
        const float* sc0 = &sc[qp*Tt + kb*128];
        const float* sc1 = &sc[(qp+4)*Tt + kb*128];
        #pragma unroll 4
        for (int kk = par; kk < 128; kk += 2) {
            float2 v = *(const float2*)&tile[kk*68 + lane*2];
            float a0 = sc0[kk], a1 = sc1[kk];
            acc0.x += a0*v.x; acc0.y += a0*v.y;
            acc1.x += a1*v.x; acc1.y += a1*v.y;
        }
    }
    // combine parities via smem: part[slot][par][d], stride slot*128 + par*64
    {
        int slot0 = qp*2 + 0;   // query qp
        int slot1 = qp*2 + 1;   // query qp+4
        part[slot0*2*HD + par*HD + lane*2]     = acc0.x;
        part[slot0*2*HD + par*HD + lane*2 + 1] = acc0.y;
        part[slot1*2*HD + par*HD + lane*2]     = acc1.x;
        part[slot1*2*HD + par*HD + lane*2 + 1] = acc1.y;
    }
    __syncthreads();
    // warp w outputs query q0+w
    {
        int qq = wid;
        int slot = (qq < 4) ? (qq*2+0) : ((qq-4)*2+1);
        float ox = part[slot*2*HD + 0*HD + lane*2]     + part[slot*2*HD + 1*HD + lane*2];
        float oy = part[slot*2*HD + 0*HD + lane*2 + 1] + part[slot*2*HD + 1*HD + lane*2 + 1];
        ox *= inv; oy *= inv;
        __nv_bfloat16 hx = __float2bfloat16(ox), hy = __float2bfloat16(oy);
        __nv_bfloat16 lx = __float2bfloat16(ox - __bfloat162float(hx));
        __nv_bfloat16 ly = __float2bfloat16(oy - __bfloat162float(hy));
        size_t off = ((size_t)(b*Tt + qg))*Cc + hh*HD + lane*2;
        *(__nv_bfloat162*)&g_ah[off] = __nv_bfloat162{hx, hy};
        *(__nv_bfloat162*)&g_al[off] = __nv_bfloat162{lx, ly};
    }
}

// ---------------- gating: top-2 + softmax + expert list build ----------------
__global__ void gate_kernel(const float* __restrict__ xn, const float* __restrict__ gw) {
    int warp = (blockIdx.x*blockDim.x + threadIdx.x) >> 5;
    int lane = threadIdx.x & 31;
    if (warp >= Nn) return;
    const float* xr = xn + (size_t)warp*Cc;
    float xv[16];
    #pragma unroll
    for (int j = 0; j < 16; j++) xv[j] = xr[lane + j*32];
    float logits[Ee];
    #pragma unroll
    for (int e = 0; e < Ee; e++) {
        float s = 0.f;
        #pragma unroll
        for (int j = 0; j < 16; j++) s += xv[j]*gw[(size_t)e*Cc + lane + j*32];
        #pragma unroll
        for (int o = 16; o > 0; o >>= 1) s += __shfl_down_sync(0xffffffffu, s, o);
        logits[e] = __shfl_sync(0xffffffffu, s, 0);
    }
    if (lane == 0) {
        int b0 = 0;
        #pragma unroll
        for (int e = 1; e < Ee; e++) if (logits[e] > logits[b0]) b0 = e;
        int b1 = -1;
        #pragma unroll
        for (int e = 0; e < Ee; e++) {
            if (e == b0) continue;
            if (b1 < 0 || logits[e] > logits[b1]) b1 = e;
        }
        float mm = logits[b0];
        float e0 = expf(logits[b0] - mm), e1 = expf(logits[b1] - mm);
        float s = e0 + e1;
        g_sel[warp*2]   = b0;   g_sel[warp*2+1] = b1;
        g_gw[warp*2]    = e0/s; g_gw[warp*2+1]  = e1/s;
        int s0 = atomicAdd(&g_cnt[b0], 1);
        g_tokslot[warp*2] = s0;
        g_glist[b0*ECAP + s0] = warp;
        int s1 = atomicAdd(&g_cnt[b1], 1);
        g_tokslot[warp*2+1] = s1;
        g_glist[b1*ECAP + s1] = warp;
    }
}

// ---------------- gather token rows into per-expert buffers ----------------
__global__ void gather_kernel() {
    int m = blockIdx.x, e = blockIdx.y;
    int cnt = g_cnt[e];
    int base = m * 128;
    if (base >= cnt) return;
    int tid = threadIdx.x;
    for (int i = tid; i < 128*64; i += 256) {
        int row = i >> 6, q = i & 63;
        int slot = base + row;
        if (slot >= cnt) continue;
        int tokn = g_glist[e*ECAP + slot];
        size_t dsti = ((size_t)e*ECAP + slot)*64 + q;
        size_t srci = (size_t)tokn*64 + q;
        ((uint4*)g_gah)[dsti] = ((const uint4*)g_ah)[srci];
        ((uint4*)g_gal)[dsti] = ((const uint4*)g_al)[srci];
    }
}

// ---------------- host launcher ----------------
extern "C" void kernel_launch(void* const* d_in, const int* in_sizes, int n_in,
                              void* d_out, int out_size) {
    (void)in_sizes; (void)n_in; (void)out_size;
    const int*   ids        = (const int*)  d_in[0];
    const float* tok        = (const float*)d_in[1];
    const float* pos        = (const float*)d_in[2];
    const float* attn_norm  = (const float*)d_in[3];
    const float* q_w        = (const float*)d_in[4];
    const float* k_w        = (const float*)d_in[5];
    const float* v_w        = (const float*)d_in[6];
    const float* o_w        = (const float*)d_in[7];
    const float* ffn_norm   = (const float*)d_in[8];
    const float* gate_w     = (const float*)d_in[9];
    const float* expert_w   = (const float*)d_in[10];
    const float* final_norm = (const float*)d_in[11];
    const float* out_w      = (const float*)d_in[12];
    float* out = (float*)d_out;

    float *h, *xn, *qkv, *gmo;
    __nv_bfloat16 *ah, *al, *gah, *gal;
    __nv_bfloat16 *wqkvh, *wqkvl, *woh, *wol, *wexh, *wexl, *wouth, *woutl;
    int *cnt;
    cudaGetSymbolAddress((void**)&h,     g_h);
    cudaGetSymbolAddress((void**)&xn,    g_xn);
    cudaGetSymbolAddress((void**)&qkv,   g_qkv);
    cudaGetSymbolAddress((void**)&gmo,   g_gmo);
    cudaGetSymbolAddress((void**)&ah,    g_ah);
    cudaGetSymbolAddress((void**)&al,    g_al);
    cudaGetSymbolAddress((void**)&gah,   g_gah);
    cudaGetSymbolAddress((void**)&gal,   g_gal);
    cudaGetSymbolAddress((void**)&cnt,   g_cnt);
    cudaGetSymbolAddress((void**)&wqkvh, g_wqkvh);
    cudaGetSymbolAddress((void**)&wqkvl, g_wqkvl);
    cudaGetSymbolAddress((void**)&woh,   g_woh);
    cudaGetSymbolAddress((void**)&wol,   g_wol);
    cudaGetSymbolAddress((void**)&wexh,  g_wexh);
    cudaGetSymbolAddress((void**)&wexl,  g_wexl);
    cudaGetSymbolAddress((void**)&wouth, g_wouth);
    cudaGetSymbolAddress((void**)&woutl, g_woutl);

    cudaFuncSetAttribute(gemm64_bf16_nt, cudaFuncAttributeMaxDynamicSharedMemorySize, GEMM64_SMEM);
    cudaFuncSetAttribute(attn_kernel,    cudaFuncAttributeMaxDynamicSharedMemorySize, ATT_SMEM);

    embed_kernel<<<(Nn*Cc + 255)/256, 256>>>(ids, tok, pos);
    rmsnorm_split_kernel<<<Nn, 256>>>(h, attn_norm, xn, ah, al, 0);
    split_qkvw_kernel<<<(Ll*QKVN*Cc/4 + 255)/256, 256>>>(q_w, k_w, v_w);
    {
        int tot = Ll*Cc*Cc/4 + Ll*Ee*Cc*Cc/4;
        split_ow_exw_kernel<<<(tot + 255)/256, 256>>>(o_w, expert_w);
    }
    split_outw_kernel<<<(Vv*Cc/4 + 255)/256, 256>>>(out_w);

    for (int l = 0; l < Ll; l++) {
        if (l > 0) {
            rmsnorm_split_kernel<<<Nn, 256>>>(h, attn_norm + (size_t)l*Cc, xn, ah, al, 1);
        }
        {
            dim3 g(Nn/128, QKVN/64);
            gemm64_bf16_nt<<<g, 256, GEMM64_SMEM>>>(ah, al,
                wqkvh + (size_t)l*QKVN*Cc, wqkvl + (size_t)l*QKVN*Cc,
                qkv, Nn, QKVN, Cc, 0, 0, 0, nullptr, 0);
        }
        {
            dim3 ga(Tt/QB, Hh, Bb);
            attn_kernel<<<ga, 256, ATT_SMEM>>>();
        }
        {
            dim3 g(Nn/128, Cc/64);
            gemm64_bf16_nt<<<g, 256, GEMM64_SMEM>>>(ah, al,
                woh + (size_t)l*Cc*Cc, wol + (size_t)l*Cc*Cc,
                h, Nn, Cc, Cc, 0, 0, 0, nullptr, 1);
        }
        rmsnorm_split_kernel<<<Nn, 256>>>(h, ffn_norm + (size_t)l*Cc, xn, ah, al, 0);
        gate_kernel<<<Nn/8, 256>>>(xn, gate_w + (size_t)l*Ee*Cc);
        {
            dim3 gg(ECAP/128, Ee);
            gather_kernel<<<gg, 256>>>();
        }
        {
            dim3 g(ECAP/128, Cc/64, Ee);
            gemm64_bf16_nt<<<g, 256, GEMM64_SMEM>>>(gah, gal,
                wexh + (size_t)l*Ee*Cc*Cc, wexl + (size_t)l*Ee*Cc*Cc,
                gmo, ECAP, Cc, Cc,
                (size_t)ECAP*Cc, (size_t)Cc*Cc, (size_t)ECAP*Cc, cnt, 0);
        }
    }

    rmsnorm_split_kernel<<<Nn, 256>>>(h, final_norm, xn, ah, al, 1);
    {
        // vocab projection on the 3-CTA/SM BN=64 kernel
        dim3 g(Nn/128, Vv/64);
        gemm64_bf16_nt<<<g, 256, GEMM64_SMEM>>>(ah, al, wouth, woutl, out, Nn, Vv, Cc,
                                                0, 0, 0, nullptr, 0);
    }
}

// round 13
// speedup vs baseline: 1.0544x; 1.0544x over previous
#include <cuda_runtime.h>
#include <cuda_bf16.h>
#include <math.h>
#include <stdint.h>

#define Bb 2
#define Tt 1024
#define Cc 512
#define Hh 8
#define KVh 2
#define HD 64
#define Ll 2
#define Ee 8
#define TOPK 2
#define Vv 32000
#define Nn (Bb*Tt)        // 2048 tokens
#define KVD (KVh*HD)      // 128
#define QKVN (Cc + 2*KVD) // 768
#define ECAP 2048         // per-expert slot capacity
#define QB 8              // queries per attention block
#define EPSf 1e-6f

// ---------------- scratch (device globals; no allocation allowed) ----------------
__device__ float g_h[Nn*Cc];
__device__ float g_xn[Nn*Cc];
__device__ float g_qkv[Nn*QKVN];
__device__ int   g_sel[Nn*TOPK];
__device__ float g_gw[Nn*TOPK];
__device__ int   g_cnt[Ee];
__device__ int   g_glist[Ee*ECAP];
__device__ int   g_tokslot[Nn*TOPK];
__device__ __nv_bfloat16 g_ah[Nn*Cc];
__device__ __nv_bfloat16 g_al[Nn*Cc];
__device__ __nv_bfloat16 g_gah[Ee*ECAP*Cc];
__device__ __nv_bfloat16 g_gal[Ee*ECAP*Cc];
__device__ float g_gmo[Ee*ECAP*Cc];
// pre-split weights (all layers)
__device__ __nv_bfloat16 g_wqkvh[Ll*QKVN*Cc];
__device__ __nv_bfloat16 g_wqkvl[Ll*QKVN*Cc];
__device__ __nv_bfloat16 g_woh[Ll*Cc*Cc];
__device__ __nv_bfloat16 g_wol[Ll*Cc*Cc];
__device__ __nv_bfloat16 g_wexh[Ll*Ee*Cc*Cc];
__device__ __nv_bfloat16 g_wexl[Ll*Ee*Cc*Cc];
__device__ __nv_bfloat16 g_wouth[Vv*Cc];
__device__ __nv_bfloat16 g_woutl[Vv*Cc];

// ---------------- embedding ----------------
__global__ void embed_kernel(const int* __restrict__ ids,
                             const float* __restrict__ tok,
                             const float* __restrict__ pos) {
    int idx = blockIdx.x * blockDim.x + threadIdx.x;
    if (idx >= Nn*Cc) return;
    int n = idx / Cc, c = idx - n*Cc;
    int t = n % Tt;
    g_h[idx] = tok[(size_t)ids[n]*Cc + c] + pos[(size_t)t*Cc + c];
}

// ---- fused (optional moe-combine) + rmsnorm + bf16 split; zeroes counters ----
__global__ void rmsnorm_split_kernel(float* __restrict__ hbuf,
                                     const float* __restrict__ w,
                                     float* __restrict__ xn,
                                     __nv_bfloat16* __restrict__ hi,
                                     __nv_bfloat16* __restrict__ lo,
                                     int do_moe) {
    int n = blockIdx.x;
    int tid = threadIdx.x;
    if (n == 0 && tid < Ee) g_cnt[tid] = 0;
    float* hr = hbuf + (size_t)n*Cc;
    float v0, v1;
    if (do_moe) {
        int e0 = g_sel[n*2],     e1 = g_sel[n*2+1];
        int s0 = g_tokslot[n*2], s1 = g_tokslot[n*2+1];
        float w0 = g_gw[n*2],    w1 = g_gw[n*2+1];
        const float* m0 = g_gmo + ((size_t)e0*ECAP + s0)*Cc;
        const float* m1 = g_gmo + ((size_t)e1*ECAP + s1)*Cc;
        v0 = hr[tid]     + w0*m0[tid]     + w1*m1[tid];
        v1 = hr[tid+256] + w0*m0[tid+256] + w1*m1[tid+256];
        hr[tid] = v0; hr[tid+256] = v1;
    } else {
        v0 = hr[tid]; v1 = hr[tid+256];
    }
    __shared__ float red[256];
    red[tid] = v0*v0 + v1*v1;
    __syncthreads();
    for (int o = 128; o > 0; o >>= 1) {
        if (tid < o) red[tid] += red[tid + o];
        __syncthreads();
    }
    float inv = rsqrtf(red[0] / (float)Cc + EPSf);
    float y0 = v0 * inv * w[tid];
    float y1 = v1 * inv * w[tid+256];
    xn[(size_t)n*Cc + tid]       = y0;
    xn[(size_t)n*Cc + tid + 256] = y1;
    __nv_bfloat16 h0 = __float2bfloat16(y0);
    __nv_bfloat16 h1 = __float2bfloat16(y1);
    hi[(size_t)n*Cc + tid]       = h0;
    hi[(size_t)n*Cc + tid + 256] = h1;
    lo[(size_t)n*Cc + tid]       = __float2bfloat16(y0 - __bfloat162float(h0));
    lo[(size_t)n*Cc + tid + 256] = __float2bfloat16(y1 - __bfloat162float(h1));
}

// ---------------- bf16 split helpers ----------------
__device__ __forceinline__ void split4(float4 v, __nv_bfloat162* H, __nv_bfloat162* L, size_t i4) {
    __nv_bfloat16 h0 = __float2bfloat16(v.x);
    __nv_bfloat16 h1 = __float2bfloat16(v.y);
    __nv_bfloat16 h2 = __float2bfloat16(v.z);
    __nv_bfloat16 h3 = __float2bfloat16(v.w);
    H[i4*2]   = __nv_bfloat162{h0, h1};
    H[i4*2+1] = __nv_bfloat162{h2, h3};
    L[i4*2]   = __nv_bfloat162{__float2bfloat16(v.x - __bfloat162float(h0)),
                               __float2bfloat16(v.y - __bfloat162float(h1))};
    L[i4*2+1] = __nv_bfloat162{__float2bfloat16(v.z - __bfloat162float(h2)),
                               __float2bfloat16(v.w - __bfloat162float(h3))};
}

__global__ void split_qkvw_kernel(const float* __restrict__ qw,
                                  const float* __restrict__ kw,
                                  const float* __restrict__ vw) {
    int idx4 = blockIdx.x*blockDim.x + threadIdx.x;
    const int per_l = QKVN*Cc/4;
    if (idx4 >= Ll*per_l) return;
    int l = idx4 / per_l, rem = idx4 - l*per_l;
    int row = rem >> 7, col4 = rem & 127;
    float4 v;
    if (row < 512)       v = ((const float4*)qw)[(size_t)l*(Cc*Cc/4)  + row*128 + col4];
    else if (row < 640)  v = ((const float4*)kw)[(size_t)l*(KVD*Cc/4) + (row-512)*128 + col4];
    else                 v = ((const float4*)vw)[(size_t)l*(KVD*Cc/4) + (row-640)*128 + col4];
    split4(v, (__nv_bfloat162*)g_wqkvh, (__nv_bfloat162*)g_wqkvl, idx4);
}

__global__ void split_ow_exw_kernel(const float* __restrict__ ow,
                                    const float* __restrict__ exw) {
    int idx4 = blockIdx.x*blockDim.x + threadIdx.x;
    const int n_o = Ll*Cc*Cc/4;
    const int n_e = Ll*Ee*Cc*Cc/4;
    if (idx4 < n_o) {
        split4(((const float4*)ow)[idx4], (__nv_bfloat162*)g_woh, (__nv_bfloat162*)g_wol, idx4);
    } else if (idx4 < n_o + n_e) {
        int j = idx4 - n_o;
        split4(((const float4*)exw)[j], (__nv_bfloat162*)g_wexh, (__nv_bfloat162*)g_wexl, j);
    }
}

__global__ void split_outw_kernel(const float* __restrict__ x) {
    int i = blockIdx.x*blockDim.x + threadIdx.x;
    if (i >= Vv*Cc/4) return;
    split4(((const float4*)x)[i], (__nv_bfloat162*)g_wouth, (__nv_bfloat162*)g_woutl, i);
}

// ---------------- mma helpers ----------------
__device__ __forceinline__ void ldsm_x4(uint32_t& r0, uint32_t& r1, uint32_t& r2, uint32_t& r3, uint32_t addr) {
    asm volatile("ldmatrix.sync.aligned.m8n8.x4.shared.b16 {%0,%1,%2,%3}, [%4];"
                 : "=r"(r0), "=r"(r1), "=r"(r2), "=r"(r3) : "r"(addr));
}
__device__ __forceinline__ void mma16816(float* c, uint32_t a0, uint32_t a1, uint32_t a2, uint32_t a3,
                                         uint32_t b0, uint32_t b1) {
    asm volatile("mma.sync.aligned.m16n8k16.row.col.f32.bf16.bf16.f32 "
                 "{%0,%1,%2,%3}, {%4,%5,%6,%7}, {%8,%9}, {%0,%1,%2,%3};"
                 : "+f"(c[0]), "+f"(c[1]), "+f"(c[2]), "+f"(c[3])
                 : "r"(a0), "r"(a1), "r"(a2), "r"(a3), "r"(b0), "r"(b1));
}
__device__ __forceinline__ void cp16(uint32_t smem, const void* gmem) {
    asm volatile("cp.async.cg.shared.global [%0], [%1], 16;" :: "r"(smem), "l"(gmem));
}
__device__ __forceinline__ void cp_commit() {
    asm volatile("cp.async.commit_group;" ::: "memory");
}
template<int N>
__device__ __forceinline__ void cp_wait() {
    asm volatile("cp.async.wait_group %0;" :: "n"(N) : "memory");
}

// ================= 128x128 bf16-split GEMM (vocab projection) =====
#define ARR_B (128*40*2)
#define STG_B (4*ARR_B)
#define GEMM_SMEM (2*STG_B)       // 81920 bytes

__global__ __launch_bounds__(256, 2)
void gemm_bf16_nt(const __nv_bfloat16* __restrict__ Ah, const __nv_bfloat16* __restrict__ Al,
                  const __nv_bfloat16* __restrict__ Bh, const __nv_bfloat16* __restrict__ Bl,
                  float* __restrict__ Cm, int M, int N, int K) {
    int row0 = blockIdx.x * 128, col0 = blockIdx.y * 128;

    extern __shared__ __align__(16) char smem[];
    uint32_t smem_u32 = (uint32_t)__cvta_generic_to_shared(smem);

    int tid = threadIdx.x;
    int lane = tid & 31, wid = tid >> 5;
    int warpM = wid >> 2, warpN = wid & 3;

    float acc[4][4][4];
    #pragma unroll
    for (int mi = 0; mi < 4; mi++)
        #pragma unroll
        for (int ni = 0; ni < 4; ni++)
            #pragma unroll
            for (int r = 0; r < 4; r++) acc[mi][ni][r] = 0.f;

    int r0c = tid >> 2, f0 = tid & 3;
    int r1c = (tid + 256) >> 2, f1 = tid & 3;

    int aRow = (lane & 15);
    int aColOff = (lane >> 4) * 8;
    int bRowX4 = (lane & 7) + ((lane >> 4) << 3);
    int bColOff = ((lane >> 3) & 1) * 8;

    const int nk = K >> 5;

    auto load_stage = [&](int stg, int kt) {
        int k0 = kt << 5;
        uint32_t sb = smem_u32 + stg * STG_B;
        const __nv_bfloat16* srcs[4] = { Ah, Al, Bh, Bl };
        #pragma unroll
        for (int m = 0; m < 4; m++) {
            const __nv_bfloat16* G = srcs[m];
            int rb = (m < 2) ? row0 : col0;
            uint32_t dst = sb + m * ARR_B;
            cp16(dst + r0c*80 + f0*16, G + (size_t)(rb + r0c)*K + k0 + f0*8);
            cp16(dst + r1c*80 + f1*16, G + (size_t)(rb + r1c)*K + k0 + f1*8);
        }
        cp_commit();
    };

    load_stage(0, 0);
    if (nk > 1) load_stage(1, 1);

    for (int kt = 0; kt < nk; kt++) {
        int stg = kt & 1;
        if (kt + 1 < nk) cp_wait<1>(); else cp_wait<0>();
        __syncthreads();

        uint32_t sb = smem_u32 + stg * STG_B;
        uint32_t sAh = sb, sAl = sb + ARR_B, sBh = sb + 2*ARR_B, sBl = sb + 3*ARR_B;

        #pragma unroll
        for (int ks = 0; ks < 32; ks += 16) {
            uint32_t bh[4][2], bl[4][2];
            #pragma unroll
            for (int nip = 0; nip < 2; nip++) {
                int brow = warpN*32 + nip*16 + bRowX4;
                uint32_t off = (uint32_t)(brow*80 + (ks + bColOff)*2);
                ldsm_x4(bh[2*nip][0], bh[2*nip][1], bh[2*nip+1][0], bh[2*nip+1][1], sBh + off);
                ldsm_x4(bl[2*nip][0], bl[2*nip][1], bl[2*nip+1][0], bl[2*nip+1][1], sBl + off);
            }
            #pragma unroll
            for (int mi = 0; mi < 4; mi++) {
                int arow = warpM*64 + mi*16 + aRow;
                uint32_t off = (uint32_t)(arow*80 + (ks + aColOff)*2);
                uint32_t ah0, ah1, ah2, ah3, al0, al1, al2, al3;
                ldsm_x4(ah0, ah1, ah2, ah3, sAh + off);
                ldsm_x4(al0, al1, al2, al3, sAl + off);
                #pragma unroll
                for (int ni = 0; ni < 4; ni++)
                    mma16816(acc[mi][ni], ah0, ah1, ah2, ah3, bh[ni][0], bh[ni][1]);
                #pragma unroll
                for (int ni = 0; ni < 4; ni++)
                    mma16816(acc[mi][ni], ah0, ah1, ah2, ah3, bl[ni][0], bl[ni][1]);
                #pragma unroll
                for (int ni = 0; ni < 4; ni++)
                    mma16816(acc[mi][ni], al0, al1, al2, al3, bh[ni][0], bh[ni][1]);
            }
        }
        __syncthreads();
        if (kt + 2 < nk) load_stage(stg, kt + 2);
    }

    #pragma unroll
    for (int mi = 0; mi < 4; mi++) {
        #pragma unroll
        for (int ni = 0; ni < 4; ni++) {
            int r = row0 + warpM*64 + mi*16 + (lane >> 2);
            int c = col0 + warpN*32 + ni*8 + (lane & 3)*2;
            float2 v0 = {acc[mi][ni][0], acc[mi][ni][1]};
            float2 v1 = {acc[mi][ni][2], acc[mi][ni][3]};
            *(float2*)&Cm[(size_t)r*N + c]       = v0;
            *(float2*)&Cm[(size_t)(r + 8)*N + c] = v1;
        }
    }
}

// ================= 128x64 bf16-split GEMM (layer GEMMs, 3 CTAs/SM) =====
#define ARR64_A (128*40*2)        // 10240
#define ARR64_B (64*40*2)         // 5120
#define STG64_B (2*ARR64_A + 2*ARR64_B)   // 30720
#define GEMM64_SMEM (2*STG64_B)   // 61440

__global__ __launch_bounds__(256, 3)
void gemm64_bf16_nt(const __nv_bfloat16* __restrict__ Ah, const __nv_bfloat16* __restrict__ Al,
                    const __nv_bfloat16* __restrict__ Bh, const __nv_bfloat16* __restrict__ Bl,
                    float* __restrict__ Cm, int M, int N, int K,
                    size_t strideA, size_t strideB, size_t strideC,
                    const int* __restrict__ cntPtr, int addC) {
    int row0 = blockIdx.x * 128, col0 = blockIdx.y * 64;
    if (cntPtr && row0 >= cntPtr[blockIdx.z]) return;
    Ah += (size_t)blockIdx.z * strideA;
    Al += (size_t)blockIdx.z * strideA;
    Bh += (size_t)blockIdx.z * strideB;
    Bl += (size_t)blockIdx.z * strideB;
    Cm += (size_t)blockIdx.z * strideC;

    extern __shared__ __align__(16) char smem[];
    uint32_t smem_u32 = (uint32_t)__cvta_generic_to_shared(smem);

    int tid = threadIdx.x;
    int lane = tid & 31, wid = tid >> 5;
    int warpM = wid >> 1, warpN = wid & 1;

    float acc[2][4][4];
    #pragma unroll
    for (int mi = 0; mi < 2; mi++)
        #pragma unroll
        for (int ni = 0; ni < 4; ni++)
            #pragma unroll
            for (int r = 0; r < 4; r++) acc[mi][ni][r] = 0.f;

    int rA0 = tid >> 2,         fA = tid & 3;
    int rA1 = (tid + 256) >> 2;
    int rB  = tid >> 2;

    int aRow = (lane & 15);
    int aColOff = (lane >> 4) * 8;
    int bRowX4 = (lane & 7) + ((lane >> 4) << 3);
    int bColOff = ((lane >> 3) & 1) * 8;

    const int nk = K >> 5;

    auto load_stage = [&](int stg, int kt) {
        int k0 = kt << 5;
        uint32_t sb = smem_u32 + stg * STG64_B;
        uint32_t dAh = sb, dAl = sb + ARR64_A;
        uint32_t dBh = sb + 2*ARR64_A, dBl = sb + 2*ARR64_A + ARR64_B;
        cp16(dAh + rA0*80 + fA*16, Ah + (size_t)(row0 + rA0)*K + k0 + fA*8);
        cp16(dAh + rA1*80 + fA*16, Ah + (size_t)(row0 + rA1)*K + k0 + fA*8);
        cp16(dAl + rA0*80 + fA*16, Al + (size_t)(row0 + rA0)*K + k0 + fA*8);
        cp16(dAl + rA1*80 + fA*16, Al + (size_t)(row0 + rA1)*K + k0 + fA*8);
        cp16(dBh + rB*80 + fA*16,  Bh + (size_t)(col0 + rB)*K + k0 + fA*8);
        cp16(dBl + rB*80 + fA*16,  Bl + (size_t)(col0 + rB)*K + k0 + fA*8);
        cp_commit();
    };

    load_stage(0, 0);
    if (nk > 1) load_stage(1, 1);

    for (int kt = 0; kt < nk; kt++) {
        int stg = kt & 1;
        if (kt + 1 < nk) cp_wait<1>(); else cp_wait<0>();
        __syncthreads();

        uint32_t sb = smem_u32 + stg * STG64_B;
        uint32_t sAh = sb, sAl = sb + ARR64_A;
        uint32_t sBh = sb + 2*ARR64_A, sBl = sb + 2*ARR64_A + ARR64_B;

        #pragma unroll
        for (int ks = 0; ks < 32; ks += 16) {
            uint32_t bh[4][2], bl[4][2];
            #pragma unroll
            for (int nip = 0; nip < 2; nip++) {
                int brow = warpN*32 + nip*16 + bRowX4;
                uint32_t off = (uint32_t)(brow*80 + (ks + bColOff)*2);
                ldsm_x4(bh[2*nip][0], bh[2*nip][1], bh[2*nip+1][0], bh[2*nip+1][1], sBh + off);
                ldsm_x4(bl[2*nip][0], bl[2*nip][1], bl[2*nip+1][0], bl[2*nip+1][1], sBl + off);
            }
            #pragma unroll
            for (int mi = 0; mi < 2; mi++) {
                int arow = warpM*32 + mi*16 + aRow;
                uint32_t off = (uint32_t)(arow*80 + (ks + aColOff)*2);
                uint32_t ah0, ah1, ah2, ah3, al0, al1, al2, al3;
                ldsm_x4(ah0, ah1, ah2, ah3, sAh + off);
                ldsm_x4(al0, al1, al2, al3, sAl + off);
                #pragma unroll
                for (int ni = 0; ni < 4; ni++)
                    mma16816(acc[mi][ni], ah0, ah1, ah2, ah3, bh[ni][0], bh[ni][1]);
                #pragma unroll
                for (int ni = 0; ni < 4; ni++)
                    mma16816(acc[mi][ni], ah0, ah1, ah2, ah3, bl[ni][0], bl[ni][1]);
                #pragma unroll
                for (int ni = 0; ni < 4; ni++)
                    mma16816(acc[mi][ni], al0, al1, al2, al3, bh[ni][0], bh[ni][1]);
            }
        }
        __syncthreads();
        if (kt + 2 < nk) load_stage(stg, kt + 2);
    }

    #pragma unroll
    for (int mi = 0; mi < 2; mi++) {
        #pragma unroll
        for (int ni = 0; ni < 4; ni++) {
            int r = row0 + warpM*32 + mi*16 + (lane >> 2);
            int c = col0 + warpN*32 + ni*8 + (lane & 3)*2;
            float2 v0 = {acc[mi][ni][0], acc[mi][ni][1]};
            float2 v1 = {acc[mi][ni][2], acc[mi][ni][3]};
            float2* p0 = (float2*)&Cm[(size_t)r*N + c];
            float2* p1 = (float2*)&Cm[(size_t)(r + 8)*N + c];
            if (addC) {
                float2 o0 = *p0, o1 = *p1;
                v0.x += o0.x; v0.y += o0.y; v1.x += o1.x; v1.y += o1.y;
            }
            *p0 = v0;
            *p1 = v1;
        }
    }
}

// ---------------- tiled causal GQA attention: QB=8 queries per block --------
// PV phase: warp pairs share V rows; part layout [slot(8)][par(2)][HD].
#define ATT_SC_F   (QB*Tt)
#define ATT_TILE_F (128*68)
#define ATT_QS_F   (QB*68)
#define ATT_PART_F (QB*2*HD)
#define ATT_SMEM   ((ATT_SC_F + ATT_TILE_F + ATT_QS_F + ATT_PART_F) * 4)

__global__ __launch_bounds__(256)
void attn_kernel() {
    int q0 = blockIdx.x * QB, hh = blockIdx.y, b = blockIdx.z;
    int kvh = hh >> 2;
    int tid = threadIdx.x;
    int lane = tid & 31, wid = tid >> 5;

    extern __shared__ __align__(16) float smem_f[];
    float* sc   = smem_f;
    float* tile = smem_f + ATT_SC_F;
    float* qs   = smem_f + ATT_SC_F + ATT_TILE_F;
    float* part = smem_f + ATT_SC_F + ATT_TILE_F + ATT_QS_F;

    if (tid < QB*16) {
        int qi = tid >> 4, c4 = tid & 15;
        const float4* src = (const float4*)(g_qkv + ((size_t)(b*Tt + q0 + qi))*QKVN + hh*HD);
        *(float4*)&qs[qi*68 + c4*4] = src[c4];
    }

    int nTiles = (q0 + QB + 127) >> 7;

    int qgrp = (wid >> 2) * 4;
    int krow = (wid & 3) * 32 + lane;

    // ---- pass 1: scores ----
    for (int kb = 0; kb < nTiles; kb++) {
        __syncthreads();
        #pragma unroll
        for (int i = 0; i < 8; i++) {
            int f4 = tid + i*256;
            int row = f4 >> 4, c4 = f4 & 15;
            const float4* src = (const float4*)(g_qkv + ((size_t)(b*Tt + kb*128 + row))*QKVN + Cc + kvh*HD);
            *(float4*)&tile[row*68 + c4*4] = src[c4];
        }
        __syncthreads();
        int kg = kb*128 + krow;
        if (kg <= q0 + qgrp + 3) {
            float a0 = 0.f, a1 = 0.f, a2 = 0.f, a3 = 0.f;
            const float4* k4 = (const float4*)&tile[krow*68];
            const float4* q40 = (const float4*)&qs[(qgrp+0)*68];
            const float4* q41 = (const float4*)&qs[(qgrp+1)*68];
            const float4* q42 = (const float4*)&qs[(qgrp+2)*68];
            const float4* q43 = (const float4*)&qs[(qgrp+3)*68];
            #pragma unroll
            for (int j = 0; j < 16; j++) {
                float4 kv = k4[j];
                float4 qv;
                qv = q40[j]; a0 += qv.x*kv.x + qv.y*kv.y + qv.z*kv.z + qv.w*kv.w;
                qv = q41[j]; a1 += qv.x*kv.x + qv.y*kv.y + qv.z*kv.z + qv.w*kv.w;
                qv = q42[j]; a2 += qv.x*kv.x + qv.y*kv.y + qv.z*kv.z + qv.w*kv.w;
                qv = q43[j]; a3 += qv.x*kv.x + qv.y*kv.y + qv.z*kv.z + qv.w*kv.w;
            }
            if (kg <= q0 + qgrp + 0) sc[(qgrp+0)*Tt + kg] = a0 * 0.125f;
            if (kg <= q0 + qgrp + 1) sc[(qgrp+1)*Tt + kg] = a1 * 0.125f;
            if (kg <= q0 + qgrp + 2) sc[(qgrp+2)*Tt + kg] = a2 * 0.125f;
            if (kg <= q0 + qgrp + 3) sc[(qgrp+3)*Tt + kg] = a3 * 0.125f;
        }
    }
    __syncthreads();

    // ---- softmax + causal-tail zero-fill ----
    int qg = q0 + wid;
    int nk = qg + 1;
    int tileEnd = nTiles * 128;
    float m = -1e30f;
    for (int k = lane; k < nk; k += 32) m = fmaxf(m, sc[wid*Tt + k]);
    #pragma unroll
    for (int o = 16; o > 0; o >>= 1) m = fmaxf(m, __shfl_xor_sync(0xffffffffu, m, o));
    float s = 0.f;
    for (int k = lane; k < nk; k += 32) {
        float e = expf(sc[wid*Tt + k] - m);
        sc[wid*Tt + k] = e;
        s += e;
    }
    for (int k = nk + lane; k < tileEnd; k += 32) sc[wid*Tt + k] = 0.f;
    #pragma unroll
    for (int o = 16; o > 0; o >>= 1) s += __shfl_xor_sync(0xffffffffu, s, o);
    float inv = 1.f / s;

    // ---- pass 2: PV (parity split) ----
    int qp  = wid & 3;
    int par = wid >> 2;
    float2 acc0 = {0.f, 0.f}, acc1 = {0.f, 0.f};
    for (int kb = 0; kb < nTiles; kb++) {
        __syncthreads();
        #pragma unroll
        for (int i = 0; i < 8; i++) {
            int f4 = tid + i*256;
            int row = f4 >> 4, c4 = f4 & 15;
            const float4* src = (const float4*)(g_qkv + ((size_t)(b*Tt + kb*128 + row))*QKVN + Cc + KVD + kvh*HD);
            *(float4*)&tile[row*68 + c4*4] = src[c4];
        }
        __syncthreads();
        const float* sc0 = &sc[qp*Tt + kb*128];
        const float* sc1 = &sc[(qp+4)*Tt + kb*128];
        #pragma unroll 4
        for (int kk = par; kk < 128; kk += 2) {
            float2 v = *(const float2*)&tile[kk*68 + lane*2];
            float a0 = sc0[kk], a1 = sc1[kk];
            acc0.x += a0*v.x; acc0.y += a0*v.y;
            acc1.x += a1*v.x; acc1.y += a1*v.y;
        }
    }
    {
        int slot0 = qp*2 + 0;
        int slot1 = qp*2 + 1;
        part[slot0*2*HD + par*HD + lane*2]     = acc0.x;
        part[slot0*2*HD + par*HD + lane*2 + 1] = acc0.y;
        part[slot1*2*HD + par*HD + lane*2]     = acc1.x;
        part[slot1*2*HD + par*HD + lane*2 + 1] = acc1.y;
    }
    __syncthreads();
    {
        int qq = wid;
        int slot = (qq < 4) ? (qq*2+0) : ((qq-4)*2+1);
        float ox = part[slot*2*HD + 0*HD + lane*2]     + part[slot*2*HD + 1*HD + lane*2];
        float oy = part[slot*2*HD + 0*HD + lane*2 + 1] + part[slot*2*HD + 1*HD + lane*2 + 1];
        ox *= inv; oy *= inv;
        __nv_bfloat16 hx = __float2bfloat16(ox), hy = __float2bfloat16(oy);
        __nv_bfloat16 lx = __float2bfloat16(ox - __bfloat162float(hx));
        __nv_bfloat16 ly = __float2bfloat16(oy - __bfloat162float(hy));
        size_t off = ((size_t)(b*Tt + qg))*Cc + hh*HD + lane*2;
        *(__nv_bfloat162*)&g_ah[off] = __nv_bfloat162{hx, hy};
        *(__nv_bfloat162*)&g_al[off] = __nv_bfloat162{lx, ly};
    }
}

// ---------------- gating: top-2 + softmax + expert list build ----------------
__global__ void gate_kernel(const float* __restrict__ xn, const float* __restrict__ gw) {
    int warp = (blockIdx.x*blockDim.x + threadIdx.x) >> 5;
    int lane = threadIdx.x & 31;
    if (warp >= Nn) return;
    const float* xr = xn + (size_t)warp*Cc;
    float xv[16];
    #pragma unroll
    for (int j = 0; j < 16; j++) xv[j] = xr[lane + j*32];
    float logits[Ee];
    #pragma unroll
    for (int e = 0; e < Ee; e++) {
        float s = 0.f;
        #pragma unroll
        for (int j = 0; j < 16; j++) s += xv[j]*gw[(size_t)e*Cc + lane + j*32];
        #pragma unroll
        for (int o = 16; o > 0; o >>= 1) s += __shfl_down_sync(0xffffffffu, s, o);
        logits[e] = __shfl_sync(0xffffffffu, s, 0);
    }
    if (lane == 0) {
        int b0 = 0;
        #pragma unroll
        for (int e = 1; e < Ee; e++) if (logits[e] > logits[b0]) b0 = e;
        int b1 = -1;
        #pragma unroll
        for (int e = 0; e < Ee; e++) {
            if (e == b0) continue;
            if (b1 < 0 || logits[e] > logits[b1]) b1 = e;
        }
        float mm = logits[b0];
        float e0 = expf(logits[b0] - mm), e1 = expf(logits[b1] - mm);
        float s = e0 + e1;
        g_sel[warp*2]   = b0;   g_sel[warp*2+1] = b1;
        g_gw[warp*2]    = e0/s; g_gw[warp*2+1]  = e1/s;
        int s0 = atomicAdd(&g_cnt[b0], 1);
        g_tokslot[warp*2] = s0;
        g_glist[b0*ECAP + s0] = warp;
        int s1 = atomicAdd(&g_cnt[b1], 1);
        g_tokslot[warp*2+1] = s1;
        g_glist[b1*ECAP + s1] = warp;
    }
}

// ---------------- gather token rows into per-expert buffers ----------------
__global__ void gather_kernel() {
    int m = blockIdx.x, e = blockIdx.y;
    int cnt = g_cnt[e];
    int base = m * 128;
    if (base >= cnt) return;
    int tid = threadIdx.x;
    for (int i = tid; i < 128*64; i += 256) {
        int row = i >> 6, q = i & 63;
        int slot = base + row;
        if (slot >= cnt) continue;
        int tokn = g_glist[e*ECAP + slot];
        size_t dsti = ((size_t)e*ECAP + slot)*64 + q;
        size_t srci = (size_t)tokn*64 + q;
        ((uint4*)g_gah)[dsti] = ((const uint4*)g_ah)[srci];
        ((uint4*)g_gal)[dsti] = ((const uint4*)g_al)[srci];
    }
}

// ---------------- host launcher ----------------
extern "C" void kernel_launch(void* const* d_in, const int* in_sizes, int n_in,
                              void* d_out, int out_size) {
    (void)in_sizes; (void)n_in; (void)out_size;
    const int*   ids        = (const int*)  d_in[0];
    const float* tok        = (const float*)d_in[1];
    const float* pos        = (const float*)d_in[2];
    const float* attn_norm  = (const float*)d_in[3];
    const float* q_w        = (const float*)d_in[4];
    const float* k_w        = (const float*)d_in[5];
    const float* v_w        = (const float*)d_in[6];
    const float* o_w        = (const float*)d_in[7];
    const float* ffn_norm   = (const float*)d_in[8];
    const float* gate_w     = (const float*)d_in[9];
    const float* expert_w   = (const float*)d_in[10];
    const float* final_norm = (const float*)d_in[11];
    const float* out_w      = (const float*)d_in[12];
    float* out = (float*)d_out;

    float *h, *xn, *qkv, *gmo;
    __nv_bfloat16 *ah, *al, *gah, *gal;
    __nv_bfloat16 *wqkvh, *wqkvl, *woh, *wol, *wexh, *wexl, *wouth, *woutl;
    int *cnt;
    cudaGetSymbolAddress((void**)&h,     g_h);
    cudaGetSymbolAddress((void**)&xn,    g_xn);
    cudaGetSymbolAddress((void**)&qkv,   g_qkv);
    cudaGetSymbolAddress((void**)&gmo,   g_gmo);
    cudaGetSymbolAddress((void**)&ah,    g_ah);
    cudaGetSymbolAddress((void**)&al,    g_al);
    cudaGetSymbolAddress((void**)&gah,   g_gah);
    cudaGetSymbolAddress((void**)&gal,   g_gal);
    cudaGetSymbolAddress((void**)&cnt,   g_cnt);
    cudaGetSymbolAddress((void**)&wqkvh, g_wqkvh);
    cudaGetSymbolAddress((void**)&wqkvl, g_wqkvl);
    cudaGetSymbolAddress((void**)&woh,   g_woh);
    cudaGetSymbolAddress((void**)&wol,   g_wol);
    cudaGetSymbolAddress((void**)&wexh,  g_wexh);
    cudaGetSymbolAddress((void**)&wexl,  g_wexl);
    cudaGetSymbolAddress((void**)&wouth, g_wouth);
    cudaGetSymbolAddress((void**)&woutl, g_woutl);

    cudaFuncSetAttribute(gemm_bf16_nt,   cudaFuncAttributeMaxDynamicSharedMemorySize, GEMM_SMEM);
    cudaFuncSetAttribute(gemm64_bf16_nt, cudaFuncAttributeMaxDynamicSharedMemorySize, GEMM64_SMEM);
    cudaFuncSetAttribute(attn_kernel,    cudaFuncAttributeMaxDynamicSharedMemorySize, ATT_SMEM);

    embed_kernel<<<(Nn*Cc + 255)/256, 256>>>(ids, tok, pos);
    rmsnorm_split_kernel<<<Nn, 256>>>(h, attn_norm, xn, ah, al, 0);
    split_qkvw_kernel<<<(Ll*QKVN*Cc/4 + 255)/256, 256>>>(q_w, k_w, v_w);
    {
        int tot = Ll*Cc*Cc/4 + Ll*Ee*Cc*Cc/4;
        split_ow_exw_kernel<<<(tot + 255)/256, 256>>>(o_w, expert_w);
    }
    split_outw_kernel<<<(Vv*Cc/4 + 255)/256, 256>>>(out_w);

    for (int l = 0; l < Ll; l++) {
        if (l > 0) {
            rmsnorm_split_kernel<<<Nn, 256>>>(h, attn_norm + (size_t)l*Cc, xn, ah, al, 1);
        }
        {
            dim3 g(Nn/128, QKVN/64);
            gemm64_bf16_nt<<<g, 256, GEMM64_SMEM>>>(ah, al,
                wqkvh + (size_t)l*QKVN*Cc, wqkvl + (size_t)l*QKVN*Cc,
                qkv, Nn, QKVN, Cc, 0, 0, 0, nullptr, 0);
        }
        {
            dim3 ga(Tt/QB, Hh, Bb);
            attn_kernel<<<ga, 256, ATT_SMEM>>>();
        }
        {
            dim3 g(Nn/128, Cc/64);
            gemm64_bf16_nt<<<g, 256, GEMM64_SMEM>>>(ah, al,
                woh + (size_t)l*Cc*Cc, wol + (size_t)l*Cc*Cc,
                h, Nn, Cc, Cc, 0, 0, 0, nullptr, 1);
        }
        rmsnorm_split_kernel<<<Nn, 256>>>(h, ffn_norm + (size_t)l*Cc, xn, ah, al, 0);
        gate_kernel<<<Nn/8, 256>>>(xn, gate_w + (size_t)l*Ee*Cc);
        {
            dim3 gg(ECAP/128, Ee);
            gather_kernel<<<gg, 256>>>();
        }
        {
            dim3 g(ECAP/128, Cc/64, Ee);
            gemm64_bf16_nt<<<g, 256, GEMM64_SMEM>>>(gah, gal,
                wexh + (size_t)l*Ee*Cc*Cc, wexl + (size_t)l*Ee*Cc*Cc,
                gmo, ECAP, Cc, Cc,
                (size_t)ECAP*Cc, (size_t)Cc*Cc, (size_t)ECAP*Cc, cnt, 0);
        }
    }

    rmsnorm_split_kernel<<<Nn, 256>>>(h, final_norm, xn, ah, al, 1);
    {
        // vocab projection back on the 128x128 kernel (throughput-bound)
        dim3 g(Nn/128, Vv/128);
        gemm_bf16_nt<<<g, 256, GEMM_SMEM>>>(ah, al, wouth, woutl, out, Nn, Vv, Cc);
    }
}

// round 14
// speedup vs baseline: 1.0583x; 1.0038x over previous
#include <cuda_runtime.h>
#include <cuda_bf16.h>
#include <math.h>
#include <stdint.h>

#define Bb 2
#define Tt 1024
#define Cc 512
#define Hh 8
#define KVh 2
#define HD 64
#define Ll 2
#define Ee 8
#define TOPK 2
#define Vv 32000
#define Nn (Bb*Tt)        // 2048 tokens
#define KVD (KVh*HD)      // 128
#define QKVN (Cc + 2*KVD) // 768
#define ECAP 2048         // per-expert slot capacity
#define QB 8              // queries per attention block
#define EPSf 1e-6f

// ---------------- scratch (device globals; no allocation allowed) ----------------
__device__ float g_h[Nn*Cc];
__device__ float g_xn[Nn*Cc];
__device__ float g_qkv[Nn*QKVN];
__device__ int   g_sel[Nn*TOPK];
__device__ float g_gw[Nn*TOPK];
__device__ int   g_cnt[Ee];
__device__ int   g_glist[Ee*ECAP];
__device__ int   g_tokslot[Nn*TOPK];
__device__ __nv_bfloat16 g_ah[Nn*Cc];
__device__ __nv_bfloat16 g_al[Nn*Cc];
__device__ __nv_bfloat16 g_gah[Ee*ECAP*Cc];
__device__ __nv_bfloat16 g_gal[Ee*ECAP*Cc];
__device__ float g_gmo[Ee*ECAP*Cc];
// pre-split weights (all layers)
__device__ __nv_bfloat16 g_wqkvh[Ll*QKVN*Cc];
__device__ __nv_bfloat16 g_wqkvl[Ll*QKVN*Cc];
__device__ __nv_bfloat16 g_woh[Ll*Cc*Cc];
__device__ __nv_bfloat16 g_wol[Ll*Cc*Cc];
__device__ __nv_bfloat16 g_wexh[Ll*Ee*Cc*Cc];
__device__ __nv_bfloat16 g_wexl[Ll*Ee*Cc*Cc];
__device__ __nv_bfloat16 g_wouth[Vv*Cc];
__device__ __nv_bfloat16 g_woutl[Vv*Cc];

// ---- fused embed + rmsnorm + bf16 split (first layer entry; zeroes counters) ----
__global__ void embed_rmsnorm_split_kernel(const int* __restrict__ ids,
                                           const float* __restrict__ tok,
                                           const float* __restrict__ pos,
                                           const float* __restrict__ w,
                                           float* __restrict__ hbuf,
                                           float* __restrict__ xn,
                                           __nv_bfloat16* __restrict__ hi,
                                           __nv_bfloat16* __restrict__ lo) {
    int n = blockIdx.x;
    int tid = threadIdx.x;
    if (n == 0 && tid < Ee) g_cnt[tid] = 0;
    int t = n % Tt;
    size_t tb = (size_t)ids[n]*Cc, pb = (size_t)t*Cc;
    float v0 = tok[tb + tid]       + pos[pb + tid];
    float v1 = tok[tb + tid + 256] + pos[pb + tid + 256];
    hbuf[(size_t)n*Cc + tid]       = v0;
    hbuf[(size_t)n*Cc + tid + 256] = v1;
    __shared__ float red[256];
    red[tid] = v0*v0 + v1*v1;
    __syncthreads();
    for (int o = 128; o > 0; o >>= 1) {
        if (tid < o) red[tid] += red[tid + o];
        __syncthreads();
    }
    float inv = rsqrtf(red[0] / (float)Cc + EPSf);
    float y0 = v0 * inv * w[tid];
    float y1 = v1 * inv * w[tid+256];
    xn[(size_t)n*Cc + tid]       = y0;
    xn[(size_t)n*Cc + tid + 256] = y1;
    __nv_bfloat16 h0 = __float2bfloat16(y0);
    __nv_bfloat16 h1 = __float2bfloat16(y1);
    hi[(size_t)n*Cc + tid]       = h0;
    hi[(size_t)n*Cc + tid + 256] = h1;
    lo[(size_t)n*Cc + tid]       = __float2bfloat16(y0 - __bfloat162float(h0));
    lo[(size_t)n*Cc + tid + 256] = __float2bfloat16(y1 - __bfloat162float(h1));
}

// ---- fused (optional moe-combine) + rmsnorm + bf16 split; zeroes counters ----
__global__ void rmsnorm_split_kernel(float* __restrict__ hbuf,
                                     const float* __restrict__ w,
                                     float* __restrict__ xn,
                                     __nv_bfloat16* __restrict__ hi,
                                     __nv_bfloat16* __restrict__ lo,
                                     int do_moe) {
    int n = blockIdx.x;
    int tid = threadIdx.x;
    if (n == 0 && tid < Ee) g_cnt[tid] = 0;
    float* hr = hbuf + (size_t)n*Cc;
    float v0, v1;
    if (do_moe) {
        int e0 = g_sel[n*2],     e1 = g_sel[n*2+1];
        int s0 = g_tokslot[n*2], s1 = g_tokslot[n*2+1];
        float w0 = g_gw[n*2],    w1 = g_gw[n*2+1];
        const float* m0 = g_gmo + ((size_t)e0*ECAP + s0)*Cc;
        const float* m1 = g_gmo + ((size_t)e1*ECAP + s1)*Cc;
        v0 = hr[tid]     + w0*m0[tid]     + w1*m1[tid];
        v1 = hr[tid+256] + w0*m0[tid+256] + w1*m1[tid+256];
        hr[tid] = v0; hr[tid+256] = v1;
    } else {
        v0 = hr[tid]; v1 = hr[tid+256];
    }
    __shared__ float red[256];
    red[tid] = v0*v0 + v1*v1;
    __syncthreads();
    for (int o = 128; o > 0; o >>= 1) {
        if (tid < o) red[tid] += red[tid + o];
        __syncthreads();
    }
    float inv = rsqrtf(red[0] / (float)Cc + EPSf);
    float y0 = v0 * inv * w[tid];
    float y1 = v1 * inv * w[tid+256];
    xn[(size_t)n*Cc + tid]       = y0;
    xn[(size_t)n*Cc + tid + 256] = y1;
    __nv_bfloat16 h0 = __float2bfloat16(y0);
    __nv_bfloat16 h1 = __float2bfloat16(y1);
    hi[(size_t)n*Cc + tid]       = h0;
    hi[(size_t)n*Cc + tid + 256] = h1;
    lo[(size_t)n*Cc + tid]       = __float2bfloat16(y0 - __bfloat162float(h0));
    lo[(size_t)n*Cc + tid + 256] = __float2bfloat16(y1 - __bfloat162float(h1));
}

// ---------------- bf16 split helpers ----------------
__device__ __forceinline__ void split4(float4 v, __nv_bfloat162* H, __nv_bfloat162* L, size_t i4) {
    __nv_bfloat16 h0 = __float2bfloat16(v.x);
    __nv_bfloat16 h1 = __float2bfloat16(v.y);
    __nv_bfloat16 h2 = __float2bfloat16(v.z);
    __nv_bfloat16 h3 = __float2bfloat16(v.w);
    H[i4*2]   = __nv_bfloat162{h0, h1};
    H[i4*2+1] = __nv_bfloat162{h2, h3};
    L[i4*2]   = __nv_bfloat162{__float2bfloat16(v.x - __bfloat162float(h0)),
                               __float2bfloat16(v.y - __bfloat162float(h1))};
    L[i4*2+1] = __nv_bfloat162{__float2bfloat16(v.z - __bfloat162float(h2)),
                               __float2bfloat16(v.w - __bfloat162float(h3))};
}

__global__ void split_qkvw_kernel(const float* __restrict__ qw,
                                  const float* __restrict__ kw,
                                  const float* __restrict__ vw) {
    int idx4 = blockIdx.x*blockDim.x + threadIdx.x;
    const int per_l = QKVN*Cc/4;
    if (idx4 >= Ll*per_l) return;
    int l = idx4 / per_l, rem = idx4 - l*per_l;
    int row = rem >> 7, col4 = rem & 127;
    float4 v;
    if (row < 512)       v = ((const float4*)qw)[(size_t)l*(Cc*Cc/4)  + row*128 + col4];
    else if (row < 640)  v = ((const float4*)kw)[(size_t)l*(KVD*Cc/4) + (row-512)*128 + col4];
    else                 v = ((const float4*)vw)[(size_t)l*(KVD*Cc/4) + (row-640)*128 + col4];
    split4(v, (__nv_bfloat162*)g_wqkvh, (__nv_bfloat162*)g_wqkvl, idx4);
}

__global__ void split_ow_exw_kernel(const float* __restrict__ ow,
                                    const float* __restrict__ exw) {
    int idx4 = blockIdx.x*blockDim.x + threadIdx.x;
    const int n_o = Ll*Cc*Cc/4;
    const int n_e = Ll*Ee*Cc*Cc/4;
    if (idx4 < n_o) {
        split4(((const float4*)ow)[idx4], (__nv_bfloat162*)g_woh, (__nv_bfloat162*)g_wol, idx4);
    } else if (idx4 < n_o + n_e) {
        int j = idx4 - n_o;
        split4(((const float4*)exw)[j], (__nv_bfloat162*)g_wexh, (__nv_bfloat162*)g_wexl, j);
    }
}

__global__ void split_outw_kernel(const float* __restrict__ x) {
    int i = blockIdx.x*blockDim.x + threadIdx.x;
    if (i >= Vv*Cc/4) return;
    split4(((const float4*)x)[i], (__nv_bfloat162*)g_wouth, (__nv_bfloat162*)g_woutl, i);
}

// ---------------- mma helpers ----------------
__device__ __forceinline__ void ldsm_x4(uint32_t& r0, uint32_t& r1, uint32_t& r2, uint32_t& r3, uint32_t addr) {
    asm volatile("ldmatrix.sync.aligned.m8n8.x4.shared.b16 {%0,%1,%2,%3}, [%4];"
                 : "=r"(r0), "=r"(r1), "=r"(r2), "=r"(r3) : "r"(addr));
}
__device__ __forceinline__ void mma16816(float* c, uint32_t a0, uint32_t a1, uint32_t a2, uint32_t a3,
                                         uint32_t b0, uint32_t b1) {
    asm volatile("mma.sync.aligned.m16n8k16.row.col.f32.bf16.bf16.f32 "
                 "{%0,%1,%2,%3}, {%4,%5,%6,%7}, {%8,%9}, {%0,%1,%2,%3};"
                 : "+f"(c[0]), "+f"(c[1]), "+f"(c[2]), "+f"(c[3])
                 : "r"(a0), "r"(a1), "r"(a2), "r"(a3), "r"(b0), "r"(b1));
}
__device__ __forceinline__ void cp16(uint32_t smem, const void* gmem) {
    asm volatile("cp.async.cg.shared.global [%0], [%1], 16;" :: "r"(smem), "l"(gmem));
}
__device__ __forceinline__ void cp_commit() {
    asm volatile("cp.async.commit_group;" ::: "memory");
}
template<int N>
__device__ __forceinline__ void cp_wait() {
    asm volatile("cp.async.wait_group %0;" :: "n"(N) : "memory");
}

// ================= 128x128 bf16-split GEMM (vocab projection) =====
#define ARR_B (128*40*2)
#define STG_B (4*ARR_B)
#define GEMM_SMEM (2*STG_B)       // 81920 bytes

__global__ __launch_bounds__(256, 2)
void gemm_bf16_nt(const __nv_bfloat16* __restrict__ Ah, const __nv_bfloat16* __restrict__ Al,
                  const __nv_bfloat16* __restrict__ Bh, const __nv_bfloat16* __restrict__ Bl,
                  float* __restrict__ Cm, int M, int N, int K) {
    int row0 = blockIdx.x * 128, col0 = blockIdx.y * 128;

    extern __shared__ __align__(16) char smem[];
    uint32_t smem_u32 = (uint32_t)__cvta_generic_to_shared(smem);

    int tid = threadIdx.x;
    int lane = tid & 31, wid = tid >> 5;
    int warpM = wid >> 2, warpN = wid & 3;

    float acc[4][4][4];
    #pragma unroll
    for (int mi = 0; mi < 4; mi++)
        #pragma unroll
        for (int ni = 0; ni < 4; ni++)
            #pragma unroll
            for (int r = 0; r < 4; r++) acc[mi][ni][r] = 0.f;

    int r0c = tid >> 2, f0 = tid & 3;
    int r1c = (tid + 256) >> 2, f1 = tid & 3;

    int aRow = (lane & 15);
    int aColOff = (lane >> 4) * 8;
    int bRowX4 = (lane & 7) + ((lane >> 4) << 3);
    int bColOff = ((lane >> 3) & 1) * 8;

    const int nk = K >> 5;

    auto load_stage = [&](int stg, int kt) {
        int k0 = kt << 5;
        uint32_t sb = smem_u32 + stg * STG_B;
        const __nv_bfloat16* srcs[4] = { Ah, Al, Bh, Bl };
        #pragma unroll
        for (int m = 0; m < 4; m++) {
            const __nv_bfloat16* G = srcs[m];
            int rb = (m < 2) ? row0 : col0;
            uint32_t dst = sb + m * ARR_B;
            cp16(dst + r0c*80 + f0*16, G + (size_t)(rb + r0c)*K + k0 + f0*8);
            cp16(dst + r1c*80 + f1*16, G + (size_t)(rb + r1c)*K + k0 + f1*8);
        }
        cp_commit();
    };

    load_stage(0, 0);
    if (nk > 1) load_stage(1, 1);

    for (int kt = 0; kt < nk; kt++) {
        int stg = kt & 1;
        if (kt + 1 < nk) cp_wait<1>(); else cp_wait<0>();
        __syncthreads();

        uint32_t sb = smem_u32 + stg * STG_B;
        uint32_t sAh = sb, sAl = sb + ARR_B, sBh = sb + 2*ARR_B, sBl = sb + 3*ARR_B;

        #pragma unroll
        for (int ks = 0; ks < 32; ks += 16) {
            uint32_t bh[4][2], bl[4][2];
            #pragma unroll
            for (int nip = 0; nip < 2; nip++) {
                int brow = warpN*32 + nip*16 + bRowX4;
                uint32_t off = (uint32_t)(brow*80 + (ks + bColOff)*2);
                ldsm_x4(bh[2*nip][0], bh[2*nip][1], bh[2*nip+1][0], bh[2*nip+1][1], sBh + off);
                ldsm_x4(bl[2*nip][0], bl[2*nip][1], bl[2*nip+1][0], bl[2*nip+1][1], sBl + off);
            }
            #pragma unroll
            for (int mi = 0; mi < 4; mi++) {
                int arow = warpM*64 + mi*16 + aRow;
                uint32_t off = (uint32_t)(arow*80 + (ks + aColOff)*2);
                uint32_t ah0, ah1, ah2, ah3, al0, al1, al2, al3;
                ldsm_x4(ah0, ah1, ah2, ah3, sAh + off);
                ldsm_x4(al0, al1, al2, al3, sAl + off);
                #pragma unroll
                for (int ni = 0; ni < 4; ni++)
                    mma16816(acc[mi][ni], ah0, ah1, ah2, ah3, bh[ni][0], bh[ni][1]);
                #pragma unroll
                for (int ni = 0; ni < 4; ni++)
                    mma16816(acc[mi][ni], ah0, ah1, ah2, ah3, bl[ni][0], bl[ni][1]);
                #pragma unroll
                for (int ni = 0; ni < 4; ni++)
                    mma16816(acc[mi][ni], al0, al1, al2, al3, bh[ni][0], bh[ni][1]);
            }
        }
        __syncthreads();
        if (kt + 2 < nk) load_stage(stg, kt + 2);
    }

    #pragma unroll
    for (int mi = 0; mi < 4; mi++) {
        #pragma unroll
        for (int ni = 0; ni < 4; ni++) {
            int r = row0 + warpM*64 + mi*16 + (lane >> 2);
            int c = col0 + warpN*32 + ni*8 + (lane & 3)*2;
            float2 v0 = {acc[mi][ni][0], acc[mi][ni][1]};
            float2 v1 = {acc[mi][ni][2], acc[mi][ni][3]};
            *(float2*)&Cm[(size_t)r*N + c]       = v0;
            *(float2*)&Cm[(size_t)(r + 8)*N + c] = v1;
        }
    }
}

// ================= 128x64 bf16-split GEMM (layer GEMMs, 3 CTAs/SM) =====
#define ARR64_A (128*40*2)        // 10240
#define ARR64_B (64*40*2)         // 5120
#define STG64_B (2*ARR64_A + 2*ARR64_B)   // 30720
#define GEMM64_SMEM (2*STG64_B)   // 61440

__global__ __launch_bounds__(256, 3)
void gemm64_bf16_nt(const __nv_bfloat16* __restrict__ Ah, const __nv_bfloat16* __restrict__ Al,
                    const __nv_bfloat16* __restrict__ Bh, const __nv_bfloat16* __restrict__ Bl,
                    float* __restrict__ Cm, int M, int N, int K,
                    size_t strideA, size_t strideB, size_t strideC,
                    const int* __restrict__ cntPtr, int addC) {
    int row0 = blockIdx.x * 128, col0 = blockIdx.y * 64;
    if (cntPtr && row0 >= cntPtr[blockIdx.z]) return;
    Ah += (size_t)blockIdx.z * strideA;
    Al += (size_t)blockIdx.z * strideA;
    Bh += (size_t)blockIdx.z * strideB;
    Bl += (size_t)blockIdx.z * strideB;
    Cm += (size_t)blockIdx.z * strideC;

    extern __shared__ __align__(16) char smem[];
    uint32_t smem_u32 = (uint32_t)__cvta_generic_to_shared(smem);

    int tid = threadIdx.x;
    int lane = tid & 31, wid = tid >> 5;
    int warpM = wid >> 1, warpN = wid & 1;

    float acc[2][4][4];
    #pragma unroll
    for (int mi = 0; mi < 2; mi++)
        #pragma unroll
        for (int ni = 0; ni < 4; ni++)
            #pragma unroll
            for (int r = 0; r < 4; r++) acc[mi][ni][r] = 0.f;

    int rA0 = tid >> 2,         fA = tid & 3;
    int rA1 = (tid + 256) >> 2;
    int rB  = tid >> 2;

    int aRow = (lane & 15);
    int aColOff = (lane >> 4) * 8;
    int bRowX4 = (lane & 7) + ((lane >> 4) << 3);
    int bColOff = ((lane >> 3) & 1) * 8;

    const int nk = K >> 5;

    auto load_stage = [&](int stg, int kt) {
        int k0 = kt << 5;
        uint32_t sb = smem_u32 + stg * STG64_B;
        uint32_t dAh = sb, dAl = sb + ARR64_A;
        uint32_t dBh = sb + 2*ARR64_A, dBl = sb + 2*ARR64_A + ARR64_B;
        cp16(dAh + rA0*80 + fA*16, Ah + (size_t)(row0 + rA0)*K + k0 + fA*8);
        cp16(dAh + rA1*80 + fA*16, Ah + (size_t)(row0 + rA1)*K + k0 + fA*8);
        cp16(dAl + rA0*80 + fA*16, Al + (size_t)(row0 + rA0)*K + k0 + fA*8);
        cp16(dAl + rA1*80 + fA*16, Al + (size_t)(row0 + rA1)*K + k0 + fA*8);
        cp16(dBh + rB*80 + fA*16,  Bh + (size_t)(col0 + rB)*K + k0 + fA*8);
        cp16(dBl + rB*80 + fA*16,  Bl + (size_t)(col0 + rB)*K + k0 + fA*8);
        cp_commit();
    };

    load_stage(0, 0);
    if (nk > 1) load_stage(1, 1);

    for (int kt = 0; kt < nk; kt++) {
        int stg = kt & 1;
        if (kt + 1 < nk) cp_wait<1>(); else cp_wait<0>();
        __syncthreads();

        uint32_t sb = smem_u32 + stg * STG64_B;
        uint32_t sAh = sb, sAl = sb + ARR64_A;
        uint32_t sBh = sb + 2*ARR64_A, sBl = sb + 2*ARR64_A + ARR64_B;

        #pragma unroll
        for (int ks = 0; ks < 32; ks += 16) {
            uint32_t bh[4][2], bl[4][2];
            #pragma unroll
            for (int nip = 0; nip < 2; nip++) {
                int brow = warpN*32 + nip*16 + bRowX4;
                uint32_t off = (uint32_t)(brow*80 + (ks + bColOff)*2);
                ldsm_x4(bh[2*nip][0], bh[2*nip][1], bh[2*nip+1][0], bh[2*nip+1][1], sBh + off);
                ldsm_x4(bl[2*nip][0], bl[2*nip][1], bl[2*nip+1][0], bl[2*nip+1][1], sBl + off);
            }
            #pragma unroll
            for (int mi = 0; mi < 2; mi++) {
                int arow = warpM*32 + mi*16 + aRow;
                uint32_t off = (uint32_t)(arow*80 + (ks + aColOff)*2);
                uint32_t ah0, ah1, ah2, ah3, al0, al1, al2, al3;
                ldsm_x4(ah0, ah1, ah2, ah3, sAh + off);
                ldsm_x4(al0, al1, al2, al3, sAl + off);
                #pragma unroll
                for (int ni = 0; ni < 4; ni++)
                    mma16816(acc[mi][ni], ah0, ah1, ah2, ah3, bh[ni][0], bh[ni][1]);
                #pragma unroll
                for (int ni = 0; ni < 4; ni++)
                    mma16816(acc[mi][ni], ah0, ah1, ah2, ah3, bl[ni][0], bl[ni][1]);
                #pragma unroll
                for (int ni = 0; ni < 4; ni++)
                    mma16816(acc[mi][ni], al0, al1, al2, al3, bh[ni][0], bh[ni][1]);
            }
        }
        __syncthreads();
        if (kt + 2 < nk) load_stage(stg, kt + 2);
    }

    #pragma unroll
    for (int mi = 0; mi < 2; mi++) {
        #pragma unroll
        for (int ni = 0; ni < 4; ni++) {
            int r = row0 + warpM*32 + mi*16 + (lane >> 2);
            int c = col0 + warpN*32 + ni*8 + (lane & 3)*2;
            float2 v0 = {acc[mi][ni][0], acc[mi][ni][1]};
            float2 v1 = {acc[mi][ni][2], acc[mi][ni][3]};
            float2* p0 = (float2*)&Cm[(size_t)r*N + c];
            float2* p1 = (float2*)&Cm[(size_t)(r + 8)*N + c];
            if (addC) {
                float2 o0 = *p0, o1 = *p1;
                v0.x += o0.x; v0.y += o0.y; v1.x += o1.x; v1.y += o1.y;
            }
            *p0 = v0;
            *p1 = v1;
        }
    }
}

// ---------------- tiled causal GQA attention ----------------
#define ATT_SC_F   (QB*Tt)
#define ATT_TILE_F (128*68)
#define ATT_QS_F   (QB*68)
#define ATT_PART_F (QB*2*HD)
#define ATT_SMEM   ((ATT_SC_F + ATT_TILE_F + ATT_QS_F + ATT_PART_F) * 4)

__global__ __launch_bounds__(256)
void attn_kernel() {
    int q0 = blockIdx.x * QB, hh = blockIdx.y, b = blockIdx.z;
    int kvh = hh >> 2;
    int tid = threadIdx.x;
    int lane = tid & 31, wid = tid >> 5;

    extern __shared__ __align__(16) float smem_f[];
    float* sc   = smem_f;
    float* tile = smem_f + ATT_SC_F;
    float* qs   = smem_f + ATT_SC_F + ATT_TILE_F;
    float* part = smem_f + ATT_SC_F + ATT_TILE_F + ATT_QS_F;

    if (tid < QB*16) {
        int qi = tid >> 4, c4 = tid & 15;
        const float4* src = (const float4*)(g_qkv + ((size_t)(b*Tt + q0 + qi))*QKVN + hh*HD);
        *(float4*)&qs[qi*68 + c4*4] = src[c4];
    }

    int nTiles = (q0 + QB + 127) >> 7;

    int qgrp = (wid >> 2) * 4;
    int krow = (wid & 3) * 32 + lane;

    for (int kb = 0; kb < nTiles; kb++) {
        __syncthreads();
        #pragma unroll
        for (int i = 0; i < 8; i++) {
            int f4 = tid + i*256;
            int row = f4 >> 4, c4 = f4 & 15;
            const float4* src = (const float4*)(g_qkv + ((size_t)(b*Tt + kb*128 + row))*QKVN + Cc + kvh*HD);
            *(float4*)&tile[row*68 + c4*4] = src[c4];
        }
        __syncthreads();
        int kg = kb*128 + krow;
        if (kg <= q0 + qgrp + 3) {
            float a0 = 0.f, a1 = 0.f, a2 = 0.f, a3 = 0.f;
            const float4* k4 = (const float4*)&tile[krow*68];
            const float4* q40 = (const float4*)&qs[(qgrp+0)*68];
            const float4* q41 = (const float4*)&qs[(qgrp+1)*68];
            const float4* q42 = (const float4*)&qs[(qgrp+2)*68];
            const float4* q43 = (const float4*)&qs[(qgrp+3)*68];
            #pragma unroll
            for (int j = 0; j < 16; j++) {
                float4 kv = k4[j];
                float4 qv;
                qv = q40[j]; a0 += qv.x*kv.x + qv.y*kv.y + qv.z*kv.z + qv.w*kv.w;
                qv = q41[j]; a1 += qv.x*kv.x + qv.y*kv.y + qv.z*kv.z + qv.w*kv.w;
                qv = q42[j]; a2 += qv.x*kv.x + qv.y*kv.y + qv.z*kv.z + qv.w*kv.w;
                qv = q43[j]; a3 += qv.x*kv.x + qv.y*kv.y + qv.z*kv.z + qv.w*kv.w;
            }
            if (kg <= q0 + qgrp + 0) sc[(qgrp+0)*Tt + kg] = a0 * 0.125f;
            if (kg <= q0 + qgrp + 1) sc[(qgrp+1)*Tt + kg] = a1 * 0.125f;
            if (kg <= q0 + qgrp + 2) sc[(qgrp+2)*Tt + kg] = a2 * 0.125f;
            if (kg <= q0 + qgrp + 3) sc[(qgrp+3)*Tt + kg] = a3 * 0.125f;
        }
    }
    __syncthreads();

    int qg = q0 + wid;
    int nk = qg + 1;
    int tileEnd = nTiles * 128;
    float m = -1e30f;
    for (int k = lane; k < nk; k += 32) m = fmaxf(m, sc[wid*Tt + k]);
    #pragma unroll
    for (int o = 16; o > 0; o >>= 1) m = fmaxf(m, __shfl_xor_sync(0xffffffffu, m, o));
    float s = 0.f;
    for (int k = lane; k < nk; k += 32) {
        float e = expf(sc[wid*Tt + k] - m);
        sc[wid*Tt + k] = e;
        s += e;
    }
    for (int k = nk + lane; k < tileEnd; k += 32) sc[wid*Tt + k] = 0.f;
    #pragma unroll
    for (int o = 16; o > 0; o >>= 1) s += __shfl_xor_sync(0xffffffffu, s, o);
    float inv = 1.f / s;

    int qp  = wid & 3;
    int par = wid >> 5 == 0 ? (wid >> 2) : 0;  // wid in [0,8): par = wid>>2
    par = wid >> 2;
    float2 acc0 = {0.f, 0.f}, acc1 = {0.f, 0.f};
    for (int kb = 0; kb < nTiles; kb++) {
        __syncthreads();
        #pragma unroll
        for (int i = 0; i < 8; i++) {
            int f4 = tid + i*256;
            int row = f4 >> 4, c4 = f4 & 15;
            const float4* src = (const float4*)(g_qkv + ((size_t)(b*Tt + kb*128 + row))*QKVN + Cc + KVD + kvh*HD);
            *(float4*)&tile[row*68 + c4*4] = src[c4];
        }
        __syncthreads();
        const float* sc0 = &sc[qp*Tt + kb*128];
        const float* sc1 = &sc[(qp+4)*Tt + kb*128];
        #pragma unroll 4
        for (int kk = par; kk < 128; kk += 2) {
            float2 v = *(const float2*)&tile[kk*68 + lane*2];
            float a0 = sc0[kk], a1 = sc1[kk];
            acc0.x += a0*v.x; acc0.y += a0*v.y;
            acc1.x += a1*v.x; acc1.y += a1*v.y;
        }
    }
    {
        int slot0 = qp*2 + 0;
        int slot1 = qp*2 + 1;
        part[slot0*2*HD + par*HD + lane*2]     = acc0.x;
        part[slot0*2*HD + par*HD + lane*2 + 1] = acc0.y;
        part[slot1*2*HD + par*HD + lane*2]     = acc1.x;
        part[slot1*2*HD + par*HD + lane*2 + 1] = acc1.y;
    }
    __syncthreads();
    {
        int qq = wid;
        int slot = (qq < 4) ? (qq*2+0) : ((qq-4)*2+1);
        float ox = part[slot*2*HD + 0*HD + lane*2]     + part[slot*2*HD + 1*HD + lane*2];
        float oy = part[slot*2*HD + 0*HD + lane*2 + 1] + part[slot*2*HD + 1*HD + lane*2 + 1];
        ox *= inv; oy *= inv;
        __nv_bfloat16 hx = __float2bfloat16(ox), hy = __float2bfloat16(oy);
        __nv_bfloat16 lx = __float2bfloat16(ox - __bfloat162float(hx));
        __nv_bfloat16 ly = __float2bfloat16(oy - __bfloat162float(hy));
        size_t off = ((size_t)(b*Tt + qg))*Cc + hh*HD + lane*2;
        *(__nv_bfloat162*)&g_ah[off] = __nv_bfloat162{hx, hy};
        *(__nv_bfloat162*)&g_al[off] = __nv_bfloat162{lx, ly};
    }
}

// ---------------- gating ----------------
__global__ void gate_kernel(const float* __restrict__ xn, const float* __restrict__ gw) {
    int warp = (blockIdx.x*blockDim.x + threadIdx.x) >> 5;
    int lane = threadIdx.x & 31;
    if (warp >= Nn) return;
    const float* xr = xn + (size_t)warp*Cc;
    float xv[16];
    #pragma unroll
    for (int j = 0; j < 16; j++) xv[j] = xr[lane + j*32];
    float logits[Ee];
    #pragma unroll
    for (int e = 0; e < Ee; e++) {
        float s = 0.f;
        #pragma unroll
        for (int j = 0; j < 16; j++) s += xv[j]*gw[(size_t)e*Cc + lane + j*32];
        #pragma unroll
        for (int o = 16; o > 0; o >>= 1) s += __shfl_down_sync(0xffffffffu, s, o);
        logits[e] = __shfl_sync(0xffffffffu, s, 0);
    }
    if (lane == 0) {
        int b0 = 0;
        #pragma unroll
        for (int e = 1; e < Ee; e++) if (logits[e] > logits[b0]) b0 = e;
        int b1 = -1;
        #pragma unroll
        for (int e = 0; e < Ee; e++) {
            if (e == b0) continue;
            if (b1 < 0 || logits[e] > logits[b1]) b1 = e;
        }
        float mm = logits[b0];
        float e0 = expf(logits[b0] - mm), e1 = expf(logits[b1] - mm);
        float s = e0 + e1;
        g_sel[warp*2]   = b0;   g_sel[warp*2+1] = b1;
        g_gw[warp*2]    = e0/s; g_gw[warp*2+1]  = e1/s;
        int s0 = atomicAdd(&g_cnt[b0], 1);
        g_tokslot[warp*2] = s0;
        g_glist[b0*ECAP + s0] = warp;
        int s1 = atomicAdd(&g_cnt[b1], 1);
        g_tokslot[warp*2+1] = s1;
        g_glist[b1*ECAP + s1] = warp;
    }
}

// ---------------- gather ----------------
__global__ void gather_kernel() {
    int m = blockIdx.x, e = blockIdx.y;
    int cnt = g_cnt[e];
    int base = m * 128;
    if (base >= cnt) return;
    int tid = threadIdx.x;
    for (int i = tid; i < 128*64; i += 256) {
        int row = i >> 6, q = i & 63;
        int slot = base + row;
        if (slot >= cnt) continue;
        int tokn = g_glist[e*ECAP + slot];
        size_t dsti = ((size_t)e*ECAP + slot)*64 + q;
        size_t srci = (size_t)tokn*64 + q;
        ((uint4*)g_gah)[dsti] = ((const uint4*)g_ah)[srci];
        ((uint4*)g_gal)[dsti] = ((const uint4*)g_al)[srci];
    }
}

// ---------------- host launcher ----------------
extern "C" void kernel_launch(void* const* d_in, const int* in_sizes, int n_in,
                              void* d_out, int out_size) {
    (void)in_sizes; (void)n_in; (void)out_size;
    const int*   ids        = (const int*)  d_in[0];
    const float* tok        = (const float*)d_in[1];
    const float* pos        = (const float*)d_in[2];
    const float* attn_norm  = (const float*)d_in[3];
    const float* q_w        = (const float*)d_in[4];
    const float* k_w        = (const float*)d_in[5];
    const float* v_w        = (const float*)d_in[6];
    const float* o_w        = (const float*)d_in[7];
    const float* ffn_norm   = (const float*)d_in[8];
    const float* gate_w     = (const float*)d_in[9];
    const float* expert_w   = (const float*)d_in[10];
    const float* final_norm = (const float*)d_in[11];
    const float* out_w      = (const float*)d_in[12];
    float* out = (float*)d_out;

    float *h, *xn, *qkv, *gmo;
    __nv_bfloat16 *ah, *al, *gah, *gal;
    __nv_bfloat16 *wqkvh, *wqkvl, *woh, *wol, *wexh, *wexl, *wouth, *woutl;
    int *cnt;
    cudaGetSymbolAddress((void**)&h,     g_h);
    cudaGetSymbolAddress((void**)&xn,    g_xn);
    cudaGetSymbolAddress((void**)&qkv,   g_qkv);
    cudaGetSymbolAddress((void**)&gmo,   g_gmo);
    cudaGetSymbolAddress((void**)&ah,    g_ah);
    cudaGetSymbolAddress((void**)&al,    g_al);
    cudaGetSymbolAddress((void**)&gah,   g_gah);
    cudaGetSymbolAddress((void**)&gal,   g_gal);
    cudaGetSymbolAddress((void**)&cnt,   g_cnt);
    cudaGetSymbolAddress((void**)&wqkvh, g_wqkvh);
    cudaGetSymbolAddress((void**)&wqkvl, g_wqkvl);
    cudaGetSymbolAddress((void**)&woh,   g_woh);
    cudaGetSymbolAddress((void**)&wol,   g_wol);
    cudaGetSymbolAddress((void**)&wexh,  g_wexh);
    cudaGetSymbolAddress((void**)&wexl,  g_wexl);
    cudaGetSymbolAddress((void**)&wouth, g_wouth);
    cudaGetSymbolAddress((void**)&woutl, g_woutl);

    cudaFuncSetAttribute(gemm_bf16_nt,   cudaFuncAttributeMaxDynamicSharedMemorySize, GEMM_SMEM);
    cudaFuncSetAttribute(gemm64_bf16_nt, cudaFuncAttributeMaxDynamicSharedMemorySize, GEMM64_SMEM);
    cudaFuncSetAttribute(attn_kernel,    cudaFuncAttributeMaxDynamicSharedMemorySize, ATT_SMEM);

    // side stream for weight splits, overlapped with the layer pipeline
    cudaStream_t sW;
    cudaStreamCreateWithFlags(&sW, cudaStreamNonBlocking);
    cudaEvent_t evFork, evQkvw, evOwExw, evOutw;
    cudaEventCreateWithFlags(&evFork,  cudaEventDisableTiming);
    cudaEventCreateWithFlags(&evQkvw,  cudaEventDisableTiming);
    cudaEventCreateWithFlags(&evOwExw, cudaEventDisableTiming);
    cudaEventCreateWithFlags(&evOutw,  cudaEventDisableTiming);

    cudaEventRecord(evFork, 0);
    cudaStreamWaitEvent(sW, evFork, 0);
    split_qkvw_kernel<<<(Ll*QKVN*Cc/4 + 255)/256, 256, 0, sW>>>(q_w, k_w, v_w);
    cudaEventRecord(evQkvw, sW);
    {
        int tot = Ll*Cc*Cc/4 + Ll*Ee*Cc*Cc/4;
        split_ow_exw_kernel<<<(tot + 255)/256, 256, 0, sW>>>(o_w, expert_w);
    }
    cudaEventRecord(evOwExw, sW);
    split_outw_kernel<<<(Vv*Cc/4 + 255)/256, 256, 0, sW>>>(out_w);
    cudaEventRecord(evOutw, sW);

    // main stream: fused embed + first rmsnorm
    embed_rmsnorm_split_kernel<<<Nn, 256>>>(ids, tok, pos, attn_norm, h, xn, ah, al);

    bool waitedOw = false;
    for (int l = 0; l < Ll; l++) {
        if (l > 0) {
            rmsnorm_split_kernel<<<Nn, 256>>>(h, attn_norm + (size_t)l*Cc, xn, ah, al, 1);
        }
        if (l == 0) cudaStreamWaitEvent(0, evQkvw, 0);
        {
            dim3 g(Nn/128, QKVN/64);
            gemm64_bf16_nt<<<g, 256, GEMM64_SMEM>>>(ah, al,
                wqkvh + (size_t)l*QKVN*Cc, wqkvl + (size_t)l*QKVN*Cc,
                qkv, Nn, QKVN, Cc, 0, 0, 0, nullptr, 0);
        }
        {
            dim3 ga(Tt/QB, Hh, Bb);
            attn_kernel<<<ga, 256, ATT_SMEM>>>();
        }
        if (!waitedOw) { cudaStreamWaitEvent(0, evOwExw, 0); waitedOw = true; }
        {
            dim3 g(Nn/128, Cc/64);
            gemm64_bf16_nt<<<g, 256, GEMM64_SMEM>>>(ah, al,
                woh + (size_t)l*Cc*Cc, wol + (size_t)l*Cc*Cc,
                h, Nn, Cc, Cc, 0, 0, 0, nullptr, 1);
        }
        rmsnorm_split_kernel<<<Nn, 256>>>(h, ffn_norm + (size_t)l*Cc, xn, ah, al, 0);
        gate_kernel<<<Nn/8, 256>>>(xn, gate_w + (size_t)l*Ee*Cc);
        {
            dim3 gg(ECAP/128, Ee);
            gather_kernel<<<gg, 256>>>();
        }
        {
            dim3 g(ECAP/128, Cc/64, Ee);
            gemm64_bf16_nt<<<g, 256, GEMM64_SMEM>>>(gah, gal,
                wexh + (size_t)l*Ee*Cc*Cc, wexl + (size_t)l*Ee*Cc*Cc,
                gmo, ECAP, Cc, Cc,
                (size_t)ECAP*Cc, (size_t)Cc*Cc, (size_t)ECAP*Cc, cnt, 0);
        }
    }

    rmsnorm_split_kernel<<<Nn, 256>>>(h, final_norm, xn, ah, al, 1);
    cudaStreamWaitEvent(0, evOutw, 0);
    {
        dim3 g(Nn/128, Vv/128);
        gemm_bf16_nt<<<g, 256, GEMM_SMEM>>>(ah, al, wouth, woutl, out, Nn, Vv, Cc);
    }
    // NOTE: stream/events intentionally not destroyed here — destroying a
    // stream that participated in an ongoing capture would abort the capture.
    // kernel_launch is invoked only a handful of times; the handles are tiny.
}

// round 15
// speedup vs baseline: 1.1242x; 1.0622x over previous
#include <cuda_runtime.h>
#include <cuda_bf16.h>
#include <math.h>
#include <stdint.h>

#define Bb 2
#define Tt 1024
#define Cc 512
#define Hh 8
#define KVh 2
#define HD 64
#define Ll 2
#define Ee 8
#define TOPK 2
#define Vv 32000
#define Nn (Bb*Tt)        // 2048 tokens
#define KVD (KVh*HD)      // 128
#define QKVN (Cc + 2*KVD) // 768
#define ECAP 2048         // per-expert slot capacity
#define QB 8              // queries per attention block
#define EPSf 1e-6f

// ---------------- scratch (device globals; no allocation allowed) ----------------
__device__ float g_h[Nn*Cc];
__device__ float g_qkv[Nn*QKVN];
__device__ int   g_sel[Nn*TOPK];
__device__ float g_gw[Nn*TOPK];
__device__ int   g_cnt[Ee];
__device__ int   g_glist[Ee*ECAP];
__device__ int   g_tokslot[Nn*TOPK];
__device__ __nv_bfloat16 g_ah[Nn*Cc];
__device__ __nv_bfloat16 g_al[Nn*Cc];
__device__ float g_gmo[Ee*ECAP*Cc];
// pre-split weights (all layers)
__device__ __nv_bfloat16 g_wqkvh[Ll*QKVN*Cc];
__device__ __nv_bfloat16 g_wqkvl[Ll*QKVN*Cc];
__device__ __nv_bfloat16 g_woh[Ll*Cc*Cc];
__device__ __nv_bfloat16 g_wol[Ll*Cc*Cc];
__device__ __nv_bfloat16 g_wexh[Ll*Ee*Cc*Cc];
__device__ __nv_bfloat16 g_wexl[Ll*Ee*Cc*Cc];
__device__ __nv_bfloat16 g_wouth[Vv*Cc];
__device__ __nv_bfloat16 g_woutl[Vv*Cc];

// ---- fused embed + rmsnorm + bf16 split (zeroes expert counters) ----
__global__ void embed_rmsnorm_split_kernel(const int* __restrict__ ids,
                                           const float* __restrict__ tok,
                                           const float* __restrict__ pos,
                                           const float* __restrict__ w,
                                           float* __restrict__ hbuf,
                                           __nv_bfloat16* __restrict__ hi,
                                           __nv_bfloat16* __restrict__ lo) {
    int n = blockIdx.x;
    int tid = threadIdx.x;
    if (n == 0 && tid < Ee) g_cnt[tid] = 0;
    int t = n % Tt;
    size_t tb = (size_t)ids[n]*Cc, pb = (size_t)t*Cc;
    float v0 = tok[tb + tid]       + pos[pb + tid];
    float v1 = tok[tb + tid + 256] + pos[pb + tid + 256];
    hbuf[(size_t)n*Cc + tid]       = v0;
    hbuf[(size_t)n*Cc + tid + 256] = v1;
    __shared__ float red[256];
    red[tid] = v0*v0 + v1*v1;
    __syncthreads();
    for (int o = 128; o > 0; o >>= 1) {
        if (tid < o) red[tid] += red[tid + o];
        __syncthreads();
    }
    float inv = rsqrtf(red[0] / (float)Cc + EPSf);
    float y0 = v0 * inv * w[tid];
    float y1 = v1 * inv * w[tid+256];
    __nv_bfloat16 h0 = __float2bfloat16(y0);
    __nv_bfloat16 h1 = __float2bfloat16(y1);
    hi[(size_t)n*Cc + tid]       = h0;
    hi[(size_t)n*Cc + tid + 256] = h1;
    lo[(size_t)n*Cc + tid]       = __float2bfloat16(y0 - __bfloat162float(h0));
    lo[(size_t)n*Cc + tid + 256] = __float2bfloat16(y1 - __bfloat162float(h1));
}

// ---- (optional moe-combine) + rmsnorm + bf16 split; zeroes counters ----
__global__ void rmsnorm_split_kernel(float* __restrict__ hbuf,
                                     const float* __restrict__ w,
                                     __nv_bfloat16* __restrict__ hi,
                                     __nv_bfloat16* __restrict__ lo,
                                     int do_moe) {
    int n = blockIdx.x;
    int tid = threadIdx.x;
    if (n == 0 && tid < Ee) g_cnt[tid] = 0;
    float* hr = hbuf + (size_t)n*Cc;
    float v0, v1;
    if (do_moe) {
        int e0 = g_sel[n*2],     e1 = g_sel[n*2+1];
        int s0 = g_tokslot[n*2], s1 = g_tokslot[n*2+1];
        float w0 = g_gw[n*2],    w1 = g_gw[n*2+1];
        const float* m0 = g_gmo + ((size_t)e0*ECAP + s0)*Cc;
        const float* m1 = g_gmo + ((size_t)e1*ECAP + s1)*Cc;
        v0 = hr[tid]     + w0*m0[tid]     + w1*m1[tid];
        v1 = hr[tid+256] + w0*m0[tid+256] + w1*m1[tid+256];
        hr[tid] = v0; hr[tid+256] = v1;
    } else {
        v0 = hr[tid]; v1 = hr[tid+256];
    }
    __shared__ float red[256];
    red[tid] = v0*v0 + v1*v1;
    __syncthreads();
    for (int o = 128; o > 0; o >>= 1) {
        if (tid < o) red[tid] += red[tid + o];
        __syncthreads();
    }
    float inv = rsqrtf(red[0] / (float)Cc + EPSf);
    float y0 = v0 * inv * w[tid];
    float y1 = v1 * inv * w[tid+256];
    __nv_bfloat16 h0 = __float2bfloat16(y0);
    __nv_bfloat16 h1 = __float2bfloat16(y1);
    hi[(size_t)n*Cc + tid]       = h0;
    hi[(size_t)n*Cc + tid + 256] = h1;
    lo[(size_t)n*Cc + tid]       = __float2bfloat16(y0 - __bfloat162float(h0));
    lo[(size_t)n*Cc + tid + 256] = __float2bfloat16(y1 - __bfloat162float(h1));
}

// ---- fused ffn rmsnorm + bf16 split + GATE (top-2, atomics). Counters must
// already be zeroed by the preceding rmsnorm/embed kernel. ----
__global__ void rmsnorm_gate_kernel(const float* __restrict__ hbuf,
                                    const float* __restrict__ w,
                                    const float* __restrict__ gw,
                                    __nv_bfloat16* __restrict__ hi,
                                    __nv_bfloat16* __restrict__ lo) {
    int n = blockIdx.x;
    int tid = threadIdx.x;
    int lane = tid & 31, wid = tid >> 5;
    const float* hr = hbuf + (size_t)n*Cc;
    float v0 = hr[tid], v1 = hr[tid+256];
    __shared__ float red[256];
    __shared__ float sy[Cc];
    __shared__ float slog[Ee];
    red[tid] = v0*v0 + v1*v1;
    __syncthreads();
    for (int o = 128; o > 0; o >>= 1) {
        if (tid < o) red[tid] += red[tid + o];
        __syncthreads();
    }
    float inv = rsqrtf(red[0] / (float)Cc + EPSf);
    float y0 = v0 * inv * w[tid];
    float y1 = v1 * inv * w[tid+256];
    sy[tid] = y0; sy[tid+256] = y1;
    __nv_bfloat16 h0 = __float2bfloat16(y0);
    __nv_bfloat16 h1 = __float2bfloat16(y1);
    hi[(size_t)n*Cc + tid]       = h0;
    hi[(size_t)n*Cc + tid + 256] = h1;
    lo[(size_t)n*Cc + tid]       = __float2bfloat16(y0 - __bfloat162float(h0));
    lo[(size_t)n*Cc + tid + 256] = __float2bfloat16(y1 - __bfloat162float(h1));
    __syncthreads();
    // warp `wid` computes expert `wid`'s logit (exact fp32)
    float s = 0.f;
    const float* gr = gw + (size_t)wid*Cc;
    #pragma unroll
    for (int j = 0; j < 16; j++) s += sy[lane + j*32] * gr[lane + j*32];
    #pragma unroll
    for (int o = 16; o > 0; o >>= 1) s += __shfl_down_sync(0xffffffffu, s, o);
    if (lane == 0) slog[wid] = s;
    __syncthreads();
    if (tid == 0) {
        float logits[Ee];
        #pragma unroll
        for (int e = 0; e < Ee; e++) logits[e] = slog[e];
        int b0 = 0;
        #pragma unroll
        for (int e = 1; e < Ee; e++) if (logits[e] > logits[b0]) b0 = e;
        int b1 = -1;
        #pragma unroll
        for (int e = 0; e < Ee; e++) {
            if (e == b0) continue;
            if (b1 < 0 || logits[e] > logits[b1]) b1 = e;
        }
        float mm = logits[b0];
        float e0 = expf(logits[b0] - mm), e1 = expf(logits[b1] - mm);
        float sw = e0 + e1;
        g_sel[n*2]   = b0;    g_sel[n*2+1] = b1;
        g_gw[n*2]    = e0/sw; g_gw[n*2+1]  = e1/sw;
        int s0 = atomicAdd(&g_cnt[b0], 1);
        g_tokslot[n*2] = s0;
        g_glist[b0*ECAP + s0] = n;
        int s1 = atomicAdd(&g_cnt[b1], 1);
        g_tokslot[n*2+1] = s1;
        g_glist[b1*ECAP + s1] = n;
    }
}

// ---------------- bf16 split helpers ----------------
__device__ __forceinline__ void split4(float4 v, __nv_bfloat162* H, __nv_bfloat162* L, size_t i4) {
    __nv_bfloat16 h0 = __float2bfloat16(v.x);
    __nv_bfloat16 h1 = __float2bfloat16(v.y);
    __nv_bfloat16 h2 = __float2bfloat16(v.z);
    __nv_bfloat16 h3 = __float2bfloat16(v.w);
    H[i4*2]   = __nv_bfloat162{h0, h1};
    H[i4*2+1] = __nv_bfloat162{h2, h3};
    L[i4*2]   = __nv_bfloat162{__float2bfloat16(v.x - __bfloat162float(h0)),
                               __float2bfloat16(v.y - __bfloat162float(h1))};
    L[i4*2+1] = __nv_bfloat162{__float2bfloat16(v.z - __bfloat162float(h2)),
                               __float2bfloat16(v.w - __bfloat162float(h3))};
}

__global__ void split_qkvw_kernel(const float* __restrict__ qw,
                                  const float* __restrict__ kw,
                                  const float* __restrict__ vw) {
    int idx4 = blockIdx.x*blockDim.x + threadIdx.x;
    const int per_l = QKVN*Cc/4;
    if (idx4 >= Ll*per_l) return;
    int l = idx4 / per_l, rem = idx4 - l*per_l;
    int row = rem >> 7, col4 = rem & 127;
    float4 v;
    if (row < 512)       v = ((const float4*)qw)[(size_t)l*(Cc*Cc/4)  + row*128 + col4];
    else if (row < 640)  v = ((const float4*)kw)[(size_t)l*(KVD*Cc/4) + (row-512)*128 + col4];
    else                 v = ((const float4*)vw)[(size_t)l*(KVD*Cc/4) + (row-640)*128 + col4];
    split4(v, (__nv_bfloat162*)g_wqkvh, (__nv_bfloat162*)g_wqkvl, idx4);
}

__global__ void split_ow_exw_kernel(const float* __restrict__ ow,
                                    const float* __restrict__ exw) {
    int idx4 = blockIdx.x*blockDim.x + threadIdx.x;
    const int n_o = Ll*Cc*Cc/4;
    const int n_e = Ll*Ee*Cc*Cc/4;
    if (idx4 < n_o) {
        split4(((const float4*)ow)[idx4], (__nv_bfloat162*)g_woh, (__nv_bfloat162*)g_wol, idx4);
    } else if (idx4 < n_o + n_e) {
        int j = idx4 - n_o;
        split4(((const float4*)exw)[j], (__nv_bfloat162*)g_wexh, (__nv_bfloat162*)g_wexl, j);
    }
}

__global__ void split_outw_kernel(const float* __restrict__ x) {
    int i = blockIdx.x*blockDim.x + threadIdx.x;
    if (i >= Vv*Cc/4) return;
    split4(((const float4*)x)[i], (__nv_bfloat162*)g_wouth, (__nv_bfloat162*)g_woutl, i);
}

// ---------------- mma helpers ----------------
__device__ __forceinline__ void ldsm_x4(uint32_t& r0, uint32_t& r1, uint32_t& r2, uint32_t& r3, uint32_t addr) {
    asm volatile("ldmatrix.sync.aligned.m8n8.x4.shared.b16 {%0,%1,%2,%3}, [%4];"
                 : "=r"(r0), "=r"(r1), "=r"(r2), "=r"(r3) : "r"(addr));
}
__device__ __forceinline__ void mma16816(float* c, uint32_t a0, uint32_t a1, uint32_t a2, uint32_t a3,
                                         uint32_t b0, uint32_t b1) {
    asm volatile("mma.sync.aligned.m16n8k16.row.col.f32.bf16.bf16.f32 "
                 "{%0,%1,%2,%3}, {%4,%5,%6,%7}, {%8,%9}, {%0,%1,%2,%3};"
                 : "+f"(c[0]), "+f"(c[1]), "+f"(c[2]), "+f"(c[3])
                 : "r"(a0), "r"(a1), "r"(a2), "r"(a3), "r"(b0), "r"(b1));
}
__device__ __forceinline__ void cp16(uint32_t smem, const void* gmem) {
    asm volatile("cp.async.cg.shared.global [%0], [%1], 16;" :: "r"(smem), "l"(gmem));
}
__device__ __forceinline__ void cp_commit() {
    asm volatile("cp.async.commit_group;" ::: "memory");
}
template<int N>
__device__ __forceinline__ void cp_wait() {
    asm volatile("cp.async.wait_group %0;" :: "n"(N) : "memory");
}

// ================= 128x128 bf16-split GEMM (vocab projection) =====
#define ARR_B (128*40*2)
#define STG_B (4*ARR_B)
#define GEMM_SMEM (2*STG_B)       // 81920 bytes

__global__ __launch_bounds__(256, 2)
void gemm_bf16_nt(const __nv_bfloat16* __restrict__ Ah, const __nv_bfloat16* __restrict__ Al,
                  const __nv_bfloat16* __restrict__ Bh, const __nv_bfloat16* __restrict__ Bl,
                  float* __restrict__ Cm, int M, int N, int K) {
    int row0 = blockIdx.x * 128, col0 = blockIdx.y * 128;

    extern __shared__ __align__(16) char smem[];
    uint32_t smem_u32 = (uint32_t)__cvta_generic_to_shared(smem);

    int tid = threadIdx.x;
    int lane = tid & 31, wid = tid >> 5;
    int warpM = wid >> 2, warpN = wid & 3;

    float acc[4][4][4];
    #pragma unroll
    for (int mi = 0; mi < 4; mi++)
        #pragma unroll
        for (int ni = 0; ni < 4; ni++)
            #pragma unroll
            for (int r = 0; r < 4; r++) acc[mi][ni][r] = 0.f;

    int r0c = tid >> 2, f0 = tid & 3;
    int r1c = (tid + 256) >> 2, f1 = tid & 3;

    int aRow = (lane & 15);
    int aColOff = (lane >> 4) * 8;
    int bRowX4 = (lane & 7) + ((lane >> 4) << 3);
    int bColOff = ((lane >> 3) & 1) * 8;

    const int nk = K >> 5;

    auto load_stage = [&](int stg, int kt) {
        int k0 = kt << 5;
        uint32_t sb = smem_u32 + stg * STG_B;
        const __nv_bfloat16* srcs[4] = { Ah, Al, Bh, Bl };
        #pragma unroll
        for (int m = 0; m < 4; m++) {
            const __nv_bfloat16* G = srcs[m];
            int rb = (m < 2) ? row0 : col0;
            uint32_t dst = sb + m * ARR_B;
            cp16(dst + r0c*80 + f0*16, G + (size_t)(rb + r0c)*K + k0 + f0*8);
            cp16(dst + r1c*80 + f1*16, G + (size_t)(rb + r1c)*K + k0 + f1*8);
        }
        cp_commit();
    };

    load_stage(0, 0);
    if (nk > 1) load_stage(1, 1);

    for (int kt = 0; kt < nk; kt++) {
        int stg = kt & 1;
        if (kt + 1 < nk) cp_wait<1>(); else cp_wait<0>();
        __syncthreads();

        uint32_t sb = smem_u32 + stg * STG_B;
        uint32_t sAh = sb, sAl = sb + ARR_B, sBh = sb + 2*ARR_B, sBl = sb + 3*ARR_B;

        #pragma unroll
        for (int ks = 0; ks < 32; ks += 16) {
            uint32_t bh[4][2], bl[4][2];
            #pragma unroll
            for (int nip = 0; nip < 2; nip++) {
                int brow = warpN*32 + nip*16 + bRowX4;
                uint32_t off = (uint32_t)(brow*80 + (ks + bColOff)*2);
                ldsm_x4(bh[2*nip][0], bh[2*nip][1], bh[2*nip+1][0], bh[2*nip+1][1], sBh + off);
                ldsm_x4(bl[2*nip][0], bl[2*nip][1], bl[2*nip+1][0], bl[2*nip+1][1], sBl + off);
            }
            #pragma unroll
            for (int mi = 0; mi < 4; mi++) {
                int arow = warpM*64 + mi*16 + aRow;
                uint32_t off = (uint32_t)(arow*80 + (ks + aColOff)*2);
                uint32_t ah0, ah1, ah2, ah3, al0, al1, al2, al3;
                ldsm_x4(ah0, ah1, ah2, ah3, sAh + off);
                ldsm_x4(al0, al1, al2, al3, sAl + off);
                #pragma unroll
                for (int ni = 0; ni < 4; ni++)
                    mma16816(acc[mi][ni], ah0, ah1, ah2, ah3, bh[ni][0], bh[ni][1]);
                #pragma unroll
                for (int ni = 0; ni < 4; ni++)
                    mma16816(acc[mi][ni], ah0, ah1, ah2, ah3, bl[ni][0], bl[ni][1]);
                #pragma unroll
                for (int ni = 0; ni < 4; ni++)
                    mma16816(acc[mi][ni], al0, al1, al2, al3, bh[ni][0], bh[ni][1]);
            }
        }
        __syncthreads();
        if (kt + 2 < nk) load_stage(stg, kt + 2);
    }

    #pragma unroll
    for (int mi = 0; mi < 4; mi++) {
        #pragma unroll
        for (int ni = 0; ni < 4; ni++) {
            int r = row0 + warpM*64 + mi*16 + (lane >> 2);
            int c = col0 + warpN*32 + ni*8 + (lane & 3)*2;
            float2 v0 = {acc[mi][ni][0], acc[mi][ni][1]};
            float2 v1 = {acc[mi][ni][2], acc[mi][ni][3]};
            *(float2*)&Cm[(size_t)r*N + c]       = v0;
            *(float2*)&Cm[(size_t)(r + 8)*N + c] = v1;
        }
    }
}

// ================= 128x64 bf16-split GEMM (dense layer GEMMs, 3 CTAs/SM) =====
// moeGather != 0: A rows are indirected through g_glist[z*ECAP + row] and the
// CTA early-outs past g_cnt[z].
#define ARR64_A (128*40*2)        // 10240
#define ARR64_B (64*40*2)         // 5120
#define STG64_B (2*ARR64_A + 2*ARR64_B)   // 30720
#define GEMM64_SMEM (2*STG64_B)   // 61440

__global__ __launch_bounds__(256, 3)
void gemm64_bf16_nt(const __nv_bfloat16* __restrict__ Ah, const __nv_bfloat16* __restrict__ Al,
                    const __nv_bfloat16* __restrict__ Bh, const __nv_bfloat16* __restrict__ Bl,
                    float* __restrict__ Cm, int M, int N, int K,
                    size_t strideB, size_t strideC,
                    int moeGather, int addC) {
    int row0 = blockIdx.x * 128, col0 = blockIdx.y * 64;
    int z = blockIdx.z;
    Bh += (size_t)z * strideB;
    Bl += (size_t)z * strideB;
    Cm += (size_t)z * strideC;

    int tid = threadIdx.x;
    int rA0 = tid >> 2, fA = tid & 3;
    int rA1 = rA0 + 64;

    // resolve A row addresses (k-invariant)
    size_t aoff0, aoff1;
    if (moeGather) {
        int cnt = g_cnt[z];
        if (row0 >= cnt) return;
        int i0 = row0 + rA0, i1 = row0 + rA1;
        int tok0 = (i0 < cnt) ? g_glist[z*ECAP + i0] : g_glist[z*ECAP];
        int tok1 = (i1 < cnt) ? g_glist[z*ECAP + i1] : tok0;
        aoff0 = (size_t)tok0 * K;
        aoff1 = (size_t)tok1 * K;
    } else {
        aoff0 = (size_t)(row0 + rA0) * K;
        aoff1 = (size_t)(row0 + rA1) * K;
    }

    extern __shared__ __align__(16) char smem[];
    uint32_t smem_u32 = (uint32_t)__cvta_generic_to_shared(smem);

    int lane = tid & 31, wid = tid >> 5;
    int warpM = wid >> 1, warpN = wid & 1;

    float acc[2][4][4];
    #pragma unroll
    for (int mi = 0; mi < 2; mi++)
        #pragma unroll
        for (int ni = 0; ni < 4; ni++)
            #pragma unroll
            for (int r = 0; r < 4; r++) acc[mi][ni][r] = 0.f;

    int rB = tid >> 2;

    int aRow = (lane & 15);
    int aColOff = (lane >> 4) * 8;
    int bRowX4 = (lane & 7) + ((lane >> 4) << 3);
    int bColOff = ((lane >> 3) & 1) * 8;

    const int nk = K >> 5;

    auto load_stage = [&](int stg, int kt) {
        int k0 = kt << 5;
        uint32_t sb = smem_u32 + stg * STG64_B;
        uint32_t dAh = sb, dAl = sb + ARR64_A;
        uint32_t dBh = sb + 2*ARR64_A, dBl = sb + 2*ARR64_A + ARR64_B;
        cp16(dAh + rA0*80 + fA*16, Ah + aoff0 + k0 + fA*8);
        cp16(dAh + rA1*80 + fA*16, Ah + aoff1 + k0 + fA*8);
        cp16(dAl + rA0*80 + fA*16, Al + aoff0 + k0 + fA*8);
        cp16(dAl + rA1*80 + fA*16, Al + aoff1 + k0 + fA*8);
        cp16(dBh + rB*80 + fA*16,  Bh + (size_t)(col0 + rB)*K + k0 + fA*8);
        cp16(dBl + rB*80 + fA*16,  Bl + (size_t)(col0 + rB)*K + k0 + fA*8);
        cp_commit();
    };

    load_stage(0, 0);
    if (nk > 1) load_stage(1, 1);

    for (int kt = 0; kt < nk; kt++) {
        int stg = kt & 1;
        if (kt + 1 < nk) cp_wait<1>(); else cp_wait<0>();
        __syncthreads();

        uint32_t sb = smem_u32 + stg * STG64_B;
        uint32_t sAh = sb, sAl = sb + ARR64_A;
        uint32_t sBh = sb + 2*ARR64_A, sBl = sb + 2*ARR64_A + ARR64_B;

        #pragma unroll
        for (int ks = 0; ks < 32; ks += 16) {
            uint32_t bh[4][2], bl[4][2];
            #pragma unroll
            for (int nip = 0; nip < 2; nip++) {
                int brow = warpN*32 + nip*16 + bRowX4;
                uint32_t off = (uint32_t)(brow*80 + (ks + bColOff)*2);
                ldsm_x4(bh[2*nip][0], bh[2*nip][1], bh[2*nip+1][0], bh[2*nip+1][1], sBh + off);
                ldsm_x4(bl[2*nip][0], bl[2*nip][1], bl[2*nip+1][0], bl[2*nip+1][1], sBl + off);
            }
            #pragma unroll
            for (int mi = 0; mi < 2; mi++) {
                int arow = warpM*32 + mi*16 + aRow;
                uint32_t off = (uint32_t)(arow*80 + (ks + aColOff)*2);
                uint32_t ah0, ah1, ah2, ah3, al0, al1, al2, al3;
                ldsm_x4(ah0, ah1, ah2, ah3, sAh + off);
                ldsm_x4(al0, al1, al2, al3, sAl + off);
                #pragma unroll
                for (int ni = 0; ni < 4; ni++)
                    mma16816(acc[mi][ni], ah0, ah1, ah2, ah3, bh[ni][0], bh[ni][1]);
                #pragma unroll
                for (int ni = 0; ni < 4; ni++)
                    mma16816(acc[mi][ni], ah0, ah1, ah2, ah3, bl[ni][0], bl[ni][1]);
                #pragma unroll
                for (int ni = 0; ni < 4; ni++)
                    mma16816(acc[mi][ni], al0, al1, al2, al3, bh[ni][0], bh[ni][1]);
            }
        }
        __syncthreads();
        if (kt + 2 < nk) load_stage(stg, kt + 2);
    }

    #pragma unroll
    for (int mi = 0; mi < 2; mi++) {
        #pragma unroll
        for (int ni = 0; ni < 4; ni++) {
            int r = row0 + warpM*32 + mi*16 + (lane >> 2);
            int c = col0 + warpN*32 + ni*8 + (lane & 3)*2;
            float2 v0 = {acc[mi][ni][0], acc[mi][ni][1]};
            float2 v1 = {acc[mi][ni][2], acc[mi][ni][3]};
            float2* p0 = (float2*)&Cm[(size_t)r*N + c];
            float2* p1 = (float2*)&Cm[(size_t)(r + 8)*N + c];
            if (addC) {
                float2 o0 = *p0, o1 = *p1;
                v0.x += o0.x; v0.y += o0.y; v1.x += o1.x; v1.y += o1.y;
            }
            *p0 = v0;
            *p1 = v1;
        }
    }
}

// ---------------- tiled causal GQA attention ----------------
#define ATT_SC_F   (QB*Tt)
#define ATT_TILE_F (128*68)
#define ATT_QS_F   (QB*68)
#define ATT_PART_F (QB*2*HD)
#define ATT_SMEM   ((ATT_SC_F + ATT_TILE_F + ATT_QS_F + ATT_PART_F) * 4)

__global__ __launch_bounds__(256)
void attn_kernel() {
    int q0 = blockIdx.x * QB, hh = blockIdx.y, b = blockIdx.z;
    int kvh = hh >> 2;
    int tid = threadIdx.x;
    int lane = tid & 31, wid = tid >> 5;

    extern __shared__ __align__(16) float smem_f[];
    float* sc   = smem_f;
    float* tile = smem_f + ATT_SC_F;
    float* qs   = smem_f + ATT_SC_F + ATT_TILE_F;
    float* part = smem_f + ATT_SC_F + ATT_TILE_F + ATT_QS_F;

    if (tid < QB*16) {
        int qi = tid >> 4, c4 = tid & 15;
        const float4* src = (const float4*)(g_qkv + ((size_t)(b*Tt + q0 + qi))*QKVN + hh*HD);
        *(float4*)&qs[qi*68 + c4*4] = src[c4];
    }

    int nTiles = (q0 + QB + 127) >> 7;

    int qgrp = (wid >> 2) * 4;
    int krow = (wid & 3) * 32 + lane;

    for (int kb = 0; kb < nTiles; kb++) {
        __syncthreads();
        #pragma unroll
        for (int i = 0; i < 8; i++) {
            int f4 = tid + i*256;
            int row = f4 >> 4, c4 = f4 & 15;
            const float4* src = (const float4*)(g_qkv + ((size_t)(b*Tt + kb*128 + row))*QKVN + Cc + kvh*HD);
            *(float4*)&tile[row*68 + c4*4] = src[c4];
        }
        __syncthreads();
        int kg = kb*128 + krow;
        if (kg <= q0 + qgrp + 3) {
            float a0 = 0.f, a1 = 0.f, a2 = 0.f, a3 = 0.f;
            const float4* k4 = (const float4*)&tile[krow*68];
            const float4* q40 = (const float4*)&qs[(qgrp+0)*68];
            const float4* q41 = (const float4*)&qs[(qgrp+1)*68];
            const float4* q42 = (const float4*)&qs[(qgrp+2)*68];
            const float4* q43 = (const float4*)&qs[(qgrp+3)*68];
            #pragma unroll
            for (int j = 0; j < 16; j++) {
                float4 kv = k4[j];
                float4 qv;
                qv = q40[j]; a0 += qv.x*kv.x + qv.y*kv.y + qv.z*kv.z + qv.w*kv.w;
                qv = q41[j]; a1 += qv.x*kv.x + qv.y*kv.y + qv.z*kv.z + qv.w*kv.w;
                qv = q42[j]; a2 += qv.x*kv.x + qv.y*kv.y + qv.z*kv.z + qv.w*kv.w;
                qv = q43[j]; a3 += qv.x*kv.x + qv.y*kv.y + qv.z*kv.z + qv.w*kv.w;
            }
            if (kg <= q0 + qgrp + 0) sc[(qgrp+0)*Tt + kg] = a0 * 0.125f;
            if (kg <= q0 + qgrp + 1) sc[(qgrp+1)*Tt + kg] = a1 * 0.125f;
            if (kg <= q0 + qgrp + 2) sc[(qgrp+2)*Tt + kg] = a2 * 0.125f;
            if (kg <= q0 + qgrp + 3) sc[(qgrp+3)*Tt + kg] = a3 * 0.125f;
        }
    }
    __syncthreads();

    int qg = q0 + wid;
    int nk = qg + 1;
    int tileEnd = nTiles * 128;
    float m = -1e30f;
    for (int k = lane; k < nk; k += 32) m = fmaxf(m, sc[wid*Tt + k]);
    #pragma unroll
    for (int o = 16; o > 0; o >>= 1) m = fmaxf(m, __shfl_xor_sync(0xffffffffu, m, o));
    float s = 0.f;
    for (int k = lane; k < nk; k += 32) {
        float e = expf(sc[wid*Tt + k] - m);
        sc[wid*Tt + k] = e;
        s += e;
    }
    for (int k = nk + lane; k < tileEnd; k += 32) sc[wid*Tt + k] = 0.f;
    #pragma unroll
    for (int o = 16; o > 0; o >>= 1) s += __shfl_xor_sync(0xffffffffu, s, o);
    float inv = 1.f / s;

    int qp  = wid & 3;
    int par = wid >> 2;
    float2 acc0 = {0.f, 0.f}, acc1 = {0.f, 0.f};
    for (int kb = 0; kb < nTiles; kb++) {
        __syncthreads();
        #pragma unroll
        for (int i = 0; i < 8; i++) {
            int f4 = tid + i*256;
            int row = f4 >> 4, c4 = f4 & 15;
            const float4* src = (const float4*)(g_qkv + ((size_t)(b*Tt + kb*128 + row))*QKVN + Cc + KVD + kvh*HD);
            *(float4*)&tile[row*68 + c4*4] = src[c4];
        }
        __syncthreads();
        const float* sc0 = &sc[qp*Tt + kb*128];
        const float* sc1 = &sc[(qp+4)*Tt + kb*128];
        #pragma unroll 4
        for (int kk = par; kk < 128; kk += 2) {
            float2 v = *(const float2*)&tile[kk*68 + lane*2];
            float a0 = sc0[kk], a1 = sc1[kk];
            acc0.x += a0*v.x; acc0.y += a0*v.y;
            acc1.x += a1*v.x; acc1.y += a1*v.y;
        }
    }
    {
        int slot0 = qp*2 + 0;
        int slot1 = qp*2 + 1;
        part[slot0*2*HD + par*HD + lane*2]     = acc0.x;
        part[slot0*2*HD + par*HD + lane*2 + 1] = acc0.y;
        part[slot1*2*HD + par*HD + lane*2]     = acc1.x;
        part[slot1*2*HD + par*HD + lane*2 + 1] = acc1.y;
    }
    __syncthreads();
    {
        int qq = wid;
        int slot = (qq < 4) ? (qq*2+0) : ((qq-4)*2+1);
        float ox = part[slot*2*HD + 0*HD + lane*2]     + part[slot*2*HD + 1*HD + lane*2];
        float oy = part[slot*2*HD + 0*HD + lane*2 + 1] + part[slot*2*HD + 1*HD + lane*2 + 1];
        ox *= inv; oy *= inv;
        __nv_bfloat16 hx = __float2bfloat16(ox), hy = __float2bfloat16(oy);
        __nv_bfloat16 lx = __float2bfloat16(ox - __bfloat162float(hx));
        __nv_bfloat16 ly = __float2bfloat16(oy - __bfloat162float(hy));
        size_t off = ((size_t)(b*Tt + qg))*Cc + hh*HD + lane*2;
        *(__nv_bfloat162*)&g_ah[off] = __nv_bfloat162{hx, hy};
        *(__nv_bfloat162*)&g_al[off] = __nv_bfloat162{lx, ly};
    }
}

// ---------------- host launcher ----------------
extern "C" void kernel_launch(void* const* d_in, const int* in_sizes, int n_in,
                              void* d_out, int out_size) {
    (void)in_sizes; (void)n_in; (void)out_size;
    const int*   ids        = (const int*)  d_in[0];
    const float* tok        = (const float*)d_in[1];
    const float* pos        = (const float*)d_in[2];
    const float* attn_norm  = (const float*)d_in[3];
    const float* q_w        = (const float*)d_in[4];
    const float* k_w        = (const float*)d_in[5];
    const float* v_w        = (const float*)d_in[6];
    const float* o_w        = (const float*)d_in[7];
    const float* ffn_norm   = (const float*)d_in[8];
    const float* gate_w     = (const float*)d_in[9];
    const float* expert_w   = (const float*)d_in[10];
    const float* final_norm = (const float*)d_in[11];
    const float* out_w      = (const float*)d_in[12];
    float* out = (float*)d_out;

    float *h, *qkv, *gmo;
    __nv_bfloat16 *ah, *al;
    __nv_bfloat16 *wqkvh, *wqkvl, *woh, *wol, *wexh, *wexl, *wouth, *woutl;
    cudaGetSymbolAddress((void**)&h,     g_h);
    cudaGetSymbolAddress((void**)&qkv,   g_qkv);
    cudaGetSymbolAddress((void**)&gmo,   g_gmo);
    cudaGetSymbolAddress((void**)&ah,    g_ah);
    cudaGetSymbolAddress((void**)&al,    g_al);
    cudaGetSymbolAddress((void**)&wqkvh, g_wqkvh);
    cudaGetSymbolAddress((void**)&wqkvl, g_wqkvl);
    cudaGetSymbolAddress((void**)&woh,   g_woh);
    cudaGetSymbolAddress((void**)&wol,   g_wol);
    cudaGetSymbolAddress((void**)&wexh,  g_wexh);
    cudaGetSymbolAddress((void**)&wexl,  g_wexl);
    cudaGetSymbolAddress((void**)&wouth, g_wouth);
    cudaGetSymbolAddress((void**)&woutl, g_woutl);

    cudaFuncSetAttribute(gemm_bf16_nt,   cudaFuncAttributeMaxDynamicSharedMemorySize, GEMM_SMEM);
    cudaFuncSetAttribute(gemm64_bf16_nt, cudaFuncAttributeMaxDynamicSharedMemorySize, GEMM64_SMEM);
    cudaFuncSetAttribute(attn_kernel,    cudaFuncAttributeMaxDynamicSharedMemorySize, ATT_SMEM);

    // side stream for weight splits (kept; mildly positive last round)
    cudaStream_t sW;
    cudaStreamCreateWithFlags(&sW, cudaStreamNonBlocking);
    cudaEvent_t evFork, evQkvw, evOwExw, evOutw;
    cudaEventCreateWithFlags(&evFork,  cudaEventDisableTiming);
    cudaEventCreateWithFlags(&evQkvw,  cudaEventDisableTiming);
    cudaEventCreateWithFlags(&evOwExw, cudaEventDisableTiming);
    cudaEventCreateWithFlags(&evOutw,  cudaEventDisableTiming);

    cudaEventRecord(evFork, 0);
    cudaStreamWaitEvent(sW, evFork, 0);
    split_qkvw_kernel<<<(Ll*QKVN*Cc/4 + 255)/256, 256, 0, sW>>>(q_w, k_w, v_w);
    cudaEventRecord(evQkvw, sW);
    {
        int tot = Ll*Cc*Cc/4 + Ll*Ee*Cc*Cc/4;
        split_ow_exw_kernel<<<(tot + 255)/256, 256, 0, sW>>>(o_w, expert_w);
    }
    cudaEventRecord(evOwExw, sW);
    split_outw_kernel<<<(Vv*Cc/4 + 255)/256, 256, 0, sW>>>(out_w);
    cudaEventRecord(evOutw, sW);

    embed_rmsnorm_split_kernel<<<Nn, 256>>>(ids, tok, pos, attn_norm, h, ah, al);

    bool waitedOw = false;
    for (int l = 0; l < Ll; l++) {
        if (l > 0) {
            rmsnorm_split_kernel<<<Nn, 256>>>(h, attn_norm + (size_t)l*Cc, ah, al, 1);
        }
        if (l == 0) cudaStreamWaitEvent(0, evQkvw, 0);
        {
            dim3 g(Nn/128, QKVN/64);
            gemm64_bf16_nt<<<g, 256, GEMM64_SMEM>>>(ah, al,
                wqkvh + (size_t)l*QKVN*Cc, wqkvl + (size_t)l*QKVN*Cc,
                qkv, Nn, QKVN, Cc, 0, 0, 0, 0);
        }
        {
            dim3 ga(Tt/QB, Hh, Bb);
            attn_kernel<<<ga, 256, ATT_SMEM>>>();
        }
        if (!waitedOw) { cudaStreamWaitEvent(0, evOwExw, 0); waitedOw = true; }
        {
            dim3 g(Nn/128, Cc/64);
            gemm64_bf16_nt<<<g, 256, GEMM64_SMEM>>>(ah, al,
                woh + (size_t)l*Cc*Cc, wol + (size_t)l*Cc*Cc,
                h, Nn, Cc, Cc, 0, 0, 0, 1);
        }
        // fused ffn rmsnorm + gate (counters were zeroed by preceding rmsnorm)
        rmsnorm_gate_kernel<<<Nn, 256>>>(h, ffn_norm + (size_t)l*Cc,
                                         gate_w + (size_t)l*Ee*Cc, ah, al);
        {
            // expert GEMM with fused gather (A rows indirected via g_glist)
            dim3 g(ECAP/128, Cc/64, Ee);
            gemm64_bf16_nt<<<g, 256, GEMM64_SMEM>>>(ah, al,
                wexh + (size_t)l*Ee*Cc*Cc, wexl + (size_t)l*Ee*Cc*Cc,
                gmo, ECAP, Cc, Cc,
                (size_t)Cc*Cc, (size_t)ECAP*Cc, 1, 0);
        }
    }

    rmsnorm_split_kernel<<<Nn, 256>>>(h, final_norm, ah, al, 1);
    cudaStreamWaitEvent(0, evOutw, 0);
    {
        dim3 g(Nn/128, Vv/128);
        gemm_bf16_nt<<<g, 256, GEMM_SMEM>>>(ah, al, wouth, woutl, out, Nn, Vv, Cc);
    }
    // stream/events intentionally not destroyed (graph capture safety).
}

// round 16
// speedup vs baseline: 1.1705x; 1.0412x over previous
#include <cuda_runtime.h>
#include <cuda_bf16.h>
#include <math.h>
#include <stdint.h>

#define Bb 2
#define Tt 1024
#define Cc 512
#define Hh 8
#define KVh 2
#define HD 64
#define Ll 2
#define Ee 8
#define TOPK 2
#define Vv 32000
#define Nn (Bb*Tt)        // 2048 tokens
#define KVD (KVh*HD)      // 128
#define QKVN (Cc + 2*KVD) // 768
#define ECAP 2048         // per-expert slot capacity
#define QB 16             // queries per attention block
#define EPSf 1e-6f

// ---------------- scratch (device globals; no allocation allowed) ----------------
__device__ float g_h[Nn*Cc];
__device__ float g_qkv[Nn*QKVN];
__device__ int   g_sel[Nn*TOPK];
__device__ float g_gw[Nn*TOPK];
__device__ int   g_cnt[Ee];
__device__ int   g_glist[Ee*ECAP];
__device__ int   g_tokslot[Nn*TOPK];
__device__ __nv_bfloat16 g_ah[Nn*Cc];
__device__ __nv_bfloat16 g_al[Nn*Cc];
__device__ float g_gmo[Ee*ECAP*Cc];
// pre-split weights (all layers)
__device__ __nv_bfloat16 g_wqkvh[Ll*QKVN*Cc];
__device__ __nv_bfloat16 g_wqkvl[Ll*QKVN*Cc];
__device__ __nv_bfloat16 g_woh[Ll*Cc*Cc];
__device__ __nv_bfloat16 g_wol[Ll*Cc*Cc];
__device__ __nv_bfloat16 g_wexh[Ll*Ee*Cc*Cc];
__device__ __nv_bfloat16 g_wexl[Ll*Ee*Cc*Cc];
__device__ __nv_bfloat16 g_wouth[Vv*Cc];
__device__ __nv_bfloat16 g_woutl[Vv*Cc];

// ---- fused embed + rmsnorm + bf16 split (zeroes expert counters) ----
__global__ void embed_rmsnorm_split_kernel(const int* __restrict__ ids,
                                           const float* __restrict__ tok,
                                           const float* __restrict__ pos,
                                           const float* __restrict__ w,
                                           float* __restrict__ hbuf,
                                           __nv_bfloat16* __restrict__ hi,
                                           __nv_bfloat16* __restrict__ lo) {
    int n = blockIdx.x;
    int tid = threadIdx.x;
    if (n == 0 && tid < Ee) g_cnt[tid] = 0;
    int t = n % Tt;
    size_t tb = (size_t)ids[n]*Cc, pb = (size_t)t*Cc;
    float v0 = tok[tb + tid]       + pos[pb + tid];
    float v1 = tok[tb + tid + 256] + pos[pb + tid + 256];
    hbuf[(size_t)n*Cc + tid]       = v0;
    hbuf[(size_t)n*Cc + tid + 256] = v1;
    __shared__ float red[256];
    red[tid] = v0*v0 + v1*v1;
    __syncthreads();
    for (int o = 128; o > 0; o >>= 1) {
        if (tid < o) red[tid] += red[tid + o];
        __syncthreads();
    }
    float inv = rsqrtf(red[0] / (float)Cc + EPSf);
    float y0 = v0 * inv * w[tid];
    float y1 = v1 * inv * w[tid+256];
    __nv_bfloat16 h0 = __float2bfloat16(y0);
    __nv_bfloat16 h1 = __float2bfloat16(y1);
    hi[(size_t)n*Cc + tid]       = h0;
    hi[(size_t)n*Cc + tid + 256] = h1;
    lo[(size_t)n*Cc + tid]       = __float2bfloat16(y0 - __bfloat162float(h0));
    lo[(size_t)n*Cc + tid + 256] = __float2bfloat16(y1 - __bfloat162float(h1));
}

// ---- (optional moe-combine) + rmsnorm + bf16 split; zeroes counters ----
__global__ void rmsnorm_split_kernel(float* __restrict__ hbuf,
                                     const float* __restrict__ w,
                                     __nv_bfloat16* __restrict__ hi,
                                     __nv_bfloat16* __restrict__ lo,
                                     int do_moe) {
    int n = blockIdx.x;
    int tid = threadIdx.x;
    if (n == 0 && tid < Ee) g_cnt[tid] = 0;
    float* hr = hbuf + (size_t)n*Cc;
    float v0, v1;
    if (do_moe) {
        int e0 = g_sel[n*2],     e1 = g_sel[n*2+1];
        int s0 = g_tokslot[n*2], s1 = g_tokslot[n*2+1];
        float w0 = g_gw[n*2],    w1 = g_gw[n*2+1];
        const float* m0 = g_gmo + ((size_t)e0*ECAP + s0)*Cc;
        const float* m1 = g_gmo + ((size_t)e1*ECAP + s1)*Cc;
        v0 = hr[tid]     + w0*m0[tid]     + w1*m1[tid];
        v1 = hr[tid+256] + w0*m0[tid+256] + w1*m1[tid+256];
        hr[tid] = v0; hr[tid+256] = v1;
    } else {
        v0 = hr[tid]; v1 = hr[tid+256];
    }
    __shared__ float red[256];
    red[tid] = v0*v0 + v1*v1;
    __syncthreads();
    for (int o = 128; o > 0; o >>= 1) {
        if (tid < o) red[tid] += red[tid + o];
        __syncthreads();
    }
    float inv = rsqrtf(red[0] / (float)Cc + EPSf);
    float y0 = v0 * inv * w[tid];
    float y1 = v1 * inv * w[tid+256];
    __nv_bfloat16 h0 = __float2bfloat16(y0);
    __nv_bfloat16 h1 = __float2bfloat16(y1);
    hi[(size_t)n*Cc + tid]       = h0;
    hi[(size_t)n*Cc + tid + 256] = h1;
    lo[(size_t)n*Cc + tid]       = __float2bfloat16(y0 - __bfloat162float(h0));
    lo[(size_t)n*Cc + tid + 256] = __float2bfloat16(y1 - __bfloat162float(h1));
}

// ---- fused ffn rmsnorm + bf16 split + GATE (top-2, atomics) ----
__global__ void rmsnorm_gate_kernel(const float* __restrict__ hbuf,
                                    const float* __restrict__ w,
                                    const float* __restrict__ gw,
                                    __nv_bfloat16* __restrict__ hi,
                                    __nv_bfloat16* __restrict__ lo) {
    int n = blockIdx.x;
    int tid = threadIdx.x;
    int lane = tid & 31, wid = tid >> 5;
    const float* hr = hbuf + (size_t)n*Cc;
    float v0 = hr[tid], v1 = hr[tid+256];
    __shared__ float red[256];
    __shared__ float sy[Cc];
    __shared__ float slog[Ee];
    red[tid] = v0*v0 + v1*v1;
    __syncthreads();
    for (int o = 128; o > 0; o >>= 1) {
        if (tid < o) red[tid] += red[tid + o];
        __syncthreads();
    }
    float inv = rsqrtf(red[0] / (float)Cc + EPSf);
    float y0 = v0 * inv * w[tid];
    float y1 = v1 * inv * w[tid+256];
    sy[tid] = y0; sy[tid+256] = y1;
    __nv_bfloat16 h0 = __float2bfloat16(y0);
    __nv_bfloat16 h1 = __float2bfloat16(y1);
    hi[(size_t)n*Cc + tid]       = h0;
    hi[(size_t)n*Cc + tid + 256] = h1;
    lo[(size_t)n*Cc + tid]       = __float2bfloat16(y0 - __bfloat162float(h0));
    lo[(size_t)n*Cc + tid + 256] = __float2bfloat16(y1 - __bfloat162float(h1));
    __syncthreads();
    float s = 0.f;
    const float* gr = gw + (size_t)wid*Cc;
    #pragma unroll
    for (int j = 0; j < 16; j++) s += sy[lane + j*32] * gr[lane + j*32];
    #pragma unroll
    for (int o = 16; o > 0; o >>= 1) s += __shfl_down_sync(0xffffffffu, s, o);
    if (lane == 0) slog[wid] = s;
    __syncthreads();
    if (tid == 0) {
        float logits[Ee];
        #pragma unroll
        for (int e = 0; e < Ee; e++) logits[e] = slog[e];
        int b0 = 0;
        #pragma unroll
        for (int e = 1; e < Ee; e++) if (logits[e] > logits[b0]) b0 = e;
        int b1 = -1;
        #pragma unroll
        for (int e = 0; e < Ee; e++) {
            if (e == b0) continue;
            if (b1 < 0 || logits[e] > logits[b1]) b1 = e;
        }
        float mm = logits[b0];
        float e0 = expf(logits[b0] - mm), e1 = expf(logits[b1] - mm);
        float sw = e0 + e1;
        g_sel[n*2]   = b0;    g_sel[n*2+1] = b1;
        g_gw[n*2]    = e0/sw; g_gw[n*2+1]  = e1/sw;
        int s0 = atomicAdd(&g_cnt[b0], 1);
        g_tokslot[n*2] = s0;
        g_glist[b0*ECAP + s0] = n;
        int s1 = atomicAdd(&g_cnt[b1], 1);
        g_tokslot[n*2+1] = s1;
        g_glist[b1*ECAP + s1] = n;
    }
}

// ---------------- bf16 split helpers ----------------
__device__ __forceinline__ void split4(float4 v, __nv_bfloat162* H, __nv_bfloat162* L, size_t i4) {
    __nv_bfloat16 h0 = __float2bfloat16(v.x);
    __nv_bfloat16 h1 = __float2bfloat16(v.y);
    __nv_bfloat16 h2 = __float2bfloat16(v.z);
    __nv_bfloat16 h3 = __float2bfloat16(v.w);
    H[i4*2]   = __nv_bfloat162{h0, h1};
    H[i4*2+1] = __nv_bfloat162{h2, h3};
    L[i4*2]   = __nv_bfloat162{__float2bfloat16(v.x - __bfloat162float(h0)),
                               __float2bfloat16(v.y - __bfloat162float(h1))};
    L[i4*2+1] = __nv_bfloat162{__float2bfloat16(v.z - __bfloat162float(h2)),
                               __float2bfloat16(v.w - __bfloat162float(h3))};
}

__global__ void split_qkvw_kernel(const float* __restrict__ qw,
                                  const float* __restrict__ kw,
                                  const float* __restrict__ vw) {
    int idx4 = blockIdx.x*blockDim.x + threadIdx.x;
    const int per_l = QKVN*Cc/4;
    if (idx4 >= Ll*per_l) return;
    int l = idx4 / per_l, rem = idx4 - l*per_l;
    int row = rem >> 7, col4 = rem & 127;
    float4 v;
    if (row < 512)       v = ((const float4*)qw)[(size_t)l*(Cc*Cc/4)  + row*128 + col4];
    else if (row < 640)  v = ((const float4*)kw)[(size_t)l*(KVD*Cc/4) + (row-512)*128 + col4];
    else                 v = ((const float4*)vw)[(size_t)l*(KVD*Cc/4) + (row-640)*128 + col4];
    split4(v, (__nv_bfloat162*)g_wqkvh, (__nv_bfloat162*)g_wqkvl, idx4);
}

__global__ void split_ow_exw_kernel(const float* __restrict__ ow,
                                    const float* __restrict__ exw) {
    int idx4 = blockIdx.x*blockDim.x + threadIdx.x;
    const int n_o = Ll*Cc*Cc/4;
    const int n_e = Ll*Ee*Cc*Cc/4;
    if (idx4 < n_o) {
        split4(((const float4*)ow)[idx4], (__nv_bfloat162*)g_woh, (__nv_bfloat162*)g_wol, idx4);
    } else if (idx4 < n_o + n_e) {
        int j = idx4 - n_o;
        split4(((const float4*)exw)[j], (__nv_bfloat162*)g_wexh, (__nv_bfloat162*)g_wexl, j);
    }
}

__global__ void split_outw_kernel(const float* __restrict__ x) {
    int i = blockIdx.x*blockDim.x + threadIdx.x;
    if (i >= Vv*Cc/4) return;
    split4(((const float4*)x)[i], (__nv_bfloat162*)g_wouth, (__nv_bfloat162*)g_woutl, i);
}

// ---------------- mma helpers ----------------
__device__ __forceinline__ void ldsm_x4(uint32_t& r0, uint32_t& r1, uint32_t& r2, uint32_t& r3, uint32_t addr) {
    asm volatile("ldmatrix.sync.aligned.m8n8.x4.shared.b16 {%0,%1,%2,%3}, [%4];"
                 : "=r"(r0), "=r"(r1), "=r"(r2), "=r"(r3) : "r"(addr));
}
__device__ __forceinline__ void mma16816(float* c, uint32_t a0, uint32_t a1, uint32_t a2, uint32_t a3,
                                         uint32_t b0, uint32_t b1) {
    asm volatile("mma.sync.aligned.m16n8k16.row.col.f32.bf16.bf16.f32 "
                 "{%0,%1,%2,%3}, {%4,%5,%6,%7}, {%8,%9}, {%0,%1,%2,%3};"
                 : "+f"(c[0]), "+f"(c[1]), "+f"(c[2]), "+f"(c[3])
                 : "r"(a0), "r"(a1), "r"(a2), "r"(a3), "r"(b0), "r"(b1));
}
__device__ __forceinline__ void cp16(uint32_t smem, const void* gmem) {
    asm volatile("cp.async.cg.shared.global [%0], [%1], 16;" :: "r"(smem), "l"(gmem));
}
__device__ __forceinline__ void cp_commit() {
    asm volatile("cp.async.commit_group;" ::: "memory");
}
template<int N>
__device__ __forceinline__ void cp_wait() {
    asm volatile("cp.async.wait_group %0;" :: "n"(N) : "memory");
}

// ================= 128x128 bf16-split GEMM (vocab projection) =====
#define ARR_B (128*40*2)
#define STG_B (4*ARR_B)
#define GEMM_SMEM (2*STG_B)       // 81920 bytes

__global__ __launch_bounds__(256, 2)
void gemm_bf16_nt(const __nv_bfloat16* __restrict__ Ah, const __nv_bfloat16* __restrict__ Al,
                  const __nv_bfloat16* __restrict__ Bh, const __nv_bfloat16* __restrict__ Bl,
                  float* __restrict__ Cm, int M, int N, int K) {
    int row0 = blockIdx.x * 128, col0 = blockIdx.y * 128;

    extern __shared__ __align__(16) char smem[];
    uint32_t smem_u32 = (uint32_t)__cvta_generic_to_shared(smem);

    int tid = threadIdx.x;
    int lane = tid & 31, wid = tid >> 5;
    int warpM = wid >> 2, warpN = wid & 3;

    float acc[4][4][4];
    #pragma unroll
    for (int mi = 0; mi < 4; mi++)
        #pragma unroll
        for (int ni = 0; ni < 4; ni++)
            #pragma unroll
            for (int r = 0; r < 4; r++) acc[mi][ni][r] = 0.f;

    int r0c = tid >> 2, f0 = tid & 3;
    int r1c = (tid + 256) >> 2, f1 = tid & 3;

    int aRow = (lane & 15);
    int aColOff = (lane >> 4) * 8;
    int bRowX4 = (lane & 7) + ((lane >> 4) << 3);
    int bColOff = ((lane >> 3) & 1) * 8;

    const int nk = K >> 5;

    auto load_stage = [&](int stg, int kt) {
        int k0 = kt << 5;
        uint32_t sb = smem_u32 + stg * STG_B;
        const __nv_bfloat16* srcs[4] = { Ah, Al, Bh, Bl };
        #pragma unroll
        for (int m = 0; m < 4; m++) {
            const __nv_bfloat16* G = srcs[m];
            int rb = (m < 2) ? row0 : col0;
            uint32_t dst = sb + m * ARR_B;
            cp16(dst + r0c*80 + f0*16, G + (size_t)(rb + r0c)*K + k0 + f0*8);
            cp16(dst + r1c*80 + f1*16, G + (size_t)(rb + r1c)*K + k0 + f1*8);
        }
        cp_commit();
    };

    load_stage(0, 0);
    if (nk > 1) load_stage(1, 1);

    for (int kt = 0; kt < nk; kt++) {
        int stg = kt & 1;
        if (kt + 1 < nk) cp_wait<1>(); else cp_wait<0>();
        __syncthreads();

        uint32_t sb = smem_u32 + stg * STG_B;
        uint32_t sAh = sb, sAl = sb + ARR_B, sBh = sb + 2*ARR_B, sBl = sb + 3*ARR_B;

        #pragma unroll
        for (int ks = 0; ks < 32; ks += 16) {
            uint32_t bh[4][2], bl[4][2];
            #pragma unroll
            for (int nip = 0; nip < 2; nip++) {
                int brow = warpN*32 + nip*16 + bRowX4;
                uint32_t off = (uint32_t)(brow*80 + (ks + bColOff)*2);
                ldsm_x4(bh[2*nip][0], bh[2*nip][1], bh[2*nip+1][0], bh[2*nip+1][1], sBh + off);
                ldsm_x4(bl[2*nip][0], bl[2*nip][1], bl[2*nip+1][0], bl[2*nip+1][1], sBl + off);
            }
            #pragma unroll
            for (int mi = 0; mi < 4; mi++) {
                int arow = warpM*64 + mi*16 + aRow;
                uint32_t off = (uint32_t)(arow*80 + (ks + aColOff)*2);
                uint32_t ah0, ah1, ah2, ah3, al0, al1, al2, al3;
                ldsm_x4(ah0, ah1, ah2, ah3, sAh + off);
                ldsm_x4(al0, al1, al2, al3, sAl + off);
                #pragma unroll
                for (int ni = 0; ni < 4; ni++)
                    mma16816(acc[mi][ni], ah0, ah1, ah2, ah3, bh[ni][0], bh[ni][1]);
                #pragma unroll
                for (int ni = 0; ni < 4; ni++)
                    mma16816(acc[mi][ni], ah0, ah1, ah2, ah3, bl[ni][0], bl[ni][1]);
                #pragma unroll
                for (int ni = 0; ni < 4; ni++)
                    mma16816(acc[mi][ni], al0, al1, al2, al3, bh[ni][0], bh[ni][1]);
            }
        }
        __syncthreads();
        if (kt + 2 < nk) load_stage(stg, kt + 2);
    }

    #pragma unroll
    for (int mi = 0; mi < 4; mi++) {
        #pragma unroll
        for (int ni = 0; ni < 4; ni++) {
            int r = row0 + warpM*64 + mi*16 + (lane >> 2);
            int c = col0 + warpN*32 + ni*8 + (lane & 3)*2;
            float2 v0 = {acc[mi][ni][0], acc[mi][ni][1]};
            float2 v1 = {acc[mi][ni][2], acc[mi][ni][3]};
            *(float2*)&Cm[(size_t)r*N + c]       = v0;
            *(float2*)&Cm[(size_t)(r + 8)*N + c] = v1;
        }
    }
}

// ================= 128x64 bf16-split GEMM (layer GEMMs, 3 CTAs/SM) =====
#define ARR64_A (128*40*2)
#define ARR64_B (64*40*2)
#define STG64_B (2*ARR64_A + 2*ARR64_B)
#define GEMM64_SMEM (2*STG64_B)   // 61440

__global__ __launch_bounds__(256, 3)
void gemm64_bf16_nt(const __nv_bfloat16* __restrict__ Ah, const __nv_bfloat16* __restrict__ Al,
                    const __nv_bfloat16* __restrict__ Bh, const __nv_bfloat16* __restrict__ Bl,
                    float* __restrict__ Cm, int M, int N, int K,
                    size_t strideB, size_t strideC,
                    int moeGather, int addC) {
    int row0 = blockIdx.x * 128, col0 = blockIdx.y * 64;
    int z = blockIdx.z;
    Bh += (size_t)z * strideB;
    Bl += (size_t)z * strideB;
    Cm += (size_t)z * strideC;

    int tid = threadIdx.x;
    int rA0 = tid >> 2, fA = tid & 3;
    int rA1 = rA0 + 64;

    size_t aoff0, aoff1;
    if (moeGather) {
        int cnt = g_cnt[z];
        if (row0 >= cnt) return;
        int i0 = row0 + rA0, i1 = row0 + rA1;
        int tok0 = (i0 < cnt) ? g_glist[z*ECAP + i0] : g_glist[z*ECAP];
        int tok1 = (i1 < cnt) ? g_glist[z*ECAP + i1] : tok0;
        aoff0 = (size_t)tok0 * K;
        aoff1 = (size_t)tok1 * K;
    } else {
        aoff0 = (size_t)(row0 + rA0) * K;
        aoff1 = (size_t)(row0 + rA1) * K;
    }

    extern __shared__ __align__(16) char smem[];
    uint32_t smem_u32 = (uint32_t)__cvta_generic_to_shared(smem);

    int lane = tid & 31, wid = tid >> 5;
    int warpM = wid >> 1, warpN = wid & 1;

    float acc[2][4][4];
    #pragma unroll
    for (int mi = 0; mi < 2; mi++)
        #pragma unroll
        for (int ni = 0; ni < 4; ni++)
            #pragma unroll
            for (int r = 0; r < 4; r++) acc[mi][ni][r] = 0.f;

    int rB = tid >> 2;

    int aRow = (lane & 15);
    int aColOff = (lane >> 4) * 8;
    int bRowX4 = (lane & 7) + ((lane >> 4) << 3);
    int bColOff = ((lane >> 3) & 1) * 8;

    const int nk = K >> 5;

    auto load_stage = [&](int stg, int kt) {
        int k0 = kt << 5;
        uint32_t sb = smem_u32 + stg * STG64_B;
        uint32_t dAh = sb, dAl = sb + ARR64_A;
        uint32_t dBh = sb + 2*ARR64_A, dBl = sb + 2*ARR64_A + ARR64_B;
        cp16(dAh + rA0*80 + fA*16, Ah + aoff0 + k0 + fA*8);
        cp16(dAh + rA1*80 + fA*16, Ah + aoff1 + k0 + fA*8);
        cp16(dAl + rA0*80 + fA*16, Al + aoff0 + k0 + fA*8);
        cp16(dAl + rA1*80 + fA*16, Al + aoff1 + k0 + fA*8);
        cp16(dBh + rB*80 + fA*16,  Bh + (size_t)(col0 + rB)*K + k0 + fA*8);
        cp16(dBl + rB*80 + fA*16,  Bl + (size_t)(col0 + rB)*K + k0 + fA*8);
        cp_commit();
    };

    load_stage(0, 0);
    if (nk > 1) load_stage(1, 1);

    for (int kt = 0; kt < nk; kt++) {
        int stg = kt & 1;
        if (kt + 1 < nk) cp_wait<1>(); else cp_wait<0>();
        __syncthreads();

        uint32_t sb = smem_u32 + stg * STG64_B;
        uint32_t sAh = sb, sAl = sb + ARR64_A;
        uint32_t sBh = sb + 2*ARR64_A, sBl = sb + 2*ARR64_A + ARR64_B;

        #pragma unroll
        for (int ks = 0; ks < 32; ks += 16) {
            uint32_t bh[4][2], bl[4][2];
            #pragma unroll
            for (int nip = 0; nip < 2; nip++) {
                int brow = warpN*32 + nip*16 + bRowX4;
                uint32_t off = (uint32_t)(brow*80 + (ks + bColOff)*2);
                ldsm_x4(bh[2*nip][0], bh[2*nip][1], bh[2*nip+1][0], bh[2*nip+1][1], sBh + off);
                ldsm_x4(bl[2*nip][0], bl[2*nip][1], bl[2*nip+1][0], bl[2*nip+1][1], sBl + off);
            }
            #pragma unroll
            for (int mi = 0; mi < 2; mi++) {
                int arow = warpM*32 + mi*16 + aRow;
                uint32_t off = (uint32_t)(arow*80 + (ks + aColOff)*2);
                uint32_t ah0, ah1, ah2, ah3, al0, al1, al2, al3;
                ldsm_x4(ah0, ah1, ah2, ah3, sAh + off);
                ldsm_x4(al0, al1, al2, al3, sAl + off);
                #pragma unroll
                for (int ni = 0; ni < 4; ni++)
                    mma16816(acc[mi][ni], ah0, ah1, ah2, ah3, bh[ni][0], bh[ni][1]);
                #pragma unroll
                for (int ni = 0; ni < 4; ni++)
                    mma16816(acc[mi][ni], ah0, ah1, ah2, ah3, bl[ni][0], bl[ni][1]);
                #pragma unroll
                for (int ni = 0; ni < 4; ni++)
                    mma16816(acc[mi][ni], al0, al1, al2, al3, bh[ni][0], bh[ni][1]);
            }
        }
        __syncthreads();
        if (kt + 2 < nk) load_stage(stg, kt + 2);
    }

    #pragma unroll
    for (int mi = 0; mi < 2; mi++) {
        #pragma unroll
        for (int ni = 0; ni < 4; ni++) {
            int r = row0 + warpM*32 + mi*16 + (lane >> 2);
            int c = col0 + warpN*32 + ni*8 + (lane & 3)*2;
            float2 v0 = {acc[mi][ni][0], acc[mi][ni][1]};
            float2 v1 = {acc[mi][ni][2], acc[mi][ni][3]};
            float2* p0 = (float2*)&Cm[(size_t)r*N + c];
            float2* p1 = (float2*)&Cm[(size_t)(r + 8)*N + c];
            if (addC) {
                float2 o0 = *p0, o1 = *p1;
                v0.x += o0.x; v0.y += o0.y; v1.x += o1.x; v1.y += o1.y;
            }
            *p0 = v0;
            *p1 = v1;
        }
    }
}

// ---------------- tiled causal GQA attention: QB=16 queries per block --------
// score: thread owns k-row (tid&127), query-half (tid>>7) -> 8 dots/thread.
// softmax & PV: warp w owns queries w and w+8 (sc rows warp-private).
#define ATT_SC_F   (QB*Tt)            // 16384
#define ATT_TILE_F (128*68)           // 8704
#define ATT_QS_F   (QB*68)            // 1088
#define ATT_INV_F  (QB)               // 16
#define ATT_SMEM   ((ATT_SC_F + ATT_TILE_F + ATT_QS_F + ATT_INV_F) * 4)

__global__ __launch_bounds__(256)
void attn_kernel() {
    int q0 = blockIdx.x * QB, hh = blockIdx.y, b = blockIdx.z;
    int kvh = hh >> 2;
    int tid = threadIdx.x;
    int lane = tid & 31, wid = tid >> 5;

    extern __shared__ __align__(16) float smem_f[];
    float* sc   = smem_f;                                     // [QB][Tt]
    float* tile = smem_f + ATT_SC_F;                          // [128][68]
    float* qs   = smem_f + ATT_SC_F + ATT_TILE_F;             // [QB][68]
    float* sinv = smem_f + ATT_SC_F + ATT_TILE_F + ATT_QS_F;  // [QB]

    // load 16 Q rows (16 float4 per row = 256 loads)
    {
        int qi = tid >> 4, c4 = tid & 15;
        const float4* src = (const float4*)(g_qkv + ((size_t)(b*Tt + q0 + qi))*QKVN + hh*HD);
        *(float4*)&qs[qi*68 + c4*4] = src[c4];
    }

    int nTiles = (q0 + QB + 127) >> 7;

    int krow = tid & 127;
    int qbase = (tid >> 7) * 8;   // 0 or 8

    // ---- pass 1: scores (k-row loaded once, reused across 8 queries) ----
    for (int kb = 0; kb < nTiles; kb++) {
        __syncthreads();
        #pragma unroll
        for (int i = 0; i < 8; i++) {
            int f4 = tid + i*256;
            int row = f4 >> 4, c4 = f4 & 15;
            const float4* src = (const float4*)(g_qkv + ((size_t)(b*Tt + kb*128 + row))*QKVN + Cc + kvh*HD);
            *(float4*)&tile[row*68 + c4*4] = src[c4];
        }
        __syncthreads();
        int kg = kb*128 + krow;
        if (kg <= q0 + qbase + 7) {
            float a[8];
            #pragma unroll
            for (int i = 0; i < 8; i++) a[i] = 0.f;
            const float4* k4 = (const float4*)&tile[krow*68];
            #pragma unroll
            for (int j = 0; j < 16; j++) {
                float4 kv = k4[j];
                #pragma unroll
                for (int i = 0; i < 8; i++) {
                    float4 qv = *(const float4*)&qs[(qbase+i)*68 + j*4];
                    a[i] += qv.x*kv.x + qv.y*kv.y + qv.z*kv.z + qv.w*kv.w;
                }
            }
            #pragma unroll
            for (int i = 0; i < 8; i++)
                if (kg <= q0 + qbase + i) sc[(qbase+i)*Tt + kg] = a[i] * 0.125f;
        }
    }
    __syncthreads();

    // ---- softmax: warp w handles queries w and w+8; zero-fill causal tail ----
    int tileEnd = nTiles * 128;
    #pragma unroll
    for (int h = 0; h < 2; h++) {
        int qi = wid + h*8;
        int qg = q0 + qi;
        int nk = qg + 1;
        float m = -1e30f;
        for (int k = lane; k < nk; k += 32) m = fmaxf(m, sc[qi*Tt + k]);
        #pragma unroll
        for (int o = 16; o > 0; o >>= 1) m = fmaxf(m, __shfl_xor_sync(0xffffffffu, m, o));
        float s = 0.f;
        for (int k = lane; k < nk; k += 32) {
            float e = expf(sc[qi*Tt + k] - m);
            sc[qi*Tt + k] = e;
            s += e;
        }
        for (int k = nk + lane; k < tileEnd; k += 32) sc[qi*Tt + k] = 0.f;
        #pragma unroll
        for (int o = 16; o > 0; o >>= 1) s += __shfl_xor_sync(0xffffffffu, s, o);
        if (lane == 0) sinv[qi] = 1.f / s;
    }

    // ---- pass 2: PV (warp w: queries w, w+8; each V float2 feeds 2 queries) ----
    float2 acc0 = {0.f, 0.f}, acc1 = {0.f, 0.f};
    for (int kb = 0; kb < nTiles; kb++) {
        __syncthreads();
        #pragma unroll
        for (int i = 0; i < 8; i++) {
            int f4 = tid + i*256;
            int row = f4 >> 4, c4 = f4 & 15;
            const float4* src = (const float4*)(g_qkv + ((size_t)(b*Tt + kb*128 + row))*QKVN + Cc + KVD + kvh*HD);
            *(float4*)&tile[row*68 + c4*4] = src[c4];
        }
        __syncthreads();
        const float* sc0 = &sc[wid*Tt + kb*128];
        const float* sc1 = &sc[(wid+8)*Tt + kb*128];
        #pragma unroll 4
        for (int kk = 0; kk < 128; kk++) {
            float2 v = *(const float2*)&tile[kk*68 + lane*2];
            float a0 = sc0[kk], a1 = sc1[kk];
            acc0.x += a0*v.x; acc0.y += a0*v.y;
            acc1.x += a1*v.x; acc1.y += a1*v.y;
        }
    }
    // output both queries (sc rows + sinv are warp-private; no extra sync)
    #pragma unroll
    for (int h = 0; h < 2; h++) {
        int qi = wid + h*8;
        float inv = sinv[qi];
        float ox = (h == 0 ? acc0.x : acc1.x) * inv;
        float oy = (h == 0 ? acc0.y : acc1.y) * inv;
        __nv_bfloat16 hx = __float2bfloat16(ox), hy = __float2bfloat16(oy);
        __nv_bfloat16 lx = __float2bfloat16(ox - __bfloat162float(hx));
        __nv_bfloat16 ly = __float2bfloat16(oy - __bfloat162float(hy));
        size_t off = ((size_t)(b*Tt + q0 + qi))*Cc + hh*HD + lane*2;
        *(__nv_bfloat162*)&g_ah[off] = __nv_bfloat162{hx, hy};
        *(__nv_bfloat162*)&g_al[off] = __nv_bfloat162{lx, ly};
    }
}

// ---------------- host launcher ----------------
extern "C" void kernel_launch(void* const* d_in, const int* in_sizes, int n_in,
                              void* d_out, int out_size) {
    (void)in_sizes; (void)n_in; (void)out_size;
    const int*   ids        = (const int*)  d_in[0];
    const float* tok        = (const float*)d_in[1];
    const float* pos        = (const float*)d_in[2];
    const float* attn_norm  = (const float*)d_in[3];
    const float* q_w        = (const float*)d_in[4];
    const float* k_w        = (const float*)d_in[5];
    const float* v_w        = (const float*)d_in[6];
    const float* o_w        = (const float*)d_in[7];
    const float* ffn_norm   = (const float*)d_in[8];
    const float* gate_w     = (const float*)d_in[9];
    const float* expert_w   = (const float*)d_in[10];
    const float* final_norm = (const float*)d_in[11];
    const float* out_w      = (const float*)d_in[12];
    float* out = (float*)d_out;

    float *h, *qkv, *gmo;
    __nv_bfloat16 *ah, *al;
    __nv_bfloat16 *wqkvh, *wqkvl, *woh, *wol, *wexh, *wexl, *wouth, *woutl;
    cudaGetSymbolAddress((void**)&h,     g_h);
    cudaGetSymbolAddress((void**)&qkv,   g_qkv);
    cudaGetSymbolAddress((void**)&gmo,   g_gmo);
    cudaGetSymbolAddress((void**)&ah,    g_ah);
    cudaGetSymbolAddress((void**)&al,    g_al);
    cudaGetSymbolAddress((void**)&wqkvh, g_wqkvh);
    cudaGetSymbolAddress((void**)&wqkvl, g_wqkvl);
    cudaGetSymbolAddress((void**)&woh,   g_woh);
    cudaGetSymbolAddress((void**)&wol,   g_wol);
    cudaGetSymbolAddress((void**)&wexh,  g_wexh);
    cudaGetSymbolAddress((void**)&wexl,  g_wexl);
    cudaGetSymbolAddress((void**)&wouth, g_wouth);
    cudaGetSymbolAddress((void**)&woutl, g_woutl);

    cudaFuncSetAttribute(gemm_bf16_nt,   cudaFuncAttributeMaxDynamicSharedMemorySize, GEMM_SMEM);
    cudaFuncSetAttribute(gemm64_bf16_nt, cudaFuncAttributeMaxDynamicSharedMemorySize, GEMM64_SMEM);
    cudaFuncSetAttribute(attn_kernel,    cudaFuncAttributeMaxDynamicSharedMemorySize, ATT_SMEM);

    cudaStream_t sW;
    cudaStreamCreateWithFlags(&sW, cudaStreamNonBlocking);
    cudaEvent_t evFork, evQkvw, evOwExw, evOutw;
    cudaEventCreateWithFlags(&evFork,  cudaEventDisableTiming);
    cudaEventCreateWithFlags(&evQkvw,  cudaEventDisableTiming);
    cudaEventCreateWithFlags(&evOwExw, cudaEventDisableTiming);
    cudaEventCreateWithFlags(&evOutw,  cudaEventDisableTiming);

    cudaEventRecord(evFork, 0);
    cudaStreamWaitEvent(sW, evFork, 0);
    split_qkvw_kernel<<<(Ll*QKVN*Cc/4 + 255)/256, 256, 0, sW>>>(q_w, k_w, v_w);
    cudaEventRecord(evQkvw, sW);
    {
        int tot = Ll*Cc*Cc/4 + Ll*Ee*Cc*Cc/4;
        split_ow_exw_kernel<<<(tot + 255)/256, 256, 0, sW>>>(o_w, expert_w);
    }
    cudaEventRecord(evOwExw, sW);
    split_outw_kernel<<<(Vv*Cc/4 + 255)/256, 256, 0, sW>>>(out_w);
    cudaEventRecord(evOutw, sW);

    embed_rmsnorm_split_kernel<<<Nn, 256>>>(ids, tok, pos, attn_norm, h, ah, al);

    bool waitedOw = false;
    for (int l = 0; l < Ll; l++) {
        if (l > 0) {
            rmsnorm_split_kernel<<<Nn, 256>>>(h, attn_norm + (size_t)l*Cc, ah, al, 1);
        }
        if (l == 0) cudaStreamWaitEvent(0, evQkvw, 0);
        {
            dim3 g(Nn/128, QKVN/64);
            gemm64_bf16_nt<<<g, 256, GEMM64_SMEM>>>(ah, al,
                wqkvh + (size_t)l*QKVN*Cc, wqkvl + (size_t)l*QKVN*Cc,
                qkv, Nn, QKVN, Cc, 0, 0, 0, 0);
        }
        {
            dim3 ga(Tt/QB, Hh, Bb);
            attn_kernel<<<ga, 256, ATT_SMEM>>>();
        }
        if (!waitedOw) { cudaStreamWaitEvent(0, evOwExw, 0); waitedOw = true; }
        {
            dim3 g(Nn/128, Cc/64);
            gemm64_bf16_nt<<<g, 256, GEMM64_SMEM>>>(ah, al,
                woh + (size_t)l*Cc*Cc, wol + (size_t)l*Cc*Cc,
                h, Nn, Cc, Cc, 0, 0, 0, 1);
        }
        rmsnorm_gate_kernel<<<Nn, 256>>>(h, ffn_norm + (size_t)l*Cc,
                                         gate_w + (size_t)l*Ee*Cc, ah, al);
        {
            dim3 g(ECAP/128, Cc/64, Ee);
            gemm64_bf16_nt<<<g, 256, GEMM64_SMEM>>>(ah, al,
                wexh + (size_t)l*Ee*Cc*Cc, wexl + (size_t)l*Ee*Cc*Cc,
                gmo, ECAP, Cc, Cc,
                (size_t)Cc*Cc, (size_t)ECAP*Cc, 1, 0);
        }
    }

    rmsnorm_split_kernel<<<Nn, 256>>>(h, final_norm, ah, al, 1);
    cudaStreamWaitEvent(0, evOutw, 0);
    {
        dim3 g(Nn/128, Vv/128);
        gemm_bf16_nt<<<g, 256, GEMM_SMEM>>>(ah, al, wouth, woutl, out, Nn, Vv, Cc);
    }
    // stream/events intentionally not destroyed (graph capture safety).
}

// round 17
// speedup vs baseline: 1.1873x; 1.0144x over previous
#include <cuda_runtime.h>
#include <cuda_bf16.h>
#include <math.h>
#include <stdint.h>

#define Bb 2
#define Tt 1024
#define Cc 512
#define Hh 8
#define KVh 2
#define HD 64
#define Ll 2
#define Ee 8
#define TOPK 2
#define Vv 32000
#define Nn (Bb*Tt)        // 2048 tokens
#define KVD (KVh*HD)      // 128
#define QKVN (Cc + 2*KVD) // 768
#define ECAP 2048         // per-expert slot capacity
#define QB 32             // queries per attention block
#define EPSf 1e-6f

// ---------------- scratch (device globals; no allocation allowed) ----------------
__device__ float g_h[Nn*Cc];
__device__ float g_qkv[Nn*QKVN];
__device__ int   g_sel[Nn*TOPK];
__device__ float g_gw[Nn*TOPK];
__device__ int   g_cnt[Ee];
__device__ int   g_glist[Ee*ECAP];
__device__ int   g_tokslot[Nn*TOPK];
__device__ __nv_bfloat16 g_ah[Nn*Cc];
__device__ __nv_bfloat16 g_al[Nn*Cc];
__device__ float g_gmo[Ee*ECAP*Cc];
// pre-split weights (all layers)
__device__ __nv_bfloat16 g_wqkvh[Ll*QKVN*Cc];
__device__ __nv_bfloat16 g_wqkvl[Ll*QKVN*Cc];
__device__ __nv_bfloat16 g_woh[Ll*Cc*Cc];
__device__ __nv_bfloat16 g_wol[Ll*Cc*Cc];
__device__ __nv_bfloat16 g_wexh[Ll*Ee*Cc*Cc];
__device__ __nv_bfloat16 g_wexl[Ll*Ee*Cc*Cc];
__device__ __nv_bfloat16 g_wouth[Vv*Cc];
__device__ __nv_bfloat16 g_woutl[Vv*Cc];

// ---- fused embed + rmsnorm + bf16 split (zeroes expert counters) ----
__global__ void embed_rmsnorm_split_kernel(const int* __restrict__ ids,
                                           const float* __restrict__ tok,
                                           const float* __restrict__ pos,
                                           const float* __restrict__ w,
                                           float* __restrict__ hbuf,
                                           __nv_bfloat16* __restrict__ hi,
                                           __nv_bfloat16* __restrict__ lo) {
    int n = blockIdx.x;
    int tid = threadIdx.x;
    if (n == 0 && tid < Ee) g_cnt[tid] = 0;
    int t = n % Tt;
    size_t tb = (size_t)ids[n]*Cc, pb = (size_t)t*Cc;
    float v0 = tok[tb + tid]       + pos[pb + tid];
    float v1 = tok[tb + tid + 256] + pos[pb + tid + 256];
    hbuf[(size_t)n*Cc + tid]       = v0;
    hbuf[(size_t)n*Cc + tid + 256] = v1;
    __shared__ float red[256];
    red[tid] = v0*v0 + v1*v1;
    __syncthreads();
    for (int o = 128; o > 0; o >>= 1) {
        if (tid < o) red[tid] += red[tid + o];
        __syncthreads();
    }
    float inv = rsqrtf(red[0] / (float)Cc + EPSf);
    float y0 = v0 * inv * w[tid];
    float y1 = v1 * inv * w[tid+256];
    __nv_bfloat16 h0 = __float2bfloat16(y0);
    __nv_bfloat16 h1 = __float2bfloat16(y1);
    hi[(size_t)n*Cc + tid]       = h0;
    hi[(size_t)n*Cc + tid + 256] = h1;
    lo[(size_t)n*Cc + tid]       = __float2bfloat16(y0 - __bfloat162float(h0));
    lo[(size_t)n*Cc + tid + 256] = __float2bfloat16(y1 - __bfloat162float(h1));
}

// ---- (optional moe-combine) + rmsnorm + bf16 split; zeroes counters ----
__global__ void rmsnorm_split_kernel(float* __restrict__ hbuf,
                                     const float* __restrict__ w,
                                     __nv_bfloat16* __restrict__ hi,
                                     __nv_bfloat16* __restrict__ lo,
                                     int do_moe) {
    int n = blockIdx.x;
    int tid = threadIdx.x;
    if (n == 0 && tid < Ee) g_cnt[tid] = 0;
    float* hr = hbuf + (size_t)n*Cc;
    float v0, v1;
    if (do_moe) {
        int e0 = g_sel[n*2],     e1 = g_sel[n*2+1];
        int s0 = g_tokslot[n*2], s1 = g_tokslot[n*2+1];
        float w0 = g_gw[n*2],    w1 = g_gw[n*2+1];
        const float* m0 = g_gmo + ((size_t)e0*ECAP + s0)*Cc;
        const float* m1 = g_gmo + ((size_t)e1*ECAP + s1)*Cc;
        v0 = hr[tid]     + w0*m0[tid]     + w1*m1[tid];
        v1 = hr[tid+256] + w0*m0[tid+256] + w1*m1[tid+256];
        hr[tid] = v0; hr[tid+256] = v1;
    } else {
        v0 = hr[tid]; v1 = hr[tid+256];
    }
    __shared__ float red[256];
    red[tid] = v0*v0 + v1*v1;
    __syncthreads();
    for (int o = 128; o > 0; o >>= 1) {
        if (tid < o) red[tid] += red[tid + o];
        __syncthreads();
    }
    float inv = rsqrtf(red[0] / (float)Cc + EPSf);
    float y0 = v0 * inv * w[tid];
    float y1 = v1 * inv * w[tid+256];
    __nv_bfloat16 h0 = __float2bfloat16(y0);
    __nv_bfloat16 h1 = __float2bfloat16(y1);
    hi[(size_t)n*Cc + tid]       = h0;
    hi[(size_t)n*Cc + tid + 256] = h1;
    lo[(size_t)n*Cc + tid]       = __float2bfloat16(y0 - __bfloat162float(h0));
    lo[(size_t)n*Cc + tid + 256] = __float2bfloat16(y1 - __bfloat162float(h1));
}

// ---- fused ffn rmsnorm + bf16 split + GATE (top-2, atomics) ----
__global__ void rmsnorm_gate_kernel(const float* __restrict__ hbuf,
                                    const float* __restrict__ w,
                                    const float* __restrict__ gw,
                                    __nv_bfloat16* __restrict__ hi,
                                    __nv_bfloat16* __restrict__ lo) {
    int n = blockIdx.x;
    int tid = threadIdx.x;
    int lane = tid & 31, wid = tid >> 5;
    const float* hr = hbuf + (size_t)n*Cc;
    float v0 = hr[tid], v1 = hr[tid+256];
    __shared__ float red[256];
    __shared__ float sy[Cc];
    __shared__ float slog[Ee];
    red[tid] = v0*v0 + v1*v1;
    __syncthreads();
    for (int o = 128; o > 0; o >>= 1) {
        if (tid < o) red[tid] += red[tid + o];
        __syncthreads();
    }
    float inv = rsqrtf(red[0] / (float)Cc + EPSf);
    float y0 = v0 * inv * w[tid];
    float y1 = v1 * inv * w[tid+256];
    sy[tid] = y0; sy[tid+256] = y1;
    __nv_bfloat16 h0 = __float2bfloat16(y0);
    __nv_bfloat16 h1 = __float2bfloat16(y1);
    hi[(size_t)n*Cc + tid]       = h0;
    hi[(size_t)n*Cc + tid + 256] = h1;
    lo[(size_t)n*Cc + tid]       = __float2bfloat16(y0 - __bfloat162float(h0));
    lo[(size_t)n*Cc + tid + 256] = __float2bfloat16(y1 - __bfloat162float(h1));
    __syncthreads();
    float s = 0.f;
    const float* gr = gw + (size_t)wid*Cc;
    #pragma unroll
    for (int j = 0; j < 16; j++) s += sy[lane + j*32] * gr[lane + j*32];
    #pragma unroll
    for (int o = 16; o > 0; o >>= 1) s += __shfl_down_sync(0xffffffffu, s, o);
    if (lane == 0) slog[wid] = s;
    __syncthreads();
    if (tid == 0) {
        float logits[Ee];
        #pragma unroll
        for (int e = 0; e < Ee; e++) logits[e] = slog[e];
        int b0 = 0;
        #pragma unroll
        for (int e = 1; e < Ee; e++) if (logits[e] > logits[b0]) b0 = e;
        int b1 = -1;
        #pragma unroll
        for (int e = 0; e < Ee; e++) {
            if (e == b0) continue;
            if (b1 < 0 || logits[e] > logits[b1]) b1 = e;
        }
        float mm = logits[b0];
        float e0 = expf(logits[b0] - mm), e1 = expf(logits[b1] - mm);
        float sw = e0 + e1;
        g_sel[n*2]   = b0;    g_sel[n*2+1] = b1;
        g_gw[n*2]    = e0/sw; g_gw[n*2+1]  = e1/sw;
        int s0 = atomicAdd(&g_cnt[b0], 1);
        g_tokslot[n*2] = s0;
        g_glist[b0*ECAP + s0] = n;
        int s1 = atomicAdd(&g_cnt[b1], 1);
        g_tokslot[n*2+1] = s1;
        g_glist[b1*ECAP + s1] = n;
    }
}

// ---------------- bf16 split helpers ----------------
__device__ __forceinline__ void split4(float4 v, __nv_bfloat162* H, __nv_bfloat162* L, size_t i4) {
    __nv_bfloat16 h0 = __float2bfloat16(v.x);
    __nv_bfloat16 h1 = __float2bfloat16(v.y);
    __nv_bfloat16 h2 = __float2bfloat16(v.z);
    __nv_bfloat16 h3 = __float2bfloat16(v.w);
    H[i4*2]   = __nv_bfloat162{h0, h1};
    H[i4*2+1] = __nv_bfloat162{h2, h3};
    L[i4*2]   = __nv_bfloat162{__float2bfloat16(v.x - __bfloat162float(h0)),
                               __float2bfloat16(v.y - __bfloat162float(h1))};
    L[i4*2+1] = __nv_bfloat162{__float2bfloat16(v.z - __bfloat162float(h2)),
                               __float2bfloat16(v.w - __bfloat162float(h3))};
}

__global__ void split_qkvw_kernel(const float* __restrict__ qw,
                                  const float* __restrict__ kw,
                                  const float* __restrict__ vw) {
    int idx4 = blockIdx.x*blockDim.x + threadIdx.x;
    const int per_l = QKVN*Cc/4;
    if (idx4 >= Ll*per_l) return;
    int l = idx4 / per_l, rem = idx4 - l*per_l;
    int row = rem >> 7, col4 = rem & 127;
    float4 v;
    if (row < 512)       v = ((const float4*)qw)[(size_t)l*(Cc*Cc/4)  + row*128 + col4];
    else if (row < 640)  v = ((const float4*)kw)[(size_t)l*(KVD*Cc/4) + (row-512)*128 + col4];
    else                 v = ((const float4*)vw)[(size_t)l*(KVD*Cc/4) + (row-640)*128 + col4];
    split4(v, (__nv_bfloat162*)g_wqkvh, (__nv_bfloat162*)g_wqkvl, idx4);
}

__global__ void split_ow_exw_kernel(const float* __restrict__ ow,
                                    const float* __restrict__ exw) {
    int idx4 = blockIdx.x*blockDim.x + threadIdx.x;
    const int n_o = Ll*Cc*Cc/4;
    const int n_e = Ll*Ee*Cc*Cc/4;
    if (idx4 < n_o) {
        split4(((const float4*)ow)[idx4], (__nv_bfloat162*)g_woh, (__nv_bfloat162*)g_wol, idx4);
    } else if (idx4 < n_o + n_e) {
        int j = idx4 - n_o;
        split4(((const float4*)exw)[j], (__nv_bfloat162*)g_wexh, (__nv_bfloat162*)g_wexl, j);
    }
}

__global__ void split_outw_kernel(const float* __restrict__ x) {
    int i = blockIdx.x*blockDim.x + threadIdx.x;
    if (i >= Vv*Cc/4) return;
    split4(((const float4*)x)[i], (__nv_bfloat162*)g_wouth, (__nv_bfloat162*)g_woutl, i);
}

// ---------------- mma helpers ----------------
__device__ __forceinline__ void ldsm_x4(uint32_t& r0, uint32_t& r1, uint32_t& r2, uint32_t& r3, uint32_t addr) {
    asm volatile("ldmatrix.sync.aligned.m8n8.x4.shared.b16 {%0,%1,%2,%3}, [%4];"
                 : "=r"(r0), "=r"(r1), "=r"(r2), "=r"(r3) : "r"(addr));
}
__device__ __forceinline__ void mma16816(float* c, uint32_t a0, uint32_t a1, uint32_t a2, uint32_t a3,
                                         uint32_t b0, uint32_t b1) {
    asm volatile("mma.sync.aligned.m16n8k16.row.col.f32.bf16.bf16.f32 "
                 "{%0,%1,%2,%3}, {%4,%5,%6,%7}, {%8,%9}, {%0,%1,%2,%3};"
                 : "+f"(c[0]), "+f"(c[1]), "+f"(c[2]), "+f"(c[3])
                 : "r"(a0), "r"(a1), "r"(a2), "r"(a3), "r"(b0), "r"(b1));
}
__device__ __forceinline__ void cp16(uint32_t smem, const void* gmem) {
    asm volatile("cp.async.cg.shared.global [%0], [%1], 16;" :: "r"(smem), "l"(gmem));
}
__device__ __forceinline__ void cp_commit() {
    asm volatile("cp.async.commit_group;" ::: "memory");
}
template<int N>
__device__ __forceinline__ void cp_wait() {
    asm volatile("cp.async.wait_group %0;" :: "n"(N) : "memory");
}

// ================= 128x128 bf16-split GEMM (vocab projection) =====
#define ARR_B (128*40*2)
#define STG_B (4*ARR_B)
#define GEMM_SMEM (2*STG_B)       // 81920 bytes

__global__ __launch_bounds__(256, 2)
void gemm_bf16_nt(const __nv_bfloat16* __restrict__ Ah, const __nv_bfloat16* __restrict__ Al,
                  const __nv_bfloat16* __restrict__ Bh, const __nv_bfloat16* __restrict__ Bl,
                  float* __restrict__ Cm, int M, int N, int K) {
    int row0 = blockIdx.x * 128, col0 = blockIdx.y * 128;

    extern __shared__ __align__(16) char smem[];
    uint32_t smem_u32 = (uint32_t)__cvta_generic_to_shared(smem);

    int tid = threadIdx.x;
    int lane = tid & 31, wid = tid >> 5;
    int warpM = wid >> 2, warpN = wid & 3;

    float acc[4][4][4];
    #pragma unroll
    for (int mi = 0; mi < 4; mi++)
        #pragma unroll
        for (int ni = 0; ni < 4; ni++)
            #pragma unroll
            for (int r = 0; r < 4; r++) acc[mi][ni][r] = 0.f;

    int r0c = tid >> 2, f0 = tid & 3;
    int r1c = (tid + 256) >> 2, f1 = tid & 3;

    int aRow = (lane & 15);
    int aColOff = (lane >> 4) * 8;
    int bRowX4 = (lane & 7) + ((lane >> 4) << 3);
    int bColOff = ((lane >> 3) & 1) * 8;

    const int nk = K >> 5;

    auto load_stage = [&](int stg, int kt) {
        int k0 = kt << 5;
        uint32_t sb = smem_u32 + stg * STG_B;
        const __nv_bfloat16* srcs[4] = { Ah, Al, Bh, Bl };
        #pragma unroll
        for (int m = 0; m < 4; m++) {
            const __nv_bfloat16* G = srcs[m];
            int rb = (m < 2) ? row0 : col0;
            uint32_t dst = sb + m * ARR_B;
            cp16(dst + r0c*80 + f0*16, G + (size_t)(rb + r0c)*K + k0 + f0*8);
            cp16(dst + r1c*80 + f1*16, G + (size_t)(rb + r1c)*K + k0 + f1*8);
        }
        cp_commit();
    };

    load_stage(0, 0);
    if (nk > 1) load_stage(1, 1);

    for (int kt = 0; kt < nk; kt++) {
        int stg = kt & 1;
        if (kt + 1 < nk) cp_wait<1>(); else cp_wait<0>();
        __syncthreads();

        uint32_t sb = smem_u32 + stg * STG_B;
        uint32_t sAh = sb, sAl = sb + ARR_B, sBh = sb + 2*ARR_B, sBl = sb + 3*ARR_B;

        #pragma unroll
        for (int ks = 0; ks < 32; ks += 16) {
            uint32_t bh[4][2], bl[4][2];
            #pragma unroll
            for (int nip = 0; nip < 2; nip++) {
                int brow = warpN*32 + nip*16 + bRowX4;
                uint32_t off = (uint32_t)(brow*80 + (ks + bColOff)*2);
                ldsm_x4(bh[2*nip][0], bh[2*nip][1], bh[2*nip+1][0], bh[2*nip+1][1], sBh + off);
                ldsm_x4(bl[2*nip][0], bl[2*nip][1], bl[2*nip+1][0], bl[2*nip+1][1], sBl + off);
            }
            #pragma unroll
            for (int mi = 0; mi < 4; mi++) {
                int arow = warpM*64 + mi*16 + aRow;
                uint32_t off = (uint32_t)(arow*80 + (ks + aColOff)*2);
                uint32_t ah0, ah1, ah2, ah3, al0, al1, al2, al3;
                ldsm_x4(ah0, ah1, ah2, ah3, sAh + off);
                ldsm_x4(al0, al1, al2, al3, sAl + off);
                #pragma unroll
                for (int ni = 0; ni < 4; ni++)
                    mma16816(acc[mi][ni], ah0, ah1, ah2, ah3, bh[ni][0], bh[ni][1]);
                #pragma unroll
                for (int ni = 0; ni < 4; ni++)
                    mma16816(acc[mi][ni], ah0, ah1, ah2, ah3, bl[ni][0], bl[ni][1]);
                #pragma unroll
                for (int ni = 0; ni < 4; ni++)
                    mma16816(acc[mi][ni], al0, al1, al2, al3, bh[ni][0], bh[ni][1]);
            }
        }
        __syncthreads();
        if (kt + 2 < nk) load_stage(stg, kt + 2);
    }

    #pragma unroll
    for (int mi = 0; mi < 4; mi++) {
        #pragma unroll
        for (int ni = 0; ni < 4; ni++) {
            int r = row0 + warpM*64 + mi*16 + (lane >> 2);
            int c = col0 + warpN*32 + ni*8 + (lane & 3)*2;
            float2 v0 = {acc[mi][ni][0], acc[mi][ni][1]};
            float2 v1 = {acc[mi][ni][2], acc[mi][ni][3]};
            *(float2*)&Cm[(size_t)r*N + c]       = v0;
            *(float2*)&Cm[(size_t)(r + 8)*N + c] = v1;
        }
    }
}

// ================= 128x64 bf16-split GEMM (layer GEMMs, 3 CTAs/SM) =====
#define ARR64_A (128*40*2)
#define ARR64_B (64*40*2)
#define STG64_B (2*ARR64_A + 2*ARR64_B)
#define GEMM64_SMEM (2*STG64_B)   // 61440

__global__ __launch_bounds__(256, 3)
void gemm64_bf16_nt(const __nv_bfloat16* __restrict__ Ah, const __nv_bfloat16* __restrict__ Al,
                    const __nv_bfloat16* __restrict__ Bh, const __nv_bfloat16* __restrict__ Bl,
                    float* __restrict__ Cm, int M, int N, int K,
                    size_t strideB, size_t strideC,
                    int moeGather, int addC) {
    int row0 = blockIdx.x * 128, col0 = blockIdx.y * 64;
    int z = blockIdx.z;
    Bh += (size_t)z * strideB;
    Bl += (size_t)z * strideB;
    Cm += (size_t)z * strideC;

    int tid = threadIdx.x;
    int rA0 = tid >> 2, fA = tid & 3;
    int rA1 = rA0 + 64;

    size_t aoff0, aoff1;
    if (moeGather) {
        int cnt = g_cnt[z];
        if (row0 >= cnt) return;
        int i0 = row0 + rA0, i1 = row0 + rA1;
        int tok0 = (i0 < cnt) ? g_glist[z*ECAP + i0] : g_glist[z*ECAP];
        int tok1 = (i1 < cnt) ? g_glist[z*ECAP + i1] : tok0;
        aoff0 = (size_t)tok0 * K;
        aoff1 = (size_t)tok1 * K;
    } else {
        aoff0 = (size_t)(row0 + rA0) * K;
        aoff1 = (size_t)(row0 + rA1) * K;
    }

    extern __shared__ __align__(16) char smem[];
    uint32_t smem_u32 = (uint32_t)__cvta_generic_to_shared(smem);

    int lane = tid & 31, wid = tid >> 5;
    int warpM = wid >> 1, warpN = wid & 1;

    float acc[2][4][4];
    #pragma unroll
    for (int mi = 0; mi < 2; mi++)
        #pragma unroll
        for (int ni = 0; ni < 4; ni++)
            #pragma unroll
            for (int r = 0; r < 4; r++) acc[mi][ni][r] = 0.f;

    int rB = tid >> 2;

    int aRow = (lane & 15);
    int aColOff = (lane >> 4) * 8;
    int bRowX4 = (lane & 7) + ((lane >> 4) << 3);
    int bColOff = ((lane >> 3) & 1) * 8;

    const int nk = K >> 5;

    auto load_stage = [&](int stg, int kt) {
        int k0 = kt << 5;
        uint32_t sb = smem_u32 + stg * STG64_B;
        uint32_t dAh = sb, dAl = sb + ARR64_A;
        uint32_t dBh = sb + 2*ARR64_A, dBl = sb + 2*ARR64_A + ARR64_B;
        cp16(dAh + rA0*80 + fA*16, Ah + aoff0 + k0 + fA*8);
        cp16(dAh + rA1*80 + fA*16, Ah + aoff1 + k0 + fA*8);
        cp16(dAl + rA0*80 + fA*16, Al + aoff0 + k0 + fA*8);
        cp16(dAl + rA1*80 + fA*16, Al + aoff1 + k0 + fA*8);
        cp16(dBh + rB*80 + fA*16,  Bh + (size_t)(col0 + rB)*K + k0 + fA*8);
        cp16(dBl + rB*80 + fA*16,  Bl + (size_t)(col0 + rB)*K + k0 + fA*8);
        cp_commit();
    };

    load_stage(0, 0);
    if (nk > 1) load_stage(1, 1);

    for (int kt = 0; kt < nk; kt++) {
        int stg = kt & 1;
        if (kt + 1 < nk) cp_wait<1>(); else cp_wait<0>();
        __syncthreads();

        uint32_t sb = smem_u32 + stg * STG64_B;
        uint32_t sAh = sb, sAl = sb + ARR64_A;
        uint32_t sBh = sb + 2*ARR64_A, sBl = sb + 2*ARR64_A + ARR64_B;

        #pragma unroll
        for (int ks = 0; ks < 32; ks += 16) {
            uint32_t bh[4][2], bl[4][2];
            #pragma unroll
            for (int nip = 0; nip < 2; nip++) {
                int brow = warpN*32 + nip*16 + bRowX4;
                uint32_t off = (uint32_t)(brow*80 + (ks + bColOff)*2);
                ldsm_x4(bh[2*nip][0], bh[2*nip][1], bh[2*nip+1][0], bh[2*nip+1][1], sBh + off);
                ldsm_x4(bl[2*nip][0], bl[2*nip][1], bl[2*nip+1][0], bl[2*nip+1][1], sBl + off);
            }
            #pragma unroll
            for (int mi = 0; mi < 2; mi++) {
                int arow = warpM*32 + mi*16 + aRow;
                uint32_t off = (uint32_t)(arow*80 + (ks + aColOff)*2);
                uint32_t ah0, ah1, ah2, ah3, al0, al1, al2, al3;
                ldsm_x4(ah0, ah1, ah2, ah3, sAh + off);
                ldsm_x4(al0, al1, al2, al3, sAl + off);
                #pragma unroll
                for (int ni = 0; ni < 4; ni++)
                    mma16816(acc[mi][ni], ah0, ah1, ah2, ah3, bh[ni][0], bh[ni][1]);
                #pragma unroll
                for (int ni = 0; ni < 4; ni++)
                    mma16816(acc[mi][ni], ah0, ah1, ah2, ah3, bl[ni][0], bl[ni][1]);
                #pragma unroll
                for (int ni = 0; ni < 4; ni++)
                    mma16816(acc[mi][ni], al0, al1, al2, al3, bh[ni][0], bh[ni][1]);
            }
        }
        __syncthreads();
        if (kt + 2 < nk) load_stage(stg, kt + 2);
    }

    #pragma unroll
    for (int mi = 0; mi < 2; mi++) {
        #pragma unroll
        for (int ni = 0; ni < 4; ni++) {
            int r = row0 + warpM*32 + mi*16 + (lane >> 2);
            int c = col0 + warpN*32 + ni*8 + (lane & 3)*2;
            float2 v0 = {acc[mi][ni][0], acc[mi][ni][1]};
            float2 v1 = {acc[mi][ni][2], acc[mi][ni][3]};
            float2* p0 = (float2*)&Cm[(size_t)r*N + c];
            float2* p1 = (float2*)&Cm[(size_t)(r + 8)*N + c];
            if (addC) {
                float2 o0 = *p0, o1 = *p1;
                v0.x += o0.x; v0.y += o0.y; v1.x += o1.x; v1.y += o1.y;
            }
            *p0 = v0;
            *p1 = v1;
        }
    }
}

// ---------------- tiled causal GQA attention: QB=32 queries per block --------
// score: thread owns k-row (tid&127), query-half (tid>>7)*16 -> 16 dots/thread.
// softmax & PV: warp w owns queries w, w+8, w+16, w+24 (sc rows warp-private).
#define ATT_SC_F   (QB*Tt)            // 32768
#define ATT_TILE_F (128*68)           // 8704
#define ATT_QS_F   (QB*68)            // 2176
#define ATT_INV_F  (QB)               // 32
#define ATT_SMEM   ((ATT_SC_F + ATT_TILE_F + ATT_QS_F + ATT_INV_F) * 4)   // ~174.7 KB

__global__ __launch_bounds__(256)
void attn_kernel() {
    int q0 = blockIdx.x * QB, hh = blockIdx.y, b = blockIdx.z;
    int kvh = hh >> 2;
    int tid = threadIdx.x;
    int lane = tid & 31, wid = tid >> 5;

    extern __shared__ __align__(16) float smem_f[];
    float* sc   = smem_f;                                     // [QB][Tt]
    float* tile = smem_f + ATT_SC_F;                          // [128][68]
    float* qs   = smem_f + ATT_SC_F + ATT_TILE_F;             // [QB][68]
    float* sinv = smem_f + ATT_SC_F + ATT_TILE_F + ATT_QS_F;  // [QB]

    // load 32 Q rows (16 float4 per row = 512 loads, 2 per thread)
    #pragma unroll
    for (int i = 0; i < 2; i++) {
        int idx = tid + i*256;
        int qi = idx >> 4, c4 = idx & 15;
        const float4* src = (const float4*)(g_qkv + ((size_t)(b*Tt + q0 + qi))*QKVN + hh*HD);
        *(float4*)&qs[qi*68 + c4*4] = src[c4];
    }

    int nTiles = (q0 + QB + 127) >> 7;

    int krow = tid & 127;
    int qbase = (tid >> 7) * 16;   // 0 or 16

    // ---- pass 1: scores (k-row loaded once, reused across 16 queries) ----
    for (int kb = 0; kb < nTiles; kb++) {
        __syncthreads();
        #pragma unroll
        for (int i = 0; i < 8; i++) {
            int f4 = tid + i*256;
            int row = f4 >> 4, c4 = f4 & 15;
            const float4* src = (const float4*)(g_qkv + ((size_t)(b*Tt + kb*128 + row))*QKVN + Cc + kvh*HD);
            *(float4*)&tile[row*68 + c4*4] = src[c4];
        }
        __syncthreads();
        int kg = kb*128 + krow;
        if (kg <= q0 + qbase + 15) {
            float a[16];
            #pragma unroll
            for (int i = 0; i < 16; i++) a[i] = 0.f;
            const float4* k4 = (const float4*)&tile[krow*68];
            #pragma unroll
            for (int j = 0; j < 16; j++) {
                float4 kv = k4[j];
                #pragma unroll
                for (int i = 0; i < 16; i++) {
                    float4 qv = *(const float4*)&qs[(qbase+i)*68 + j*4];
                    a[i] += qv.x*kv.x + qv.y*kv.y + qv.z*kv.z + qv.w*kv.w;
                }
            }
            #pragma unroll
            for (int i = 0; i < 16; i++)
                if (kg <= q0 + qbase + i) sc[(qbase+i)*Tt + kg] = a[i] * 0.125f;
        }
    }
    __syncthreads();

    // ---- softmax: warp w handles queries w+8h (h=0..3); zero-fill tail ----
    int tileEnd = nTiles * 128;
    #pragma unroll
    for (int h = 0; h < 4; h++) {
        int qi = wid + h*8;
        int qg = q0 + qi;
        int nk = qg + 1;
        float m = -1e30f;
        for (int k = lane; k < nk; k += 32) m = fmaxf(m, sc[qi*Tt + k]);
        #pragma unroll
        for (int o = 16; o > 0; o >>= 1) m = fmaxf(m, __shfl_xor_sync(0xffffffffu, m, o));
        float s = 0.f;
        for (int k = lane; k < nk; k += 32) {
            float e = expf(sc[qi*Tt + k] - m);
            sc[qi*Tt + k] = e;
            s += e;
        }
        for (int k = nk + lane; k < tileEnd; k += 32) sc[qi*Tt + k] = 0.f;
        #pragma unroll
        for (int o = 16; o > 0; o >>= 1) s += __shfl_xor_sync(0xffffffffu, s, o);
        if (lane == 0) sinv[qi] = 1.f / s;
    }

    // ---- pass 2: PV (warp w: queries w+8h; each V float2 feeds 4 queries) ----
    float2 acc[4];
    #pragma unroll
    for (int h = 0; h < 4; h++) acc[h] = make_float2(0.f, 0.f);
    for (int kb = 0; kb < nTiles; kb++) {
        __syncthreads();
        #pragma unroll
        for (int i = 0; i < 8; i++) {
            int f4 = tid + i*256;
            int row = f4 >> 4, c4 = f4 & 15;
            const float4* src = (const float4*)(g_qkv + ((size_t)(b*Tt + kb*128 + row))*QKVN + Cc + KVD + kvh*HD);
            *(float4*)&tile[row*68 + c4*4] = src[c4];
        }
        __syncthreads();
        const float* s0 = &sc[(wid     )*Tt + kb*128];
        const float* s1 = &sc[(wid +  8)*Tt + kb*128];
        const float* s2 = &sc[(wid + 16)*Tt + kb*128];
        const float* s3 = &sc[(wid + 24)*Tt + kb*128];
        #pragma unroll 4
        for (int kk = 0; kk < 128; kk++) {
            float2 v = *(const float2*)&tile[kk*68 + lane*2];
            float a0 = s0[kk], a1 = s1[kk], a2 = s2[kk], a3 = s3[kk];
            acc[0].x += a0*v.x; acc[0].y += a0*v.y;
            acc[1].x += a1*v.x; acc[1].y += a1*v.y;
            acc[2].x += a2*v.x; acc[2].y += a2*v.y;
            acc[3].x += a3*v.x; acc[3].y += a3*v.y;
        }
    }
    // output (sc rows + sinv are warp-private; no extra sync)
    #pragma unroll
    for (int h = 0; h < 4; h++) {
        int qi = wid + h*8;
        float inv = sinv[qi];
        float ox = acc[h].x * inv, oy = acc[h].y * inv;
        __nv_bfloat16 hx = __float2bfloat16(ox), hy = __float2bfloat16(oy);
        __nv_bfloat16 lx = __float2bfloat16(ox - __bfloat162float(hx));
        __nv_bfloat16 ly = __float2bfloat16(oy - __bfloat162float(hy));
        size_t off = ((size_t)(b*Tt + q0 + qi))*Cc + hh*HD + lane*2;
        *(__nv_bfloat162*)&g_ah[off] = __nv_bfloat162{hx, hy};
        *(__nv_bfloat162*)&g_al[off] = __nv_bfloat162{lx, ly};
    }
}

// ---------------- host launcher ----------------
extern "C" void kernel_launch(void* const* d_in, const int* in_sizes, int n_in,
                              void* d_out, int out_size) {
    (void)in_sizes; (void)n_in; (void)out_size;
    const int*   ids        = (const int*)  d_in[0];
    const float* tok        = (const float*)d_in[1];
    const float* pos        = (const float*)d_in[2];
    const float* attn_norm  = (const float*)d_in[3];
    const float* q_w        = (const float*)d_in[4];
    const float* k_w        = (const float*)d_in[5];
    const float* v_w        = (const float*)d_in[6];
    const float* o_w        = (const float*)d_in[7];
    const float* ffn_norm   = (const float*)d_in[8];
    const float* gate_w     = (const float*)d_in[9];
    const float* expert_w   = (const float*)d_in[10];
    const float* final_norm = (const float*)d_in[11];
    const float* out_w      = (const float*)d_in[12];
    float* out = (float*)d_out;

    float *h, *qkv, *gmo;
    __nv_bfloat16 *ah, *al;
    __nv_bfloat16 *wqkvh, *wqkvl, *woh, *wol, *wexh, *wexl, *wouth, *woutl;
    cudaGetSymbolAddress((void**)&h,     g_h);
    cudaGetSymbolAddress((void**)&qkv,   g_qkv);
    cudaGetSymbolAddress((void**)&gmo,   g_gmo);
    cudaGetSymbolAddress((void**)&ah,    g_ah);
    cudaGetSymbolAddress((void**)&al,    g_al);
    cudaGetSymbolAddress((void**)&wqkvh, g_wqkvh);
    cudaGetSymbolAddress((void**)&wqkvl, g_wqkvl);
    cudaGetSymbolAddress((void**)&woh,   g_woh);
    cudaGetSymbolAddress((void**)&wol,   g_wol);
    cudaGetSymbolAddress((void**)&wexh,  g_wexh);
    cudaGetSymbolAddress((void**)&wexl,  g_wexl);
    cudaGetSymbolAddress((void**)&wouth, g_wouth);
    cudaGetSymbolAddress((void**)&woutl, g_woutl);

    cudaFuncSetAttribute(gemm_bf16_nt,   cudaFuncAttributeMaxDynamicSharedMemorySize, GEMM_SMEM);
    cudaFuncSetAttribute(gemm64_bf16_nt, cudaFuncAttributeMaxDynamicSharedMemorySize, GEMM64_SMEM);
    cudaFuncSetAttribute(attn_kernel,    cudaFuncAttributeMaxDynamicSharedMemorySize, ATT_SMEM);

    cudaStream_t sW;
    cudaStreamCreateWithFlags(&sW, cudaStreamNonBlocking);
    cudaEvent_t evFork, evQkvw, evOwExw, evOutw;
    cudaEventCreateWithFlags(&evFork,  cudaEventDisableTiming);
    cudaEventCreateWithFlags(&evQkvw,  cudaEventDisableTiming);
    cudaEventCreateWithFlags(&evOwExw, cudaEventDisableTiming);
    cudaEventCreateWithFlags(&evOutw,  cudaEventDisableTiming);

    cudaEventRecord(evFork, 0);
    cudaStreamWaitEvent(sW, evFork, 0);
    split_qkvw_kernel<<<(Ll*QKVN*Cc/4 + 255)/256, 256, 0, sW>>>(q_w, k_w, v_w);
    cudaEventRecord(evQkvw, sW);
    {
        int tot = Ll*Cc*Cc/4 + Ll*Ee*Cc*Cc/4;
        split_ow_exw_kernel<<<(tot + 255)/256, 256, 0, sW>>>(o_w, expert_w);
    }
    cudaEventRecord(evOwExw, sW);
    split_outw_kernel<<<(Vv*Cc/4 + 255)/256, 256, 0, sW>>>(out_w);
    cudaEventRecord(evOutw, sW);

    embed_rmsnorm_split_kernel<<<Nn, 256>>>(ids, tok, pos, attn_norm, h, ah, al);

    bool waitedOw = false;
    for (int l = 0; l < Ll; l++) {
        if (l > 0) {
            rmsnorm_split_kernel<<<Nn, 256>>>(h, attn_norm + (size_t)l*Cc, ah, al, 1);
        }
        if (l == 0) cudaStreamWaitEvent(0, evQkvw, 0);
        {
            dim3 g(Nn/128, QKVN/64);
            gemm64_bf16_nt<<<g, 256, GEMM64_SMEM>>>(ah, al,
                wqkvh + (size_t)l*QKVN*Cc, wqkvl + (size_t)l*QKVN*Cc,
                qkv, Nn, QKVN, Cc, 0, 0, 0, 0);
        }
        {
            dim3 ga(Tt/QB, Hh, Bb);
            attn_kernel<<<ga, 256, ATT_SMEM>>>();
        }
        if (!waitedOw) { cudaStreamWaitEvent(0, evOwExw, 0); waitedOw = true; }
        {
            dim3 g(Nn/128, Cc/64);
            gemm64_bf16_nt<<<g, 256, GEMM64_SMEM>>>(ah, al,
                woh + (size_t)l*Cc*Cc, wol + (size_t)l*Cc*Cc,
                h, Nn, Cc, Cc, 0, 0, 0, 1);
        }
        rmsnorm_gate_kernel<<<Nn, 256>>>(h, ffn_norm + (size_t)l*Cc,
                                         gate_w + (size_t)l*Ee*Cc, ah, al);
        {
            dim3 g(ECAP/128, Cc/64, Ee);
            gemm64_bf16_nt<<<g, 256, GEMM64_SMEM>>>(ah, al,
                wexh + (size_t)l*Ee*Cc*Cc, wexl + (size_t)l*Ee*Cc*Cc,
                gmo, ECAP, Cc, Cc,
                (size_t)Cc*Cc, (size_t)ECAP*Cc, 1, 0);
        }
    }

    rmsnorm_split_kernel<<<Nn, 256>>>(h, final_norm, ah, al, 1);
    cudaStreamWaitEvent(0, evOutw, 0);
    {
        dim3 g(Nn/128, Vv/128);
        gemm_bf16_nt<<<g, 256, GEMM_SMEM>>>(ah, al, wouth, woutl, out, Nn, Vv, Cc);
    }
    // stream/events intentionally not destroyed (graph capture safety).
}